// round 1
// baseline (speedup 1.0000x reference)
#include <cuda_runtime.h>
#include <math.h>

// ---------------------------------------------------------------------------
// StackMSA: two-scale windowed transformer forward, fp32 baseline.
// B=4, H=W=8, M=16, C=256, NH=8, HD=32, GW=2
// scale0: 256 windows x 256 tokens; scale1: 16 windows x 256 tokens
// out: [272, 256, 256] f32 = [o0 (256 win) ; o1 (16 win)]
// ---------------------------------------------------------------------------

#define NTOK0 65536
#define NTOK1 4096
#define ATTN_SMEM (2 * 256 * 36 * 4)

// Scratch (static device globals; no runtime allocation)
__device__ float g_X0[65536 * 256];          // 64 MB  running activations scale0
__device__ float g_X1[4096 * 256];           //  4 MB  running activations scale1
__device__ float g_H[65536 * 256];           // 64 MB  LN out / attn out
__device__ float g_QKV[65536 * 768];         // 192 MB qkv / cross K|V
__device__ float g_T[65536 * 1024];          // 256 MB mlp hidden / cross scratch
__device__ float g_PE[2 * 256 * 256];        // position embedding tables
__device__ float g_G[4096 * 256];            // gathered global tokens

__device__ __forceinline__ float gelu_exact(float x) {
    return 0.5f * x * (1.0f + erff(x * 0.70710678118654752f));
}

// ---------------------------------------------------------------------------
// Position embedding table: pe[s][t][c] = relu(coords[t] @ w1[s] + b1[s]) @ w2[s]
// coords[t] = ((t/16 - 8)/8, (t%16 - 8)/8), t in [0,256)
// ---------------------------------------------------------------------------
__global__ void smsa_posemb_kernel(const float* __restrict__ w1,
                                   const float* __restrict__ b1,
                                   const float* __restrict__ w2,
                                   float* __restrict__ pe) {
    int t = blockIdx.x;   // token 0..255
    int s = blockIdx.y;   // scale 0..1
    int tid = threadIdx.x;
    __shared__ float hid[512];
    float c0 = (float)((t >> 4) - 8) * 0.125f;
    float c1 = (float)((t & 15) - 8) * 0.125f;
    const float* W1 = w1 + s * 1024;   // [2,512]
    const float* B1 = b1 + s * 512;
    for (int k = tid; k < 512; k += 256) {
        float hv = fmaf(c0, W1[k], fmaf(c1, W1[512 + k], B1[k]));
        hid[k] = fmaxf(hv, 0.0f);
    }
    __syncthreads();
    const float* W2 = w2 + s * 512 * 256;
    float acc = 0.0f;
#pragma unroll 8
    for (int k = 0; k < 512; k++) acc = fmaf(hid[k], W2[k * 256 + tid], acc);
    pe[s * 65536 + t * 256 + tid] = acc;
}

// y = x + pe (pe indexed mod one window)
__global__ void smsa_add_pe_kernel(const float* __restrict__ x,
                                   const float* __restrict__ pe,
                                   float* __restrict__ y) {
    size_t i = (size_t)blockIdx.x * 256 + threadIdx.x;   // float4 index
    float4 a = ((const float4*)x)[i];
    float4 p = ((const float4*)pe)[i & 16383];
    float4 r;
    r.x = a.x + p.x; r.y = a.y + p.y; r.z = a.z + p.z; r.w = a.w + p.w;
    ((float4*)y)[i] = r;
}

// propagate_bottom_up: X1[gwin][tt][c] += max over 4x4 fine region of X0
__global__ void smsa_pool_kernel(const float* __restrict__ x0,
                                 float* __restrict__ x1) {
    int gid = blockIdx.x;          // 0..4095 = (b, gr, gc)
    int c = threadIdx.x;
    int b = gid >> 10;
    int gr = (gid >> 5) & 31;
    int gc = gid & 31;
    int h = gr >> 2, r1 = gr & 3, w = gc >> 2, r2 = gc & 3;
    int fw = (b * 8 + h) * 8 + w;
    const float* base = x0 + ((size_t)fw * 256 + r1 * 64 + r2 * 4) * 256 + c;
    float m = -1e30f;
#pragma unroll
    for (int p1 = 0; p1 < 4; p1++)
#pragma unroll
        for (int p2 = 0; p2 < 4; p2++)
            m = fmaxf(m, base[(p1 * 16 + p2) * 256]);
    int gwin = b * 4 + (gr >> 4) * 2 + (gc >> 4);
    int tt = (gr & 15) * 16 + (gc & 15);
    x1[((size_t)gwin * 256 + tt) * 256 + c] += m;
}

// ---------------------------------------------------------------------------
// LayerNorm over C=256, one warp per token
// ---------------------------------------------------------------------------
__global__ __launch_bounds__(256) void smsa_ln_kernel(
    const float* __restrict__ x, float* __restrict__ y,
    const float* __restrict__ gg, const float* __restrict__ bb) {
    int tok = blockIdx.x * 8 + (threadIdx.x >> 5);
    int lane = threadIdx.x & 31;
    const float4* row = (const float4*)(x + (size_t)tok * 256);
    float4 v0 = row[lane], v1 = row[lane + 32];
    float s = v0.x + v0.y + v0.z + v0.w + v1.x + v1.y + v1.z + v1.w;
    float ss = v0.x * v0.x + v0.y * v0.y + v0.z * v0.z + v0.w * v0.w +
               v1.x * v1.x + v1.y * v1.y + v1.z * v1.z + v1.w * v1.w;
#pragma unroll
    for (int o = 16; o > 0; o >>= 1) {
        s += __shfl_xor_sync(0xffffffffu, s, o);
        ss += __shfl_xor_sync(0xffffffffu, ss, o);
    }
    float mean = s * 0.00390625f;
    float var = ss * 0.00390625f - mean * mean;
    float rstd = rsqrtf(var + 1e-5f);
    float4 g0 = ((const float4*)gg)[lane], g1 = ((const float4*)gg)[lane + 32];
    float4 b0 = ((const float4*)bb)[lane], b1 = ((const float4*)bb)[lane + 32];
    float4 o0, o1;
    o0.x = (v0.x - mean) * rstd * g0.x + b0.x;
    o0.y = (v0.y - mean) * rstd * g0.y + b0.y;
    o0.z = (v0.z - mean) * rstd * g0.z + b0.z;
    o0.w = (v0.w - mean) * rstd * g0.w + b0.w;
    o1.x = (v1.x - mean) * rstd * g1.x + b1.x;
    o1.y = (v1.y - mean) * rstd * g1.y + b1.y;
    o1.z = (v1.z - mean) * rstd * g1.z + b1.z;
    o1.w = (v1.w - mean) * rstd * g1.w + b1.w;
    float4* yr = (float4*)(y + (size_t)tok * 256);
    yr[lane] = o0;
    yr[lane + 32] = o1;
}

// ---------------------------------------------------------------------------
// SGEMM: C[M,N] = A[M,K] @ B[K,N] (+bias[N]) (+res) (gelu optional)
// 128x128x8 tile, 256 threads, 8x8 per thread. All dims multiples of tiles.
// ---------------------------------------------------------------------------
__global__ __launch_bounds__(256) void smsa_sgemm_kernel(
    const float* __restrict__ A, int lda,
    const float* __restrict__ B, int ldb,
    float* __restrict__ Cm, int ldc,
    const float* __restrict__ bias,
    const float* __restrict__ res, int ldr,
    int K, int act) {
    __shared__ float As[8][128];
    __shared__ float Bs[8][128];
    int tid = threadIdx.x;
    int mb = blockIdx.y, nb = blockIdx.x;
    int tr = tid >> 4, tc = tid & 15;

    int arow = tid >> 1, acol = (tid & 1) * 4;
    int brow = tid >> 5, bcol = (tid & 31) * 4;
    const float* Ag = A + ((size_t)mb * 128 + arow) * lda + acol;
    const float* Bg = B + (size_t)brow * ldb + nb * 128 + bcol;

    float acc[8][8];
#pragma unroll
    for (int i = 0; i < 8; i++)
#pragma unroll
        for (int j = 0; j < 8; j++) acc[i][j] = 0.0f;

    for (int kt = 0; kt < K; kt += 8) {
        float4 av = *(const float4*)Ag;
        float4 bv = *(const float4*)Bg;
        As[acol + 0][arow] = av.x;
        As[acol + 1][arow] = av.y;
        As[acol + 2][arow] = av.z;
        As[acol + 3][arow] = av.w;
        *(float4*)&Bs[brow][bcol] = bv;
        __syncthreads();
#pragma unroll
        for (int kk = 0; kk < 8; kk++) {
            float a[8], b[8];
            *(float4*)&a[0] = *(const float4*)&As[kk][tr * 8];
            *(float4*)&a[4] = *(const float4*)&As[kk][tr * 8 + 4];
            *(float4*)&b[0] = *(const float4*)&Bs[kk][tc * 8];
            *(float4*)&b[4] = *(const float4*)&Bs[kk][tc * 8 + 4];
#pragma unroll
            for (int i = 0; i < 8; i++)
#pragma unroll
                for (int j = 0; j < 8; j++)
                    acc[i][j] = fmaf(a[i], b[j], acc[i][j]);
        }
        __syncthreads();
        Ag += 8;
        Bg += (size_t)8 * ldb;
    }

    int row0 = mb * 128 + tr * 8;
    int col0 = nb * 128 + tc * 8;
    float bi[8];
    if (bias) {
        *(float4*)&bi[0] = *(const float4*)(bias + col0);
        *(float4*)&bi[4] = *(const float4*)(bias + col0 + 4);
    } else {
#pragma unroll
        for (int j = 0; j < 8; j++) bi[j] = 0.0f;
    }
#pragma unroll
    for (int i = 0; i < 8; i++) {
        float v[8];
#pragma unroll
        for (int j = 0; j < 8; j++) v[j] = acc[i][j] + bi[j];
        if (res) {
            const float* rp = res + (size_t)(row0 + i) * ldr + col0;
            float4 r0 = *(const float4*)rp;
            float4 r1 = *(const float4*)(rp + 4);
            v[0] += r0.x; v[1] += r0.y; v[2] += r0.z; v[3] += r0.w;
            v[4] += r1.x; v[5] += r1.y; v[6] += r1.z; v[7] += r1.w;
        }
        if (act == 1) {
#pragma unroll
            for (int j = 0; j < 8; j++) v[j] = gelu_exact(v[j]);
        }
        float* cp = Cm + (size_t)(row0 + i) * ldc + col0;
        *(float4*)cp = make_float4(v[0], v[1], v[2], v[3]);
        *(float4*)(cp + 4) = make_float4(v[4], v[5], v[6], v[7]);
    }
}

// ---------------------------------------------------------------------------
// Windowed attention: one block per (window, head), one query row per thread.
// K/V for the head live in smem; exact online softmax.
// qkv layout per token: [q(256) | k(256) | v(256)], ld = 768.
// ---------------------------------------------------------------------------
__global__ __launch_bounds__(256) void smsa_attn_kernel(
    const float* __restrict__ qkv, float* __restrict__ out) {
    extern __shared__ float sm[];
    float* Ks = sm;               // [256][36]
    float* Vs = sm + 256 * 36;
    int win = blockIdx.x >> 3;
    int h = blockIdx.x & 7;
    int t = threadIdx.x;
    const float* base = qkv + (size_t)win * 256 * 768;

    float q[32];
    {
        const float4* qp = (const float4*)(base + (size_t)t * 768 + h * 32);
#pragma unroll
        for (int i = 0; i < 8; i++) ((float4*)q)[i] = qp[i];
    }
    {
        const float4* kp = (const float4*)(base + (size_t)t * 768 + 256 + h * 32);
        const float4* vp = (const float4*)(base + (size_t)t * 768 + 512 + h * 32);
#pragma unroll
        for (int i = 0; i < 8; i++) {
            *(float4*)&Ks[t * 36 + i * 4] = kp[i];
            *(float4*)&Vs[t * 36 + i * 4] = vp[i];
        }
    }
    __syncthreads();

    float acc[32];
#pragma unroll
    for (int d = 0; d < 32; d++) acc[d] = 0.0f;
    float mmax = -1e30f, l = 0.0f;
    const float sc = 0.17677669529663687f;   // 1/sqrt(32)

    for (int j = 0; j < 256; j++) {
        const float4* kj = (const float4*)&Ks[j * 36];
        float s0 = 0.f, s1 = 0.f, s2 = 0.f, s3 = 0.f;
#pragma unroll
        for (int i = 0; i < 8; i++) {
            float4 kv = kj[i];
            s0 = fmaf(q[4 * i + 0], kv.x, s0);
            s1 = fmaf(q[4 * i + 1], kv.y, s1);
            s2 = fmaf(q[4 * i + 2], kv.z, s2);
            s3 = fmaf(q[4 * i + 3], kv.w, s3);
        }
        float s = ((s0 + s1) + (s2 + s3)) * sc;
        if (s > mmax) {
            float corr = __expf(mmax - s);
            l *= corr;
#pragma unroll
            for (int d = 0; d < 32; d++) acc[d] *= corr;
            mmax = s;
        }
        float p = __expf(s - mmax);
        l += p;
        const float4* vj = (const float4*)&Vs[j * 36];
#pragma unroll
        for (int i = 0; i < 8; i++) {
            float4 vv = vj[i];
            acc[4 * i + 0] = fmaf(p, vv.x, acc[4 * i + 0]);
            acc[4 * i + 1] = fmaf(p, vv.y, acc[4 * i + 1]);
            acc[4 * i + 2] = fmaf(p, vv.z, acc[4 * i + 2]);
            acc[4 * i + 3] = fmaf(p, vv.w, acc[4 * i + 3]);
        }
    }
    float inv = 1.0f / l;
    float4* op = (float4*)(out + ((size_t)(win * 256 + t)) * 256 + h * 32);
#pragma unroll
    for (int i = 0; i < 8; i++) {
        float4 o;
        o.x = acc[4 * i + 0] * inv;
        o.y = acc[4 * i + 1] * inv;
        o.z = acc[4 * i + 2] * inv;
        o.w = acc[4 * i + 3] * inv;
        op[i] = o;
    }
}

// ---------------------------------------------------------------------------
// Cross-attention gather/scatter and 1->16 attention
// f = ((b*8+h)*8+w)*16 + r1*4 + r2
// ---------------------------------------------------------------------------
__device__ __forceinline__ void decode_f(int f, int& fw, int& base_t,
                                         int& gwin, int& tt) {
    int b = f >> 10, h = (f >> 7) & 7, w = (f >> 4) & 7;
    int r1 = (f >> 2) & 3, r2 = f & 3;
    fw = (b * 8 + h) * 8 + w;
    base_t = r1 * 64 + r2 * 4;
    int gr = h * 4 + r1, gc = w * 4 + r2;
    gwin = b * 4 + (gr >> 4) * 2 + (gc >> 4);
    tt = (gr & 15) * 16 + (gc & 15);
}

__global__ void smsa_gather_g_kernel(const float* __restrict__ x1,
                                     float* __restrict__ g) {
    int f = blockIdx.x, c = threadIdx.x;
    int fw, base_t, gwin, tt;
    decode_f(f, fw, base_t, gwin, tt);
    g[(size_t)f * 256 + c] = x1[((size_t)gwin * 256 + tt) * 256 + c];
}

__global__ void smsa_scatter_g_kernel(const float* __restrict__ g,
                                      float* __restrict__ out1) {
    int f = blockIdx.x, c = threadIdx.x;
    int fw, base_t, gwin, tt;
    decode_f(f, fw, base_t, gwin, tt);
    out1[((size_t)gwin * 256 + tt) * 256 + c] = g[(size_t)f * 256 + c];
}

// Q: [4096,256]; KV: [65536,512] in original o0 token order (K cols 0..255, V 256..511)
__global__ __launch_bounds__(256) void smsa_xattn_kernel(
    const float* __restrict__ Q, const float* __restrict__ KV,
    float* __restrict__ AO) {
    int f = blockIdx.x;
    int h = threadIdx.x >> 5;
    int d = threadIdx.x & 31;
    int fw, base_t, gwin, tt;
    decode_f(f, fw, base_t, gwin, tt);
    float qd = Q[(size_t)f * 256 + h * 32 + d];
    const float sc = 0.17677669529663687f;
    float s[16];
#pragma unroll
    for (int j = 0; j < 16; j++) {
        int t = base_t + (j >> 2) * 16 + (j & 3);
        float kd = KV[((size_t)(fw * 256 + t)) * 512 + h * 32 + d];
        float pr = qd * kd;
#pragma unroll
        for (int o = 16; o > 0; o >>= 1)
            pr += __shfl_xor_sync(0xffffffffu, pr, o);
        s[j] = pr * sc;
    }
    float m = s[0];
#pragma unroll
    for (int j = 1; j < 16; j++) m = fmaxf(m, s[j]);
    float l = 0.0f, p[16];
#pragma unroll
    for (int j = 0; j < 16; j++) {
        p[j] = __expf(s[j] - m);
        l += p[j];
    }
    float inv = 1.0f / l;
    float acc = 0.0f;
#pragma unroll
    for (int j = 0; j < 16; j++) {
        int t = base_t + (j >> 2) * 16 + (j & 3);
        acc = fmaf(p[j], KV[((size_t)(fw * 256 + t)) * 512 + 256 + h * 32 + d], acc);
    }
    AO[(size_t)f * 256 + h * 32 + d] = acc * inv;
}

// ---------------------------------------------------------------------------
// Host side
// ---------------------------------------------------------------------------
static void run_sgemm(const float* A, int lda, const float* B, int ldb,
                      float* Cm, int ldc, const float* bias,
                      const float* res, int ldr, int M, int N, int K, int act) {
    dim3 grid(N / 128, M / 128);
    smsa_sgemm_kernel<<<grid, 256>>>(A, lda, B, ldb, Cm, ldc, bias, res, ldr, K, act);
}

static void run_ln(const float* x, float* y, const float* g, const float* b, int ntok) {
    smsa_ln_kernel<<<ntok / 8, 256>>>(x, y, g, b);
}

struct BlockParams {
    const float *ln1g, *ln1b, *wqkv, *bqkv, *wo, *bo;
    const float *ln2g, *ln2b, *w1, *b1, *w2, *b2;
};

static void run_sattn_block(float* X, float* outC, int ntok, const BlockParams& P,
                            float* H, float* QKV, float* T) {
    run_ln(X, H, P.ln1g, P.ln1b, ntok);
    run_sgemm(H, 256, P.wqkv, 768, QKV, 768, P.bqkv, nullptr, 0, ntok, 768, 256, 0);
    smsa_attn_kernel<<<(ntok / 256) * 8, 256, ATTN_SMEM>>>(QKV, H);
    run_sgemm(H, 256, P.wo, 256, X, 256, P.bo, X, 256, ntok, 256, 256, 0);
    run_ln(X, H, P.ln2g, P.ln2b, ntok);
    run_sgemm(H, 256, P.w1, 1024, T, 1024, P.b1, nullptr, 0, ntok, 1024, 256, 1);
    run_sgemm(T, 1024, P.w2, 256, outC, 256, P.b2, X, 256, ntok, 256, 1024, 0);
}

extern "C" void kernel_launch(void* const* d_in, const int* in_sizes, int n_in,
                              void* d_out, int out_size) {
    const float* scale0 = (const float*)d_in[0];
    const float* scale1 = (const float*)d_in[1];
    const float* pe_w1 = (const float*)d_in[2];
    const float* pe_b1 = (const float*)d_in[3];
    const float* pe_w2 = (const float*)d_in[4];
    const float* ln1_g = (const float*)d_in[5];
    const float* ln1_b = (const float*)d_in[6];
    const float* wqkv = (const float*)d_in[7];
    const float* bqkv = (const float*)d_in[8];
    const float* wo = (const float*)d_in[9];
    const float* bo = (const float*)d_in[10];
    const float* ln2_g = (const float*)d_in[11];
    const float* ln2_b = (const float*)d_in[12];
    const float* mw1 = (const float*)d_in[13];
    const float* mb1 = (const float*)d_in[14];
    const float* mw2 = (const float*)d_in[15];
    const float* mb2 = (const float*)d_in[16];
    float* out = (float*)d_out;
    float* out0 = out;                       // [65536,256]
    float* out1 = out + (size_t)65536 * 256; // [4096,256]

    float *X0, *X1, *H, *QKV, *T, *PE, *G;
    cudaGetSymbolAddress((void**)&X0, g_X0);
    cudaGetSymbolAddress((void**)&X1, g_X1);
    cudaGetSymbolAddress((void**)&H, g_H);
    cudaGetSymbolAddress((void**)&QKV, g_QKV);
    cudaGetSymbolAddress((void**)&T, g_T);
    cudaGetSymbolAddress((void**)&PE, g_PE);
    cudaGetSymbolAddress((void**)&G, g_G);

    cudaFuncSetAttribute(smsa_attn_kernel,
                         cudaFuncAttributeMaxDynamicSharedMemorySize, ATTN_SMEM);

    // 1) position embedding tables + add
    smsa_posemb_kernel<<<dim3(256, 2), 256>>>(pe_w1, pe_b1, pe_w2, PE);
    smsa_add_pe_kernel<<<16384, 256>>>(scale0, PE, X0);
    smsa_add_pe_kernel<<<1024, 256>>>(scale1, PE + 65536, X1);

    // 2) bottom-up max-pool into global tokens
    smsa_pool_kernel<<<4096, 256>>>(X0, X1);

    // 3) sattn blocks (scale1 then scale0; independent)
    BlockParams P1 = {ln1_g + 256, ln1_b + 256, wqkv + 196608, bqkv + 768,
                      wo + 65536, bo + 256, ln2_g + 256, ln2_b + 256,
                      mw1 + 262144, mb1 + 1024, mw2 + 262144, mb2 + 256};
    BlockParams P0 = {ln1_g, ln1_b, wqkv, bqkv, wo, bo,
                      ln2_g, ln2_b, mw1, mb1, mw2, mb2};
    run_sattn_block(X1, X1, NTOK1, P1, H, QKV, T);
    run_sattn_block(X0, out0, NTOK0, P0, H, QKV, T);   // o0 lands in d_out

    // 4) one2one cross-attention (all params index 1)
    // kn = ln(o0), then K|V = kn @ wqkv1[:,256:768]  -> QKV as [65536,512]
    run_ln(out0, H, P1.ln1g, P1.ln1b, NTOK0);
    run_sgemm(H, 256, P1.wqkv + 256, 768, QKV, 512, P1.bqkv + 256, nullptr, 0,
              NTOK0, 512, 256, 0);
    // gather g from o1 (=X1)
    smsa_gather_g_kernel<<<4096, 256>>>(X1, G);

    float* S0 = T;                         // qn [4096,256]
    float* Sq = T + (size_t)4096 * 256;    // Q  [4096,256]
    float* AO = T + (size_t)2 * 4096 * 256;// attn out [4096,256]
    float* Sg = T + (size_t)3 * 4096 * 256;// ln2(g) [4096,256]
    float* Th = T + (size_t)4 * 4096 * 256;// mlp hidden [4096,1024]

    run_ln(G, S0, P1.ln1g, P1.ln1b, NTOK1);
    run_sgemm(S0, 256, P1.wqkv, 768, Sq, 256, P1.bqkv, nullptr, 0, NTOK1, 256, 256, 0);
    smsa_xattn_kernel<<<4096, 256>>>(Sq, QKV, AO);
    run_sgemm(AO, 256, P1.wo, 256, G, 256, P1.bo, G, 256, NTOK1, 256, 256, 0);
    run_ln(G, Sg, P1.ln2g, P1.ln2b, NTOK1);
    run_sgemm(Sg, 256, P1.w1, 1024, Th, 1024, P1.b1, nullptr, 0, NTOK1, 1024, 256, 1);
    run_sgemm(Th, 1024, P1.w2, 256, G, 256, P1.b2, G, 256, NTOK1, 256, 1024, 0);

    // 5) scatter g back to o1 window layout
    smsa_scatter_g_kernel<<<4096, 256>>>(G, out1);
}

// round 3
// speedup vs baseline: 2.3789x; 2.3789x over previous
#include <cuda_runtime.h>
#include <cuda_bf16.h>
#include <math.h>
#include <stdint.h>

// ---------------------------------------------------------------------------
// StackMSA: two-scale windowed transformer forward.
// Round 3: GEMMs on mma.sync bf16 (HMMA path; tcgen05 unavailable: harness PTX
//          target is compute_103 w/o 'a'), attention on packed fma.rn.f32x2.
// B=4, H=W=8, M=16, C=256, NH=8, HD=32, GW=2
// out: [272, 256, 256] f32 = [o0 (256 win) ; o1 (16 win)]
// ---------------------------------------------------------------------------

#define NTOK0 65536
#define NTOK1 4096
#define ATTN_SMEM (2 * 256 * 36 * 4)
#define GEMM_SMEM 32768

// Scratch (static device globals; no runtime allocation)
__device__ float g_X0[65536 * 256];
__device__ float g_X1[4096 * 256];
__device__ float g_H[65536 * 256];
__device__ float g_QKV[65536 * 768];
__device__ float g_T[65536 * 1024];
__device__ float g_PE[2 * 256 * 256];
__device__ float g_G[4096 * 256];
__device__ float g_WT[1572864];   // transposed weights [N,K] fp32, both scales

__device__ __forceinline__ float gelu_exact(float x) {
    return 0.5f * x * (1.0f + erff(x * 0.70710678118654752f));
}

__device__ __forceinline__ uint32_t smem_u32(const void* p) {
    uint32_t a;
    asm("{ .reg .u64 t; cvta.to.shared.u64 t, %1; cvt.u32.u64 %0, t; }"
        : "=r"(a) : "l"(p));
    return a;
}

#define SWZ128(o) ((o) ^ (((o) >> 3) & 0x70))

// packed f32x2
__device__ __forceinline__ unsigned long long pk2(float x, float y) {
    unsigned long long r;
    asm("mov.b64 %0, {%1, %2};" : "=l"(r) : "f"(x), "f"(y));
    return r;
}
__device__ __forceinline__ void upk2(float& x, float& y, unsigned long long v) {
    asm("mov.b64 {%0, %1}, %2;" : "=f"(x), "=f"(y) : "l"(v));
}
__device__ __forceinline__ unsigned long long fma2(unsigned long long a,
                                                   unsigned long long b,
                                                   unsigned long long c) {
    unsigned long long d;
    asm("fma.rn.f32x2 %0, %1, %2, %3;" : "=l"(d) : "l"(a), "l"(b), "l"(c));
    return d;
}
__device__ __forceinline__ unsigned long long mul2(unsigned long long a,
                                                   unsigned long long b) {
    unsigned long long d;
    asm("mul.rn.f32x2 %0, %1, %2;" : "=l"(d) : "l"(a), "l"(b));
    return d;
}

// ---------------------------------------------------------------------------
// Position embedding table
// ---------------------------------------------------------------------------
__global__ void smsa_posemb_kernel(const float* __restrict__ w1,
                                   const float* __restrict__ b1,
                                   const float* __restrict__ w2,
                                   float* __restrict__ pe) {
    int t = blockIdx.x, s = blockIdx.y, tid = threadIdx.x;
    __shared__ float hid[512];
    float c0 = (float)((t >> 4) - 8) * 0.125f;
    float c1 = (float)((t & 15) - 8) * 0.125f;
    const float* W1 = w1 + s * 1024;
    const float* B1 = b1 + s * 512;
    for (int k = tid; k < 512; k += 256)
        hid[k] = fmaxf(fmaf(c0, W1[k], fmaf(c1, W1[512 + k], B1[k])), 0.0f);
    __syncthreads();
    const float* W2 = w2 + s * 512 * 256;
    float acc = 0.0f;
#pragma unroll 8
    for (int k = 0; k < 512; k++) acc = fmaf(hid[k], W2[k * 256 + tid], acc);
    pe[s * 65536 + t * 256 + tid] = acc;
}

__global__ void smsa_add_pe_kernel(const float* __restrict__ x,
                                   const float* __restrict__ pe,
                                   float* __restrict__ y) {
    size_t i = (size_t)blockIdx.x * 256 + threadIdx.x;
    float4 a = ((const float4*)x)[i];
    float4 p = ((const float4*)pe)[i & 16383];
    float4 r;
    r.x = a.x + p.x; r.y = a.y + p.y; r.z = a.z + p.z; r.w = a.w + p.w;
    ((float4*)y)[i] = r;
}

__global__ void smsa_pool_kernel(const float* __restrict__ x0,
                                 float* __restrict__ x1) {
    int gid = blockIdx.x, c = threadIdx.x;
    int b = gid >> 10, gr = (gid >> 5) & 31, gc = gid & 31;
    int h = gr >> 2, r1 = gr & 3, w = gc >> 2, r2 = gc & 3;
    int fw = (b * 8 + h) * 8 + w;
    const float* base = x0 + ((size_t)fw * 256 + r1 * 64 + r2 * 4) * 256 + c;
    float m = -1e30f;
#pragma unroll
    for (int p1 = 0; p1 < 4; p1++)
#pragma unroll
        for (int p2 = 0; p2 < 4; p2++)
            m = fmaxf(m, base[(p1 * 16 + p2) * 256]);
    int gwin = b * 4 + (gr >> 4) * 2 + (gc >> 4);
    int tt = (gr & 15) * 16 + (gc & 15);
    x1[((size_t)gwin * 256 + tt) * 256 + c] += m;
}

// ---------------------------------------------------------------------------
// LayerNorm over C=256, one warp per token
// ---------------------------------------------------------------------------
__global__ __launch_bounds__(256) void smsa_ln_kernel(
    const float* __restrict__ x, float* __restrict__ y,
    const float* __restrict__ gg, const float* __restrict__ bb) {
    int tok = blockIdx.x * 8 + (threadIdx.x >> 5);
    int lane = threadIdx.x & 31;
    const float4* row = (const float4*)(x + (size_t)tok * 256);
    float4 v0 = row[lane], v1 = row[lane + 32];
    float s = v0.x + v0.y + v0.z + v0.w + v1.x + v1.y + v1.z + v1.w;
    float ss = v0.x * v0.x + v0.y * v0.y + v0.z * v0.z + v0.w * v0.w +
               v1.x * v1.x + v1.y * v1.y + v1.z * v1.z + v1.w * v1.w;
#pragma unroll
    for (int o = 16; o > 0; o >>= 1) {
        s += __shfl_xor_sync(0xffffffffu, s, o);
        ss += __shfl_xor_sync(0xffffffffu, ss, o);
    }
    float mean = s * 0.00390625f;
    float var = ss * 0.00390625f - mean * mean;
    float rstd = rsqrtf(var + 1e-5f);
    float4 g0 = ((const float4*)gg)[lane], g1 = ((const float4*)gg)[lane + 32];
    float4 b0 = ((const float4*)bb)[lane], b1 = ((const float4*)bb)[lane + 32];
    float4 o0, o1;
    o0.x = (v0.x - mean) * rstd * g0.x + b0.x;
    o0.y = (v0.y - mean) * rstd * g0.y + b0.y;
    o0.z = (v0.z - mean) * rstd * g0.z + b0.z;
    o0.w = (v0.w - mean) * rstd * g0.w + b0.w;
    o1.x = (v1.x - mean) * rstd * g1.x + b1.x;
    o1.y = (v1.y - mean) * rstd * g1.y + b1.y;
    o1.z = (v1.z - mean) * rstd * g1.z + b1.z;
    o1.w = (v1.w - mean) * rstd * g1.w + b1.w;
    float4* yr = (float4*)(y + (size_t)tok * 256);
    yr[lane] = o0;
    yr[lane + 32] = o1;
}

// ---------------------------------------------------------------------------
// Weight transpose: W[K,N] fp32 -> Wt[N,K] fp32
// ---------------------------------------------------------------------------
__global__ void smsa_transpose_kernel(const float* __restrict__ W,
                                      float* __restrict__ Wt, int K, int N) {
    __shared__ float t[32][33];
    int n0 = blockIdx.x * 32, k0 = blockIdx.y * 32;
    int tx = threadIdx.x, ty = threadIdx.y;
#pragma unroll
    for (int i = 0; i < 32; i += 8)
        t[ty + i][tx] = W[(size_t)(k0 + ty + i) * N + n0 + tx];
    __syncthreads();
#pragma unroll
    for (int i = 0; i < 32; i += 8)
        Wt[(size_t)(n0 + ty + i) * K + k0 + tx] = t[tx][ty + i];
}

// ---------------------------------------------------------------------------
// bf16 HMMA GEMM: C[M,N] = A[M,K] @ Bt[N,K]^T (+bias) (+res) (gelu opt)
// CTA tile 128x128, 512 threads (4x4 warps, warp tile 32x32), K-chunk 64.
// fp32 in/out, bf16 operands via in-flight conversion, fp32 accumulate.
// smem: A 16KB @0, B 16KB @16384 (SW128 swizzle, 128B rows), single stage,
// register prefetch of the next chunk.
// ---------------------------------------------------------------------------
__global__ __launch_bounds__(512, 1) void smsa_hgemm_kernel(
    const float* __restrict__ A, int lda,
    const float* __restrict__ Bt,
    float* __restrict__ Cm, int ldc,
    const float* __restrict__ bias,
    const float* __restrict__ res, int ldr,
    int K, int act) {
    extern __shared__ __align__(1024) char sm[];
    uint32_t sb = smem_u32(sm);
    const int tid = threadIdx.x;
    const int mb = blockIdx.y, nb = blockIdx.x;
    const int warp = tid >> 5, lane = tid & 31;
    const int wm = warp & 3, wn = warp >> 2;

    // loader mapping: threads 0-255 -> A, 256-511 -> B. 16 threads/row.
    const bool isB = tid >= 256;
    const int lt = tid & 255;
    const int lrow0 = lt >> 4;        // 0..15, +16 per pass
    const int f4 = lt & 15;           // float4 index within 64-float chunk row
    const int gld = isB ? K : lda;
    const float* gbase = isB ? Bt + (size_t)(nb * 128 + lrow0) * K + f4 * 4
                             : A + (size_t)(mb * 128 + lrow0) * lda + f4 * 4;
    const uint32_t sdst = sb + (isB ? 16384u : 0u);

    float4 pf[8];
#pragma unroll
    for (int p = 0; p < 8; p++)
        pf[p] = *(const float4*)(gbase + (size_t)p * 16 * gld);

    float acc[2][4][4];
#pragma unroll
    for (int mt = 0; mt < 2; mt++)
#pragma unroll
        for (int nt = 0; nt < 4; nt++)
#pragma unroll
            for (int q = 0; q < 4; q++) acc[mt][nt][q] = 0.0f;

    const int a_row = wm * 32 + (lane & 15);
    const int b_row = wn * 32 + (lane & 15);
    const int hi = lane >> 4;

    const int nch = K >> 6;
    for (int c = 0; c < nch; c++) {
        // store current prefetch into smem (fp32 -> bf16, SW128)
#pragma unroll
        for (int p = 0; p < 8; p++) {
            __nv_bfloat162 h0 = __float22bfloat162_rn(make_float2(pf[p].x, pf[p].y));
            __nv_bfloat162 h1 = __float22bfloat162_rn(make_float2(pf[p].z, pf[p].w));
            uint32_t u0 = *(uint32_t*)&h0, u1 = *(uint32_t*)&h1;
            uint32_t off = (uint32_t)(lrow0 + p * 16) * 128 + f4 * 8;
            asm volatile("st.shared.v2.b32 [%0], {%1,%2};"
                         :: "r"(sdst + SWZ128(off)), "r"(u0), "r"(u1));
        }
        __syncthreads();
        if (c + 1 < nch) {
            const float* g2 = gbase + (size_t)(c + 1) * 64;
#pragma unroll
            for (int p = 0; p < 8; p++)
                pf[p] = *(const float4*)(g2 + (size_t)p * 16 * gld);
        }
        // 4 k16 steps over this chunk
#pragma unroll
        for (int j = 0; j < 4; j++) {
            uint32_t af[2][4], bf[2][4];
            int ch = 2 * j + hi;
#pragma unroll
            for (int mt = 0; mt < 2; mt++) {
                uint32_t off = (uint32_t)(a_row + mt * 16) * 128 + ch * 16;
                uint32_t ad = sb + SWZ128(off);
                asm volatile(
                    "ldmatrix.sync.aligned.m8n8.x4.shared.b16 {%0,%1,%2,%3}, [%4];"
                    : "=r"(af[mt][0]), "=r"(af[mt][1]),
                      "=r"(af[mt][2]), "=r"(af[mt][3]) : "r"(ad));
            }
#pragma unroll
            for (int bt = 0; bt < 2; bt++) {
                uint32_t off = (uint32_t)(b_row + bt * 16) * 128 + ch * 16;
                uint32_t bd = sb + 16384u + SWZ128(off);
                asm volatile(
                    "ldmatrix.sync.aligned.m8n8.x4.shared.b16 {%0,%1,%2,%3}, [%4];"
                    : "=r"(bf[bt][0]), "=r"(bf[bt][1]),
                      "=r"(bf[bt][2]), "=r"(bf[bt][3]) : "r"(bd));
            }
#pragma unroll
            for (int mt = 0; mt < 2; mt++)
#pragma unroll
                for (int nt = 0; nt < 4; nt++) {
                    uint32_t b0 = bf[nt >> 1][nt & 1];
                    uint32_t b1 = bf[nt >> 1][(nt & 1) + 2];
                    asm volatile(
                        "mma.sync.aligned.m16n8k16.row.col.f32.bf16.bf16.f32 "
                        "{%0,%1,%2,%3}, {%4,%5,%6,%7}, {%8,%9}, {%0,%1,%2,%3};"
                        : "+f"(acc[mt][nt][0]), "+f"(acc[mt][nt][1]),
                          "+f"(acc[mt][nt][2]), "+f"(acc[mt][nt][3])
                        : "r"(af[mt][0]), "r"(af[mt][1]),
                          "r"(af[mt][2]), "r"(af[mt][3]),
                          "r"(b0), "r"(b1));
                }
        }
        __syncthreads();
    }

    // epilogue
    int qrow = lane >> 2, qcol = (lane & 3) * 2;
#pragma unroll
    for (int mt = 0; mt < 2; mt++)
#pragma unroll
        for (int half = 0; half < 2; half++) {
            int row = mb * 128 + wm * 32 + mt * 16 + qrow + half * 8;
#pragma unroll
            for (int nt = 0; nt < 4; nt++) {
                int col = nb * 128 + wn * 32 + nt * 8 + qcol;
                float v0 = acc[mt][nt][half * 2 + 0];
                float v1 = acc[mt][nt][half * 2 + 1];
                if (bias) {
                    float2 bv = *(const float2*)(bias + col);
                    v0 += bv.x; v1 += bv.y;
                }
                if (res) {
                    float2 rr = *(const float2*)(res + (size_t)row * ldr + col);
                    v0 += rr.x; v1 += rr.y;
                }
                if (act) { v0 = gelu_exact(v0); v1 = gelu_exact(v1); }
                *(float2*)(Cm + (size_t)row * ldc + col) = make_float2(v0, v1);
            }
        }
}

// ---------------------------------------------------------------------------
// Windowed attention with packed f32x2 FMA.
// ---------------------------------------------------------------------------
__global__ __launch_bounds__(256) void smsa_attn_kernel(
    const float* __restrict__ qkv, float* __restrict__ out) {
    extern __shared__ float smf[];
    float* Ks = smf;
    float* Vs = smf + 256 * 36;
    int win = blockIdx.x >> 3;
    int h = blockIdx.x & 7;
    int t = threadIdx.x;
    const float* base = qkv + (size_t)win * 256 * 768;

    unsigned long long q2[16];
    {
        const unsigned long long* qp =
            (const unsigned long long*)(base + (size_t)t * 768 + h * 32);
#pragma unroll
        for (int i = 0; i < 16; i++) q2[i] = qp[i];
    }
    {
        const float4* kp = (const float4*)(base + (size_t)t * 768 + 256 + h * 32);
        const float4* vp = (const float4*)(base + (size_t)t * 768 + 512 + h * 32);
#pragma unroll
        for (int i = 0; i < 8; i++) {
            *(float4*)&Ks[t * 36 + i * 4] = kp[i];
            *(float4*)&Vs[t * 36 + i * 4] = vp[i];
        }
    }
    __syncthreads();

    unsigned long long acc2[16];
#pragma unroll
    for (int d = 0; d < 16; d++) acc2[d] = 0ull;
    float mmax = -1e30f, l = 0.0f;
    const float sc = 0.17677669529663687f;

    for (int j = 0; j < 256; j++) {
        const unsigned long long* kj = (const unsigned long long*)&Ks[j * 36];
        unsigned long long s2 = 0ull;
#pragma unroll
        for (int i = 0; i < 16; i++) s2 = fma2(q2[i], kj[i], s2);
        float slo, shi;
        upk2(slo, shi, s2);
        float s = (slo + shi) * sc;
        if (s > mmax) {
            float corr = __expf(mmax - s);
            unsigned long long c2 = pk2(corr, corr);
            l *= corr;
#pragma unroll
            for (int d = 0; d < 16; d++) acc2[d] = mul2(acc2[d], c2);
            mmax = s;
        }
        float p = __expf(s - mmax);
        l += p;
        unsigned long long pp = pk2(p, p);
        const unsigned long long* vj = (const unsigned long long*)&Vs[j * 36];
#pragma unroll
        for (int i = 0; i < 16; i++) acc2[i] = fma2(pp, vj[i], acc2[i]);
    }
    float inv = 1.0f / l;
    unsigned long long iv = pk2(inv, inv);
    unsigned long long* op =
        (unsigned long long*)(out + ((size_t)(win * 256 + t)) * 256 + h * 32);
#pragma unroll
    for (int i = 0; i < 16; i++) op[i] = mul2(acc2[i], iv);
}

// ---------------------------------------------------------------------------
// Cross-attention gather/scatter and 1->16 attention
// ---------------------------------------------------------------------------
__device__ __forceinline__ void decode_f(int f, int& fw, int& base_t,
                                         int& gwin, int& tt) {
    int b = f >> 10, h = (f >> 7) & 7, w = (f >> 4) & 7;
    int r1 = (f >> 2) & 3, r2 = f & 3;
    fw = (b * 8 + h) * 8 + w;
    base_t = r1 * 64 + r2 * 4;
    int gr = h * 4 + r1, gc = w * 4 + r2;
    gwin = b * 4 + (gr >> 4) * 2 + (gc >> 4);
    tt = (gr & 15) * 16 + (gc & 15);
}

__global__ void smsa_gather_g_kernel(const float* __restrict__ x1,
                                     float* __restrict__ g) {
    int f = blockIdx.x, c = threadIdx.x;
    int fw, base_t, gwin, tt;
    decode_f(f, fw, base_t, gwin, tt);
    g[(size_t)f * 256 + c] = x1[((size_t)gwin * 256 + tt) * 256 + c];
}

__global__ void smsa_scatter_g_kernel(const float* __restrict__ g,
                                      float* __restrict__ out1) {
    int f = blockIdx.x, c = threadIdx.x;
    int fw, base_t, gwin, tt;
    decode_f(f, fw, base_t, gwin, tt);
    out1[((size_t)gwin * 256 + tt) * 256 + c] = g[(size_t)f * 256 + c];
}

__global__ __launch_bounds__(256) void smsa_xattn_kernel(
    const float* __restrict__ Q, const float* __restrict__ KV,
    float* __restrict__ AO) {
    int f = blockIdx.x;
    int h = threadIdx.x >> 5;
    int d = threadIdx.x & 31;
    int fw, base_t, gwin, tt;
    decode_f(f, fw, base_t, gwin, tt);
    float qd = Q[(size_t)f * 256 + h * 32 + d];
    const float sc = 0.17677669529663687f;
    float s[16];
#pragma unroll
    for (int j = 0; j < 16; j++) {
        int t = base_t + (j >> 2) * 16 + (j & 3);
        float kd = KV[((size_t)(fw * 256 + t)) * 512 + h * 32 + d];
        float pr = qd * kd;
#pragma unroll
        for (int o = 16; o > 0; o >>= 1)
            pr += __shfl_xor_sync(0xffffffffu, pr, o);
        s[j] = pr * sc;
    }
    float m = s[0];
#pragma unroll
    for (int j = 1; j < 16; j++) m = fmaxf(m, s[j]);
    float l = 0.0f, p[16];
#pragma unroll
    for (int j = 0; j < 16; j++) {
        p[j] = __expf(s[j] - m);
        l += p[j];
    }
    float inv = 1.0f / l;
    float acc = 0.0f;
#pragma unroll
    for (int j = 0; j < 16; j++) {
        int t = base_t + (j >> 2) * 16 + (j & 3);
        acc = fmaf(p[j], KV[((size_t)(fw * 256 + t)) * 512 + 256 + h * 32 + d], acc);
    }
    AO[(size_t)f * 256 + h * 32 + d] = acc * inv;
}

// ---------------------------------------------------------------------------
// Host side
// ---------------------------------------------------------------------------
static void run_hgemm(const float* A, int lda, const float* Bt,
                      float* Cm, int ldc, const float* bias,
                      const float* res, int ldr, int M, int N, int K, int act) {
    dim3 grid(N / 128, M / 128);
    smsa_hgemm_kernel<<<grid, 512, GEMM_SMEM>>>(A, lda, Bt, Cm, ldc, bias,
                                                res, ldr, K, act);
}

static void run_ln(const float* x, float* y, const float* g, const float* b, int ntok) {
    smsa_ln_kernel<<<ntok / 8, 256>>>(x, y, g, b);
}

struct BlockParams {
    const float *ln1g, *ln1b, *wqkvT, *bqkv, *woT, *bo;
    const float *ln2g, *ln2b, *w1T, *b1, *w2T, *b2;
};

static void run_sattn_block(float* X, float* outC, int ntok, const BlockParams& P,
                            float* H, float* QKV, float* T) {
    run_ln(X, H, P.ln1g, P.ln1b, ntok);
    run_hgemm(H, 256, P.wqkvT, QKV, 768, P.bqkv, nullptr, 0, ntok, 768, 256, 0);
    smsa_attn_kernel<<<(ntok / 256) * 8, 256, ATTN_SMEM>>>(QKV, H);
    run_hgemm(H, 256, P.woT, X, 256, P.bo, X, 256, ntok, 256, 256, 0);
    run_ln(X, H, P.ln2g, P.ln2b, ntok);
    run_hgemm(H, 256, P.w1T, T, 1024, P.b1, nullptr, 0, ntok, 1024, 256, 1);
    run_hgemm(T, 1024, P.w2T, outC, 256, P.b2, X, 256, ntok, 256, 1024, 0);
}

extern "C" void kernel_launch(void* const* d_in, const int* in_sizes, int n_in,
                              void* d_out, int out_size) {
    const float* scale0 = (const float*)d_in[0];
    const float* scale1 = (const float*)d_in[1];
    const float* pe_w1 = (const float*)d_in[2];
    const float* pe_b1 = (const float*)d_in[3];
    const float* pe_w2 = (const float*)d_in[4];
    const float* ln1_g = (const float*)d_in[5];
    const float* ln1_b = (const float*)d_in[6];
    const float* wqkv = (const float*)d_in[7];
    const float* bqkv = (const float*)d_in[8];
    const float* wo = (const float*)d_in[9];
    const float* bo = (const float*)d_in[10];
    const float* ln2_g = (const float*)d_in[11];
    const float* ln2_b = (const float*)d_in[12];
    const float* mw1 = (const float*)d_in[13];
    const float* mb1 = (const float*)d_in[14];
    const float* mw2 = (const float*)d_in[15];
    const float* mb2 = (const float*)d_in[16];
    float* out = (float*)d_out;
    float* out0 = out;
    float* out1 = out + (size_t)65536 * 256;

    float *X0, *X1, *H, *QKV, *T, *PE, *G, *WT;
    cudaGetSymbolAddress((void**)&X0, g_X0);
    cudaGetSymbolAddress((void**)&X1, g_X1);
    cudaGetSymbolAddress((void**)&H, g_H);
    cudaGetSymbolAddress((void**)&QKV, g_QKV);
    cudaGetSymbolAddress((void**)&T, g_T);
    cudaGetSymbolAddress((void**)&PE, g_PE);
    cudaGetSymbolAddress((void**)&G, g_G);
    cudaGetSymbolAddress((void**)&WT, g_WT);

    cudaFuncSetAttribute(smsa_attn_kernel,
                         cudaFuncAttributeMaxDynamicSharedMemorySize, ATTN_SMEM);
    cudaFuncSetAttribute(smsa_hgemm_kernel,
                         cudaFuncAttributeMaxDynamicSharedMemorySize, GEMM_SMEM);

    // 0) weight transposes (fp32, [K,N]->[N,K])
    auto tr = [&](const float* W, float* Wt, int K_, int N_) {
        smsa_transpose_kernel<<<dim3(N_ / 32, K_ / 32), dim3(32, 8)>>>(W, Wt, K_, N_);
    };
    tr(wqkv,           WT + 0,       256, 768);
    tr(wqkv + 196608,  WT + 786432,  256, 768);
    tr(wo,             WT + 196608,  256, 256);
    tr(wo + 65536,     WT + 983040,  256, 256);
    tr(mw1,            WT + 262144,  256, 1024);
    tr(mw1 + 262144,   WT + 1048576, 256, 1024);
    tr(mw2,            WT + 524288,  1024, 256);
    tr(mw2 + 262144,   WT + 1310720, 1024, 256);

    // 1) position embedding tables + add
    smsa_posemb_kernel<<<dim3(256, 2), 256>>>(pe_w1, pe_b1, pe_w2, PE);
    smsa_add_pe_kernel<<<16384, 256>>>(scale0, PE, X0);
    smsa_add_pe_kernel<<<1024, 256>>>(scale1, PE + 65536, X1);

    // 2) bottom-up max-pool into global tokens
    smsa_pool_kernel<<<4096, 256>>>(X0, X1);

    // 3) sattn blocks
    BlockParams P1 = {ln1_g + 256, ln1_b + 256, WT + 786432, bqkv + 768,
                      WT + 983040, bo + 256, ln2_g + 256, ln2_b + 256,
                      WT + 1048576, mb1 + 1024, WT + 1310720, mb2 + 256};
    BlockParams P0 = {ln1_g, ln1_b, WT + 0, bqkv, WT + 196608, bo,
                      ln2_g, ln2_b, WT + 262144, mb1, WT + 524288, mb2};
    run_sattn_block(X1, X1, NTOK1, P1, H, QKV, T);
    run_sattn_block(X0, out0, NTOK0, P0, H, QKV, T);

    // 4) one2one cross-attention (params scale 1)
    run_ln(out0, H, P1.ln1g, P1.ln1b, NTOK0);
    // K|V = ln(o0) @ wqkv1[:,256:768] -> [65536,512]
    run_hgemm(H, 256, P1.wqkvT + 256 * 256, QKV, 512, bqkv + 768 + 256,
              nullptr, 0, NTOK0, 512, 256, 0);
    smsa_gather_g_kernel<<<4096, 256>>>(X1, G);

    float* S0 = T;
    float* Sq = T + (size_t)4096 * 256;
    float* AO = T + (size_t)2 * 4096 * 256;
    float* Sg = T + (size_t)3 * 4096 * 256;
    float* Th = T + (size_t)4 * 4096 * 256;

    run_ln(G, S0, P1.ln1g, P1.ln1b, NTOK1);
    run_hgemm(S0, 256, P1.wqkvT, Sq, 256, bqkv + 768, nullptr, 0, NTOK1, 256, 256, 0);
    smsa_xattn_kernel<<<4096, 256>>>(Sq, QKV, AO);
    run_hgemm(AO, 256, P1.woT, G, 256, P1.bo, G, 256, NTOK1, 256, 256, 0);
    run_ln(G, Sg, P1.ln2g, P1.ln2b, NTOK1);
    run_hgemm(Sg, 256, P1.w1T, Th, 1024, P1.b1, nullptr, 0, NTOK1, 1024, 256, 1);
    run_hgemm(Th, 1024, P1.w2T, G, 256, P1.b2, G, 256, NTOK1, 256, 1024, 0);

    // 5) scatter g back to o1 window layout
    smsa_scatter_g_kernel<<<4096, 256>>>(G, out1);
}

// round 4
// speedup vs baseline: 3.0347x; 1.2757x over previous
#include <cuda_runtime.h>
#include <cuda_bf16.h>
#include <math.h>
#include <stdint.h>

// ---------------------------------------------------------------------------
// StackMSA round 4: bf16 activations between ops, cp.async 3-stage HMMA GEMM,
// f32x2 attention on bf16 qkv.
// B=4, H=W=8, M=16, C=256, NH=8, HD=32, GW=2
// out: [272, 256, 256] f32 = [o0 (256 win) ; o1 (16 win)]
// ---------------------------------------------------------------------------

#define NTOK0 65536
#define NTOK1 4096
#define ATTN_SMEM (2 * 256 * 36 * 4)
#define GEMM_SMEM 98304

// fp32 residual streams + scratch
__device__ float g_X0[65536 * 256];
__device__ float g_X1[4096 * 256];
__device__ float g_PE[2 * 256 * 256];
__device__ float g_G[4096 * 256];
// bf16 activation streams
__device__ __nv_bfloat16 g_Hb[65536 * 256];
__device__ __nv_bfloat16 g_QKVb[65536 * 768];
__device__ __nv_bfloat16 g_Tb[65536 * 1024];
__device__ __nv_bfloat16 g_WT[1572864];   // transposed weights [N,K] bf16

__device__ __forceinline__ float gelu_exact(float x) {
    return 0.5f * x * (1.0f + erff(x * 0.70710678118654752f));
}

__device__ __forceinline__ uint32_t smem_u32(const void* p) {
    uint32_t a;
    asm("{ .reg .u64 t; cvta.to.shared.u64 t, %1; cvt.u32.u64 %0, t; }"
        : "=r"(a) : "l"(p));
    return a;
}

#define SWZ128(o) ((o) ^ (((o) >> 3) & 0x70))
#define CP16(dst, src) \
    asm volatile("cp.async.cg.shared.global [%0], [%1], 16;" :: "r"(dst), "l"(src))
#define CPCOMMIT() asm volatile("cp.async.commit_group;" ::: "memory")
#define CPWAIT1() asm volatile("cp.async.wait_group 1;" ::: "memory")

// packed f32x2
__device__ __forceinline__ unsigned long long pk2(float x, float y) {
    unsigned long long r;
    asm("mov.b64 %0, {%1, %2};" : "=l"(r) : "f"(x), "f"(y));
    return r;
}
__device__ __forceinline__ void upk2(float& x, float& y, unsigned long long v) {
    asm("mov.b64 {%0, %1}, %2;" : "=f"(x), "=f"(y) : "l"(v));
}
__device__ __forceinline__ unsigned long long fma2(unsigned long long a,
                                                   unsigned long long b,
                                                   unsigned long long c) {
    unsigned long long d;
    asm("fma.rn.f32x2 %0, %1, %2, %3;" : "=l"(d) : "l"(a), "l"(b), "l"(c));
    return d;
}
__device__ __forceinline__ unsigned long long mul2(unsigned long long a,
                                                   unsigned long long b) {
    unsigned long long d;
    asm("mul.rn.f32x2 %0, %1, %2;" : "=l"(d) : "l"(a), "l"(b));
    return d;
}

__device__ __forceinline__ void cvt8(uint4 u, float* o) {
    const __nv_bfloat162* p = (const __nv_bfloat162*)&u;
#pragma unroll
    for (int i = 0; i < 4; i++) {
        float2 f = __bfloat1622float2(p[i]);
        o[2 * i] = f.x;
        o[2 * i + 1] = f.y;
    }
}
__device__ __forceinline__ uint32_t bf2u(float x, float y) {
    __nv_bfloat162 h = __float22bfloat162_rn(make_float2(x, y));
    return *(uint32_t*)&h;
}

// ---------------------------------------------------------------------------
// Position embedding table + add (fp32)
// ---------------------------------------------------------------------------
__global__ void smsa_posemb_kernel(const float* __restrict__ w1,
                                   const float* __restrict__ b1,
                                   const float* __restrict__ w2,
                                   float* __restrict__ pe) {
    int t = blockIdx.x, s = blockIdx.y, tid = threadIdx.x;
    __shared__ float hid[512];
    float c0 = (float)((t >> 4) - 8) * 0.125f;
    float c1 = (float)((t & 15) - 8) * 0.125f;
    const float* W1 = w1 + s * 1024;
    const float* B1 = b1 + s * 512;
    for (int k = tid; k < 512; k += 256)
        hid[k] = fmaxf(fmaf(c0, W1[k], fmaf(c1, W1[512 + k], B1[k])), 0.0f);
    __syncthreads();
    const float* W2 = w2 + s * 512 * 256;
    float acc = 0.0f;
#pragma unroll 8
    for (int k = 0; k < 512; k++) acc = fmaf(hid[k], W2[k * 256 + tid], acc);
    pe[s * 65536 + t * 256 + tid] = acc;
}

__global__ void smsa_add_pe_kernel(const float* __restrict__ x,
                                   const float* __restrict__ pe,
                                   float* __restrict__ y) {
    size_t i = (size_t)blockIdx.x * 256 + threadIdx.x;
    float4 a = ((const float4*)x)[i];
    float4 p = ((const float4*)pe)[i & 16383];
    float4 r;
    r.x = a.x + p.x; r.y = a.y + p.y; r.z = a.z + p.z; r.w = a.w + p.w;
    ((float4*)y)[i] = r;
}

__global__ void smsa_pool_kernel(const float* __restrict__ x0,
                                 float* __restrict__ x1) {
    int gid = blockIdx.x, c = threadIdx.x;
    int b = gid >> 10, gr = (gid >> 5) & 31, gc = gid & 31;
    int h = gr >> 2, r1 = gr & 3, w = gc >> 2, r2 = gc & 3;
    int fw = (b * 8 + h) * 8 + w;
    const float* base = x0 + ((size_t)fw * 256 + r1 * 64 + r2 * 4) * 256 + c;
    float m = -1e30f;
#pragma unroll
    for (int p1 = 0; p1 < 4; p1++)
#pragma unroll
        for (int p2 = 0; p2 < 4; p2++)
            m = fmaxf(m, base[(p1 * 16 + p2) * 256]);
    int gwin = b * 4 + (gr >> 4) * 2 + (gc >> 4);
    int tt = (gr & 15) * 16 + (gc & 15);
    x1[((size_t)gwin * 256 + tt) * 256 + c] += m;
}

// ---------------------------------------------------------------------------
// LayerNorm over C=256 (fp32 in, bf16 out), one warp per token
// ---------------------------------------------------------------------------
__global__ __launch_bounds__(256) void smsa_ln_kernel(
    const float* __restrict__ x, __nv_bfloat16* __restrict__ y,
    const float* __restrict__ gg, const float* __restrict__ bb) {
    int tok = blockIdx.x * 8 + (threadIdx.x >> 5);
    int lane = threadIdx.x & 31;
    const float4* row = (const float4*)(x + (size_t)tok * 256);
    float4 v0 = row[lane], v1 = row[lane + 32];
    float s = v0.x + v0.y + v0.z + v0.w + v1.x + v1.y + v1.z + v1.w;
    float ss = v0.x * v0.x + v0.y * v0.y + v0.z * v0.z + v0.w * v0.w +
               v1.x * v1.x + v1.y * v1.y + v1.z * v1.z + v1.w * v1.w;
#pragma unroll
    for (int o = 16; o > 0; o >>= 1) {
        s += __shfl_xor_sync(0xffffffffu, s, o);
        ss += __shfl_xor_sync(0xffffffffu, ss, o);
    }
    float mean = s * 0.00390625f;
    float var = ss * 0.00390625f - mean * mean;
    float rstd = rsqrtf(var + 1e-5f);
    float4 g0 = ((const float4*)gg)[lane], g1 = ((const float4*)gg)[lane + 32];
    float4 b0 = ((const float4*)bb)[lane], b1 = ((const float4*)bb)[lane + 32];
    uint2 o0, o1;
    o0.x = bf2u((v0.x - mean) * rstd * g0.x + b0.x, (v0.y - mean) * rstd * g0.y + b0.y);
    o0.y = bf2u((v0.z - mean) * rstd * g0.z + b0.z, (v0.w - mean) * rstd * g0.w + b0.w);
    o1.x = bf2u((v1.x - mean) * rstd * g1.x + b1.x, (v1.y - mean) * rstd * g1.y + b1.y);
    o1.y = bf2u((v1.z - mean) * rstd * g1.z + b1.z, (v1.w - mean) * rstd * g1.w + b1.w);
    uint2* yr = (uint2*)(y + (size_t)tok * 256);
    yr[lane] = o0;
    yr[lane + 32] = o1;
}

// ---------------------------------------------------------------------------
// Weight transpose: W[K,N] fp32 -> Wt[N,K] bf16
// ---------------------------------------------------------------------------
__global__ void smsa_transpose_kernel(const float* __restrict__ W,
                                      __nv_bfloat16* __restrict__ Wt, int K, int N) {
    __shared__ float t[32][33];
    int n0 = blockIdx.x * 32, k0 = blockIdx.y * 32;
    int tx = threadIdx.x, ty = threadIdx.y;
#pragma unroll
    for (int i = 0; i < 32; i += 8)
        t[ty + i][tx] = W[(size_t)(k0 + ty + i) * N + n0 + tx];
    __syncthreads();
#pragma unroll
    for (int i = 0; i < 32; i += 8)
        Wt[(size_t)(n0 + ty + i) * K + k0 + tx] = __float2bfloat16(t[tx][ty + i]);
}

// ---------------------------------------------------------------------------
// bf16 HMMA GEMM with cp.async 3-stage pipeline.
// C[M,N] = A[M,K] @ Bt[N,K]^T (+bias) (+res fp32) (gelu opt), out fp32 or bf16.
// CTA tile 128x128, 512 threads (4x4 warps, warp tile 32x32), K-chunk 64.
// smem stage (32KB): A 16KB + B 16KB, SW128, 128B rows. 3 stages.
// ---------------------------------------------------------------------------
__global__ __launch_bounds__(512, 1) void smsa_hgemm_kernel(
    const __nv_bfloat16* __restrict__ A, int lda,
    const __nv_bfloat16* __restrict__ Bt,
    void* __restrict__ Cm, int ldc,
    const float* __restrict__ bias,
    const float* __restrict__ res, int ldr,
    int K, int act, int outbf) {
    extern __shared__ __align__(1024) char sm[];
    uint32_t sb = smem_u32(sm);
    const int tid = threadIdx.x;
    const int mb = blockIdx.y, nb = blockIdx.x;
    const int warp = tid >> 5, lane = tid & 31;
    const int wm = warp & 3, wn = warp >> 2;

    // loader mapping: threads 0-255 -> A tile, 256-511 -> B tile; 4x16B each
    const bool isB = tid >= 256;
    const int lt = tid & 255;
    const int gld = isB ? K : lda;
    const __nv_bfloat16* gsrc =
        isB ? Bt + (size_t)(nb * 128) * K : A + (size_t)(mb * 128) * lda;
    const uint32_t soff = isB ? 16384u : 0u;

    const int nch = K >> 6;
    auto copy_stage = [&](int c, int s) {
        uint32_t sbase = sb + (uint32_t)s * 32768u + soff;
        const __nv_bfloat16* g = gsrc + c * 64;
#pragma unroll
        for (int p = 0; p < 4; p++) {
            int u = p * 256 + lt;
            int row = u >> 3, c16 = u & 7;
            CP16(sbase + SWZ128((uint32_t)row * 128 + c16 * 16),
                 g + (size_t)row * gld + c16 * 8);
        }
    };

    float acc[2][4][4];
#pragma unroll
    for (int mt = 0; mt < 2; mt++)
#pragma unroll
        for (int nt = 0; nt < 4; nt++)
#pragma unroll
            for (int q = 0; q < 4; q++) acc[mt][nt][q] = 0.0f;

    const int a_row = wm * 32 + (lane & 15);
    const int b_row = wn * 32 + (lane & 15);
    const int hi = lane >> 4;

    copy_stage(0, 0);
    CPCOMMIT();
    if (nch > 1) copy_stage(1, 1);
    CPCOMMIT();

    for (int c = 0; c < nch; c++) {
        CPWAIT1();
        __syncthreads();
        // prefetch stage c+2 into buffer (c+2)%3 (free: consumed at iter c-1)
        if (c + 2 < nch) copy_stage(c + 2, (c + 2) % 3);
        CPCOMMIT();

        uint32_t abase = sb + (uint32_t)(c % 3) * 32768u;
        uint32_t bbase = abase + 16384u;
#pragma unroll
        for (int j = 0; j < 4; j++) {
            uint32_t af[2][4], bf[2][4];
            int ch = 2 * j + hi;
#pragma unroll
            for (int mt = 0; mt < 2; mt++) {
                uint32_t ad = abase + SWZ128((uint32_t)(a_row + mt * 16) * 128 + ch * 16);
                asm volatile(
                    "ldmatrix.sync.aligned.m8n8.x4.shared.b16 {%0,%1,%2,%3}, [%4];"
                    : "=r"(af[mt][0]), "=r"(af[mt][1]),
                      "=r"(af[mt][2]), "=r"(af[mt][3]) : "r"(ad));
            }
#pragma unroll
            for (int bt = 0; bt < 2; bt++) {
                uint32_t bd = bbase + SWZ128((uint32_t)(b_row + bt * 16) * 128 + ch * 16);
                asm volatile(
                    "ldmatrix.sync.aligned.m8n8.x4.shared.b16 {%0,%1,%2,%3}, [%4];"
                    : "=r"(bf[bt][0]), "=r"(bf[bt][1]),
                      "=r"(bf[bt][2]), "=r"(bf[bt][3]) : "r"(bd));
            }
#pragma unroll
            for (int mt = 0; mt < 2; mt++)
#pragma unroll
                for (int nt = 0; nt < 4; nt++) {
                    uint32_t b0 = bf[nt >> 1][nt & 1];
                    uint32_t b1 = bf[nt >> 1][(nt & 1) + 2];
                    asm volatile(
                        "mma.sync.aligned.m16n8k16.row.col.f32.bf16.bf16.f32 "
                        "{%0,%1,%2,%3}, {%4,%5,%6,%7}, {%8,%9}, {%0,%1,%2,%3};"
                        : "+f"(acc[mt][nt][0]), "+f"(acc[mt][nt][1]),
                          "+f"(acc[mt][nt][2]), "+f"(acc[mt][nt][3])
                        : "r"(af[mt][0]), "r"(af[mt][1]),
                          "r"(af[mt][2]), "r"(af[mt][3]),
                          "r"(b0), "r"(b1));
                }
        }
        __syncthreads();
    }

    // epilogue
    int qrow = lane >> 2, qcol = (lane & 3) * 2;
#pragma unroll
    for (int mt = 0; mt < 2; mt++)
#pragma unroll
        for (int half = 0; half < 2; half++) {
            int row = mb * 128 + wm * 32 + mt * 16 + qrow + half * 8;
#pragma unroll
            for (int nt = 0; nt < 4; nt++) {
                int col = nb * 128 + wn * 32 + nt * 8 + qcol;
                float v0 = acc[mt][nt][half * 2 + 0];
                float v1 = acc[mt][nt][half * 2 + 1];
                if (bias) {
                    float2 bv = *(const float2*)(bias + col);
                    v0 += bv.x; v1 += bv.y;
                }
                if (res) {
                    float2 rr = *(const float2*)(res + (size_t)row * ldr + col);
                    v0 += rr.x; v1 += rr.y;
                }
                if (act) { v0 = gelu_exact(v0); v1 = gelu_exact(v1); }
                if (outbf) {
                    *(uint32_t*)((__nv_bfloat16*)Cm + (size_t)row * ldc + col) =
                        bf2u(v0, v1);
                } else {
                    *(float2*)((float*)Cm + (size_t)row * ldc + col) =
                        make_float2(v0, v1);
                }
            }
        }
}

// ---------------------------------------------------------------------------
// Windowed attention, bf16 qkv in, bf16 out, packed f32x2 FMA in fp32.
// ---------------------------------------------------------------------------
__global__ __launch_bounds__(256) void smsa_attn_kernel(
    const __nv_bfloat16* __restrict__ qkv, __nv_bfloat16* __restrict__ out) {
    extern __shared__ float smf[];
    float* Ks = smf;
    float* Vs = smf + 256 * 36;
    int win = blockIdx.x >> 3;
    int h = blockIdx.x & 7;
    int t = threadIdx.x;
    const __nv_bfloat16* base = qkv + (size_t)win * 256 * 768;

    float q[32];
    {
        const uint4* qp = (const uint4*)(base + (size_t)t * 768 + h * 32);
#pragma unroll
        for (int i = 0; i < 4; i++) cvt8(qp[i], q + 8 * i);
    }
    unsigned long long q2[16];
#pragma unroll
    for (int i = 0; i < 16; i++) q2[i] = pk2(q[2 * i], q[2 * i + 1]);
    {
        const uint4* kp = (const uint4*)(base + (size_t)t * 768 + 256 + h * 32);
        const uint4* vp = (const uint4*)(base + (size_t)t * 768 + 512 + h * 32);
        float kv[8];
#pragma unroll
        for (int i = 0; i < 4; i++) {
            cvt8(kp[i], kv);
            *(float4*)&Ks[t * 36 + i * 8] = make_float4(kv[0], kv[1], kv[2], kv[3]);
            *(float4*)&Ks[t * 36 + i * 8 + 4] = make_float4(kv[4], kv[5], kv[6], kv[7]);
            cvt8(vp[i], kv);
            *(float4*)&Vs[t * 36 + i * 8] = make_float4(kv[0], kv[1], kv[2], kv[3]);
            *(float4*)&Vs[t * 36 + i * 8 + 4] = make_float4(kv[4], kv[5], kv[6], kv[7]);
        }
    }
    __syncthreads();

    unsigned long long acc2[16];
#pragma unroll
    for (int d = 0; d < 16; d++) acc2[d] = 0ull;
    float mmax = -1e30f, l = 0.0f;
    const float sc = 0.17677669529663687f;

    for (int j = 0; j < 256; j++) {
        const unsigned long long* kj = (const unsigned long long*)&Ks[j * 36];
        unsigned long long s2 = 0ull;
#pragma unroll
        for (int i = 0; i < 16; i++) s2 = fma2(q2[i], kj[i], s2);
        float slo, shi;
        upk2(slo, shi, s2);
        float s = (slo + shi) * sc;
        if (s > mmax) {
            float corr = __expf(mmax - s);
            unsigned long long c2 = pk2(corr, corr);
            l *= corr;
#pragma unroll
            for (int d = 0; d < 16; d++) acc2[d] = mul2(acc2[d], c2);
            mmax = s;
        }
        float p = __expf(s - mmax);
        l += p;
        unsigned long long pp = pk2(p, p);
        const unsigned long long* vj = (const unsigned long long*)&Vs[j * 36];
#pragma unroll
        for (int i = 0; i < 16; i++) acc2[i] = fma2(pp, vj[i], acc2[i]);
    }
    float inv = 1.0f / l;
    uint32_t ov[16];
#pragma unroll
    for (int i = 0; i < 16; i++) {
        float x, y;
        upk2(x, y, acc2[i]);
        ov[i] = bf2u(x * inv, y * inv);
    }
    uint4* op = (uint4*)(out + ((size_t)(win * 256 + t)) * 256 + h * 32);
#pragma unroll
    for (int i = 0; i < 4; i++) op[i] = ((uint4*)ov)[i];
}

// ---------------------------------------------------------------------------
// Cross-attention gather/scatter and 1->16 attention
// ---------------------------------------------------------------------------
__device__ __forceinline__ void decode_f(int f, int& fw, int& base_t,
                                         int& gwin, int& tt) {
    int b = f >> 10, h = (f >> 7) & 7, w = (f >> 4) & 7;
    int r1 = (f >> 2) & 3, r2 = f & 3;
    fw = (b * 8 + h) * 8 + w;
    base_t = r1 * 64 + r2 * 4;
    int gr = h * 4 + r1, gc = w * 4 + r2;
    gwin = b * 4 + (gr >> 4) * 2 + (gc >> 4);
    tt = (gr & 15) * 16 + (gc & 15);
}

__global__ void smsa_gather_g_kernel(const float* __restrict__ x1,
                                     float* __restrict__ g) {
    int f = blockIdx.x, c = threadIdx.x;
    int fw, base_t, gwin, tt;
    decode_f(f, fw, base_t, gwin, tt);
    g[(size_t)f * 256 + c] = x1[((size_t)gwin * 256 + tt) * 256 + c];
}

__global__ void smsa_scatter_g_kernel(const float* __restrict__ g,
                                      float* __restrict__ out1) {
    int f = blockIdx.x, c = threadIdx.x;
    int fw, base_t, gwin, tt;
    decode_f(f, fw, base_t, gwin, tt);
    out1[((size_t)gwin * 256 + tt) * 256 + c] = g[(size_t)f * 256 + c];
}

__global__ __launch_bounds__(256) void smsa_xattn_kernel(
    const __nv_bfloat16* __restrict__ Q, const __nv_bfloat16* __restrict__ KV,
    __nv_bfloat16* __restrict__ AO) {
    int f = blockIdx.x;
    int h = threadIdx.x >> 5;
    int d = threadIdx.x & 31;
    int fw, base_t, gwin, tt;
    decode_f(f, fw, base_t, gwin, tt);
    float qd = __bfloat162float(Q[(size_t)f * 256 + h * 32 + d]);
    const float sc = 0.17677669529663687f;
    float s[16];
#pragma unroll
    for (int j = 0; j < 16; j++) {
        int t = base_t + (j >> 2) * 16 + (j & 3);
        float kd = __bfloat162float(KV[((size_t)(fw * 256 + t)) * 512 + h * 32 + d]);
        float pr = qd * kd;
#pragma unroll
        for (int o = 16; o > 0; o >>= 1)
            pr += __shfl_xor_sync(0xffffffffu, pr, o);
        s[j] = pr * sc;
    }
    float m = s[0];
#pragma unroll
    for (int j = 1; j < 16; j++) m = fmaxf(m, s[j]);
    float l = 0.0f, p[16];
#pragma unroll
    for (int j = 0; j < 16; j++) {
        p[j] = __expf(s[j] - m);
        l += p[j];
    }
    float inv = 1.0f / l;
    float acc = 0.0f;
#pragma unroll
    for (int j = 0; j < 16; j++) {
        int t = base_t + (j >> 2) * 16 + (j & 3);
        acc = fmaf(p[j], __bfloat162float(
                        KV[((size_t)(fw * 256 + t)) * 512 + 256 + h * 32 + d]),
                   acc);
    }
    AO[(size_t)f * 256 + h * 32 + d] = __float2bfloat16(acc * inv);
}

// ---------------------------------------------------------------------------
// Host side
// ---------------------------------------------------------------------------
static void run_hgemm(const __nv_bfloat16* A, int lda, const __nv_bfloat16* Bt,
                      void* Cm, int ldc, const float* bias,
                      const float* res, int ldr, int M, int N, int K,
                      int act, int outbf) {
    dim3 grid(N / 128, M / 128);
    smsa_hgemm_kernel<<<grid, 512, GEMM_SMEM>>>(A, lda, Bt, Cm, ldc, bias,
                                                res, ldr, K, act, outbf);
}

static void run_ln(const float* x, __nv_bfloat16* y, const float* g,
                   const float* b, int ntok) {
    smsa_ln_kernel<<<ntok / 8, 256>>>(x, y, g, b);
}

struct BlockParams {
    const float *ln1g, *ln1b;
    const __nv_bfloat16* wqkvT;
    const float* bqkv;
    const __nv_bfloat16* woT;
    const float *bo, *ln2g, *ln2b;
    const __nv_bfloat16* w1T;
    const float* b1;
    const __nv_bfloat16* w2T;
    const float* b2;
};

static void run_sattn_block(float* X, float* outC, int ntok, const BlockParams& P,
                            __nv_bfloat16* Hb, __nv_bfloat16* QKVb,
                            __nv_bfloat16* Tb) {
    run_ln(X, Hb, P.ln1g, P.ln1b, ntok);
    run_hgemm(Hb, 256, P.wqkvT, QKVb, 768, P.bqkv, nullptr, 0, ntok, 768, 256, 0, 1);
    smsa_attn_kernel<<<(ntok / 256) * 8, 256, ATTN_SMEM>>>(QKVb, Hb);
    run_hgemm(Hb, 256, P.woT, X, 256, P.bo, X, 256, ntok, 256, 256, 0, 0);
    run_ln(X, Hb, P.ln2g, P.ln2b, ntok);
    run_hgemm(Hb, 256, P.w1T, Tb, 1024, P.b1, nullptr, 0, ntok, 1024, 256, 1, 1);
    run_hgemm(Tb, 1024, P.w2T, outC, 256, P.b2, X, 256, ntok, 256, 1024, 0, 0);
}

extern "C" void kernel_launch(void* const* d_in, const int* in_sizes, int n_in,
                              void* d_out, int out_size) {
    const float* scale0 = (const float*)d_in[0];
    const float* scale1 = (const float*)d_in[1];
    const float* pe_w1 = (const float*)d_in[2];
    const float* pe_b1 = (const float*)d_in[3];
    const float* pe_w2 = (const float*)d_in[4];
    const float* ln1_g = (const float*)d_in[5];
    const float* ln1_b = (const float*)d_in[6];
    const float* wqkv = (const float*)d_in[7];
    const float* bqkv = (const float*)d_in[8];
    const float* wo = (const float*)d_in[9];
    const float* bo = (const float*)d_in[10];
    const float* ln2_g = (const float*)d_in[11];
    const float* ln2_b = (const float*)d_in[12];
    const float* mw1 = (const float*)d_in[13];
    const float* mb1 = (const float*)d_in[14];
    const float* mw2 = (const float*)d_in[15];
    const float* mb2 = (const float*)d_in[16];
    float* out = (float*)d_out;
    float* out0 = out;
    float* out1 = out + (size_t)65536 * 256;

    float *X0, *X1, *PE, *G;
    __nv_bfloat16 *Hb, *QKVb, *Tb, *WT;
    cudaGetSymbolAddress((void**)&X0, g_X0);
    cudaGetSymbolAddress((void**)&X1, g_X1);
    cudaGetSymbolAddress((void**)&PE, g_PE);
    cudaGetSymbolAddress((void**)&G, g_G);
    cudaGetSymbolAddress((void**)&Hb, g_Hb);
    cudaGetSymbolAddress((void**)&QKVb, g_QKVb);
    cudaGetSymbolAddress((void**)&Tb, g_Tb);
    cudaGetSymbolAddress((void**)&WT, g_WT);

    cudaFuncSetAttribute(smsa_attn_kernel,
                         cudaFuncAttributeMaxDynamicSharedMemorySize, ATTN_SMEM);
    cudaFuncSetAttribute(smsa_hgemm_kernel,
                         cudaFuncAttributeMaxDynamicSharedMemorySize, GEMM_SMEM);

    // 0) weight transposes ([K,N] fp32 -> [N,K] bf16)
    auto tr = [&](const float* W, __nv_bfloat16* Wt, int K_, int N_) {
        smsa_transpose_kernel<<<dim3(N_ / 32, K_ / 32), dim3(32, 8)>>>(W, Wt, K_, N_);
    };
    tr(wqkv,           WT + 0,       256, 768);
    tr(wqkv + 196608,  WT + 786432,  256, 768);
    tr(wo,             WT + 196608,  256, 256);
    tr(wo + 65536,     WT + 983040,  256, 256);
    tr(mw1,            WT + 262144,  256, 1024);
    tr(mw1 + 262144,   WT + 1048576, 256, 1024);
    tr(mw2,            WT + 524288,  1024, 256);
    tr(mw2 + 262144,   WT + 1310720, 1024, 256);

    // 1) position embedding tables + add
    smsa_posemb_kernel<<<dim3(256, 2), 256>>>(pe_w1, pe_b1, pe_w2, PE);
    smsa_add_pe_kernel<<<16384, 256>>>(scale0, PE, X0);
    smsa_add_pe_kernel<<<1024, 256>>>(scale1, PE + 65536, X1);

    // 2) bottom-up max-pool into global tokens
    smsa_pool_kernel<<<4096, 256>>>(X0, X1);

    // 3) sattn blocks
    BlockParams P1 = {ln1_g + 256, ln1_b + 256, WT + 786432, bqkv + 768,
                      WT + 983040, bo + 256, ln2_g + 256, ln2_b + 256,
                      WT + 1048576, mb1 + 1024, WT + 1310720, mb2 + 256};
    BlockParams P0 = {ln1_g, ln1_b, WT + 0, bqkv, WT + 196608, bo,
                      ln2_g, ln2_b, WT + 262144, mb1, WT + 524288, mb2};
    run_sattn_block(X1, X1, NTOK1, P1, Hb, QKVb, Tb);
    run_sattn_block(X0, out0, NTOK0, P0, Hb, QKVb, Tb);

    // 4) one2one cross-attention (params scale 1)
    run_ln(out0, Hb, P1.ln1g, P1.ln1b, NTOK0);
    // K|V = ln(o0) @ wqkv1[:,256:768] -> [65536,512] bf16
    run_hgemm(Hb, 256, P1.wqkvT + 256 * 256, QKVb, 512, bqkv + 768 + 256,
              nullptr, 0, NTOK0, 512, 256, 0, 1);
    smsa_gather_g_kernel<<<4096, 256>>>(X1, G);

    __nv_bfloat16* S0b = Tb;
    __nv_bfloat16* Sqb = Tb + (size_t)4096 * 256;
    __nv_bfloat16* AOb = Tb + (size_t)2 * 4096 * 256;
    __nv_bfloat16* Sgb = Tb + (size_t)3 * 4096 * 256;
    __nv_bfloat16* Thb = Tb + (size_t)4 * 4096 * 256;

    run_ln(G, S0b, P1.ln1g, P1.ln1b, NTOK1);
    run_hgemm(S0b, 256, P1.wqkvT, Sqb, 256, bqkv + 768, nullptr, 0,
              NTOK1, 256, 256, 0, 1);
    smsa_xattn_kernel<<<4096, 256>>>(Sqb, QKVb, AOb);
    run_hgemm(AOb, 256, P1.woT, G, 256, P1.bo, G, 256, NTOK1, 256, 256, 0, 0);
    run_ln(G, Sgb, P1.ln2g, P1.ln2b, NTOK1);
    run_hgemm(Sgb, 256, P1.w1T, Thb, 1024, P1.b1, nullptr, 0, NTOK1, 1024, 256, 1, 1);
    run_hgemm(Thb, 1024, P1.w2T, G, 256, P1.b2, G, 256, NTOK1, 256, 1024, 0, 0);

    // 5) scatter g back to o1 window layout
    smsa_scatter_g_kernel<<<4096, 256>>>(G, out1);
}

// round 5
// speedup vs baseline: 3.1457x; 1.0365x over previous
#include <cuda_runtime.h>
#include <cuda_bf16.h>
#include <math.h>
#include <stdint.h>

// ---------------------------------------------------------------------------
// StackMSA round 5: 128x256 HMMA GEMM tiles (warp tile 32x64, 3-stage
// cp.async, 144KB smem), fused single-launch weight transpose.
// B=4, H=W=8, M=16, C=256, NH=8, HD=32, GW=2
// out: [272, 256, 256] f32 = [o0 (256 win) ; o1 (16 win)]
// ---------------------------------------------------------------------------

#define NTOK0 65536
#define NTOK1 4096
#define ATTN_SMEM (2 * 256 * 36 * 4)
#define GEMM_SMEM 147456   // 3 stages x (16KB A + 32KB B)

// fp32 residual streams + scratch
__device__ float g_X0[65536 * 256];
__device__ float g_X1[4096 * 256];
__device__ float g_PE[2 * 256 * 256];
__device__ float g_G[4096 * 256];
// bf16 activation streams
__device__ __nv_bfloat16 g_Hb[65536 * 256];
__device__ __nv_bfloat16 g_QKVb[65536 * 768];
__device__ __nv_bfloat16 g_Tb[65536 * 1024];
__device__ __nv_bfloat16 g_WT[1572864];   // transposed weights [N,K] bf16

__device__ __forceinline__ float gelu_exact(float x) {
    return 0.5f * x * (1.0f + erff(x * 0.70710678118654752f));
}

__device__ __forceinline__ uint32_t smem_u32(const void* p) {
    uint32_t a;
    asm("{ .reg .u64 t; cvta.to.shared.u64 t, %1; cvt.u32.u64 %0, t; }"
        : "=r"(a) : "l"(p));
    return a;
}

#define SWZ128(o) ((o) ^ (((o) >> 3) & 0x70))
#define CP16(dst, src) \
    asm volatile("cp.async.cg.shared.global [%0], [%1], 16;" :: "r"(dst), "l"(src))
#define CPCOMMIT() asm volatile("cp.async.commit_group;" ::: "memory")
#define CPWAIT1() asm volatile("cp.async.wait_group 1;" ::: "memory")

// packed f32x2
__device__ __forceinline__ unsigned long long pk2(float x, float y) {
    unsigned long long r;
    asm("mov.b64 %0, {%1, %2};" : "=l"(r) : "f"(x), "f"(y));
    return r;
}
__device__ __forceinline__ void upk2(float& x, float& y, unsigned long long v) {
    asm("mov.b64 {%0, %1}, %2;" : "=f"(x), "=f"(y) : "l"(v));
}
__device__ __forceinline__ unsigned long long fma2(unsigned long long a,
                                                   unsigned long long b,
                                                   unsigned long long c) {
    unsigned long long d;
    asm("fma.rn.f32x2 %0, %1, %2, %3;" : "=l"(d) : "l"(a), "l"(b), "l"(c));
    return d;
}
__device__ __forceinline__ unsigned long long mul2(unsigned long long a,
                                                   unsigned long long b) {
    unsigned long long d;
    asm("mul.rn.f32x2 %0, %1, %2;" : "=l"(d) : "l"(a), "l"(b));
    return d;
}

__device__ __forceinline__ void cvt8(uint4 u, float* o) {
    const __nv_bfloat162* p = (const __nv_bfloat162*)&u;
#pragma unroll
    for (int i = 0; i < 4; i++) {
        float2 f = __bfloat1622float2(p[i]);
        o[2 * i] = f.x;
        o[2 * i + 1] = f.y;
    }
}
__device__ __forceinline__ uint32_t bf2u(float x, float y) {
    __nv_bfloat162 h = __float22bfloat162_rn(make_float2(x, y));
    return *(uint32_t*)&h;
}

// ---------------------------------------------------------------------------
// Position embedding table + add (fp32)
// ---------------------------------------------------------------------------
__global__ void smsa_posemb_kernel(const float* __restrict__ w1,
                                   const float* __restrict__ b1,
                                   const float* __restrict__ w2,
                                   float* __restrict__ pe) {
    int t = blockIdx.x, s = blockIdx.y, tid = threadIdx.x;
    __shared__ float hid[512];
    float c0 = (float)((t >> 4) - 8) * 0.125f;
    float c1 = (float)((t & 15) - 8) * 0.125f;
    const float* W1 = w1 + s * 1024;
    const float* B1 = b1 + s * 512;
    for (int k = tid; k < 512; k += 256)
        hid[k] = fmaxf(fmaf(c0, W1[k], fmaf(c1, W1[512 + k], B1[k])), 0.0f);
    __syncthreads();
    const float* W2 = w2 + s * 512 * 256;
    float acc = 0.0f;
#pragma unroll 8
    for (int k = 0; k < 512; k++) acc = fmaf(hid[k], W2[k * 256 + tid], acc);
    pe[s * 65536 + t * 256 + tid] = acc;
}

__global__ void smsa_add_pe_kernel(const float* __restrict__ x,
                                   const float* __restrict__ pe,
                                   float* __restrict__ y) {
    size_t i = (size_t)blockIdx.x * 256 + threadIdx.x;
    float4 a = ((const float4*)x)[i];
    float4 p = ((const float4*)pe)[i & 16383];
    float4 r;
    r.x = a.x + p.x; r.y = a.y + p.y; r.z = a.z + p.z; r.w = a.w + p.w;
    ((float4*)y)[i] = r;
}

__global__ void smsa_pool_kernel(const float* __restrict__ x0,
                                 float* __restrict__ x1) {
    int gid = blockIdx.x, c = threadIdx.x;
    int b = gid >> 10, gr = (gid >> 5) & 31, gc = gid & 31;
    int h = gr >> 2, r1 = gr & 3, w = gc >> 2, r2 = gc & 3;
    int fw = (b * 8 + h) * 8 + w;
    const float* base = x0 + ((size_t)fw * 256 + r1 * 64 + r2 * 4) * 256 + c;
    float m = -1e30f;
#pragma unroll
    for (int p1 = 0; p1 < 4; p1++)
#pragma unroll
        for (int p2 = 0; p2 < 4; p2++)
            m = fmaxf(m, base[(p1 * 16 + p2) * 256]);
    int gwin = b * 4 + (gr >> 4) * 2 + (gc >> 4);
    int tt = (gr & 15) * 16 + (gc & 15);
    x1[((size_t)gwin * 256 + tt) * 256 + c] += m;
}

// ---------------------------------------------------------------------------
// LayerNorm over C=256 (fp32 in, bf16 out), one warp per token
// ---------------------------------------------------------------------------
__global__ __launch_bounds__(256) void smsa_ln_kernel(
    const float* __restrict__ x, __nv_bfloat16* __restrict__ y,
    const float* __restrict__ gg, const float* __restrict__ bb) {
    int tok = blockIdx.x * 8 + (threadIdx.x >> 5);
    int lane = threadIdx.x & 31;
    const float4* row = (const float4*)(x + (size_t)tok * 256);
    float4 v0 = row[lane], v1 = row[lane + 32];
    float s = v0.x + v0.y + v0.z + v0.w + v1.x + v1.y + v1.z + v1.w;
    float ss = v0.x * v0.x + v0.y * v0.y + v0.z * v0.z + v0.w * v0.w +
               v1.x * v1.x + v1.y * v1.y + v1.z * v1.z + v1.w * v1.w;
#pragma unroll
    for (int o = 16; o > 0; o >>= 1) {
        s += __shfl_xor_sync(0xffffffffu, s, o);
        ss += __shfl_xor_sync(0xffffffffu, ss, o);
    }
    float mean = s * 0.00390625f;
    float var = ss * 0.00390625f - mean * mean;
    float rstd = rsqrtf(var + 1e-5f);
    float4 g0 = ((const float4*)gg)[lane], g1 = ((const float4*)gg)[lane + 32];
    float4 b0 = ((const float4*)bb)[lane], b1 = ((const float4*)bb)[lane + 32];
    uint2 o0, o1;
    o0.x = bf2u((v0.x - mean) * rstd * g0.x + b0.x, (v0.y - mean) * rstd * g0.y + b0.y);
    o0.y = bf2u((v0.z - mean) * rstd * g0.z + b0.z, (v0.w - mean) * rstd * g0.w + b0.w);
    o1.x = bf2u((v1.x - mean) * rstd * g1.x + b1.x, (v1.y - mean) * rstd * g1.y + b1.y);
    o1.y = bf2u((v1.z - mean) * rstd * g1.z + b1.z, (v1.w - mean) * rstd * g1.w + b1.w);
    uint2* yr = (uint2*)(y + (size_t)tok * 256);
    yr[lane] = o0;
    yr[lane + 32] = o1;
}

// ---------------------------------------------------------------------------
// Fused weight transpose: 8 jobs, one launch.
// W[K,N] fp32 -> Wt[N,K] bf16, 32x32 tiles, 32x8 threads.
// ---------------------------------------------------------------------------
struct TrJobs {
    const float* W[8];
    __nv_bfloat16* Wt[8];
    int K[8], N[8], blk0[8];
};

__global__ void smsa_transpose_all_kernel(TrJobs J) {
    __shared__ float t[32][33];
    int bid = blockIdx.x;
    int j = 0;
#pragma unroll
    for (int i = 1; i < 8; i++)
        if (bid >= J.blk0[i]) j = i;
    int rel = bid - J.blk0[j];
    int K = J.K[j], N = J.N[j];
    int nbx = N >> 5;
    int n0 = (rel % nbx) * 32, k0 = (rel / nbx) * 32;
    const float* W = J.W[j];
    __nv_bfloat16* Wt = J.Wt[j];
    int tx = threadIdx.x, ty = threadIdx.y;
#pragma unroll
    for (int i = 0; i < 32; i += 8)
        t[ty + i][tx] = W[(size_t)(k0 + ty + i) * N + n0 + tx];
    __syncthreads();
#pragma unroll
    for (int i = 0; i < 32; i += 8)
        Wt[(size_t)(n0 + ty + i) * K + k0 + tx] = __float2bfloat16(t[tx][ty + i]);
}

// ---------------------------------------------------------------------------
// bf16 HMMA GEMM, CTA tile 128x256, warp tile 32x64, 3-stage cp.async.
// C[M,N] = A[M,K] @ Bt[N,K]^T (+bias) (+res fp32) (gelu opt), out fp32/bf16.
// 512 threads (warp grid 4m x 4n). Stage: A 16KB @0, B 32KB @16384. SW128.
// ---------------------------------------------------------------------------
__global__ __launch_bounds__(512, 1) void smsa_hgemm_kernel(
    const __nv_bfloat16* __restrict__ A, int lda,
    const __nv_bfloat16* __restrict__ Bt,
    void* __restrict__ Cm, int ldc,
    const float* __restrict__ bias,
    const float* __restrict__ res, int ldr,
    int K, int act, int outbf) {
    extern __shared__ __align__(1024) char sm[];
    uint32_t sb = smem_u32(sm);
    const int tid = threadIdx.x;
    const int mb = blockIdx.y, nb = blockIdx.x;
    const int warp = tid >> 5, lane = tid & 31;
    const int wm = warp & 3, wn = warp >> 2;

    const __nv_bfloat16* Ag = A + (size_t)(mb * 128) * lda;
    const __nv_bfloat16* Bg = Bt + (size_t)(nb * 256) * K;

    const int nch = K >> 6;
    auto copy_stage = [&](int c, int s) {
        uint32_t sbase = sb + (uint32_t)s * 49152u;
        const __nv_bfloat16* ga = Ag + c * 64;
        const __nv_bfloat16* gb = Bg + c * 64;
        // A: 1024 16B units, 2/thread
#pragma unroll
        for (int p = 0; p < 2; p++) {
            int u = p * 512 + tid;
            int row = u >> 3, c16 = u & 7;
            CP16(sbase + SWZ128((uint32_t)row * 128 + c16 * 16),
                 ga + (size_t)row * lda + c16 * 8);
        }
        // B: 2048 units, 4/thread
#pragma unroll
        for (int p = 0; p < 4; p++) {
            int u = p * 512 + tid;
            int row = u >> 3, c16 = u & 7;
            CP16(sbase + 16384u + SWZ128((uint32_t)row * 128 + c16 * 16),
                 gb + (size_t)row * K + c16 * 8);
        }
    };

    float acc[2][8][4];
#pragma unroll
    for (int mt = 0; mt < 2; mt++)
#pragma unroll
        for (int nt = 0; nt < 8; nt++)
#pragma unroll
            for (int q = 0; q < 4; q++) acc[mt][nt][q] = 0.0f;

    const int a_row = wm * 32 + (lane & 15);
    const int b_row = wn * 64 + (lane & 15);
    const int hi = lane >> 4;

    copy_stage(0, 0);
    CPCOMMIT();
    if (nch > 1) copy_stage(1, 1);
    CPCOMMIT();

    for (int c = 0; c < nch; c++) {
        CPWAIT1();
        __syncthreads();
        if (c + 2 < nch) copy_stage(c + 2, (c + 2) % 3);
        CPCOMMIT();

        uint32_t abase = sb + (uint32_t)(c % 3) * 49152u;
        uint32_t bbase = abase + 16384u;
#pragma unroll
        for (int j = 0; j < 4; j++) {
            uint32_t af[2][4], bf[4][4];
            int ch = 2 * j + hi;
#pragma unroll
            for (int mt = 0; mt < 2; mt++) {
                uint32_t ad = abase + SWZ128((uint32_t)(a_row + mt * 16) * 128 + ch * 16);
                asm volatile(
                    "ldmatrix.sync.aligned.m8n8.x4.shared.b16 {%0,%1,%2,%3}, [%4];"
                    : "=r"(af[mt][0]), "=r"(af[mt][1]),
                      "=r"(af[mt][2]), "=r"(af[mt][3]) : "r"(ad));
            }
#pragma unroll
            for (int bt = 0; bt < 4; bt++) {
                uint32_t bd = bbase + SWZ128((uint32_t)(b_row + bt * 16) * 128 + ch * 16);
                asm volatile(
                    "ldmatrix.sync.aligned.m8n8.x4.shared.b16 {%0,%1,%2,%3}, [%4];"
                    : "=r"(bf[bt][0]), "=r"(bf[bt][1]),
                      "=r"(bf[bt][2]), "=r"(bf[bt][3]) : "r"(bd));
            }
#pragma unroll
            for (int mt = 0; mt < 2; mt++)
#pragma unroll
                for (int nt = 0; nt < 8; nt++) {
                    uint32_t b0 = bf[nt >> 1][nt & 1];
                    uint32_t b1 = bf[nt >> 1][(nt & 1) + 2];
                    asm volatile(
                        "mma.sync.aligned.m16n8k16.row.col.f32.bf16.bf16.f32 "
                        "{%0,%1,%2,%3}, {%4,%5,%6,%7}, {%8,%9}, {%0,%1,%2,%3};"
                        : "+f"(acc[mt][nt][0]), "+f"(acc[mt][nt][1]),
                          "+f"(acc[mt][nt][2]), "+f"(acc[mt][nt][3])
                        : "r"(af[mt][0]), "r"(af[mt][1]),
                          "r"(af[mt][2]), "r"(af[mt][3]),
                          "r"(b0), "r"(b1));
                }
        }
        __syncthreads();
    }

    // epilogue
    int qrow = lane >> 2, qcol = (lane & 3) * 2;
#pragma unroll
    for (int mt = 0; mt < 2; mt++)
#pragma unroll
        for (int half = 0; half < 2; half++) {
            int row = mb * 128 + wm * 32 + mt * 16 + qrow + half * 8;
#pragma unroll
            for (int nt = 0; nt < 8; nt++) {
                int col = nb * 256 + wn * 64 + nt * 8 + qcol;
                float v0 = acc[mt][nt][half * 2 + 0];
                float v1 = acc[mt][nt][half * 2 + 1];
                if (bias) {
                    float2 bv = *(const float2*)(bias + col);
                    v0 += bv.x; v1 += bv.y;
                }
                if (res) {
                    float2 rr = *(const float2*)(res + (size_t)row * ldr + col);
                    v0 += rr.x; v1 += rr.y;
                }
                if (act) { v0 = gelu_exact(v0); v1 = gelu_exact(v1); }
                if (outbf) {
                    *(uint32_t*)((__nv_bfloat16*)Cm + (size_t)row * ldc + col) =
                        bf2u(v0, v1);
                } else {
                    *(float2*)((float*)Cm + (size_t)row * ldc + col) =
                        make_float2(v0, v1);
                }
            }
        }
}

// ---------------------------------------------------------------------------
// Windowed attention, bf16 qkv in, bf16 out, packed f32x2 FMA in fp32.
// ---------------------------------------------------------------------------
__global__ __launch_bounds__(256) void smsa_attn_kernel(
    const __nv_bfloat16* __restrict__ qkv, __nv_bfloat16* __restrict__ out) {
    extern __shared__ float smf[];
    float* Ks = smf;
    float* Vs = smf + 256 * 36;
    int win = blockIdx.x >> 3;
    int h = blockIdx.x & 7;
    int t = threadIdx.x;
    const __nv_bfloat16* base = qkv + (size_t)win * 256 * 768;

    float q[32];
    {
        const uint4* qp = (const uint4*)(base + (size_t)t * 768 + h * 32);
#pragma unroll
        for (int i = 0; i < 4; i++) cvt8(qp[i], q + 8 * i);
    }
    unsigned long long q2[16];
#pragma unroll
    for (int i = 0; i < 16; i++) q2[i] = pk2(q[2 * i], q[2 * i + 1]);
    {
        const uint4* kp = (const uint4*)(base + (size_t)t * 768 + 256 + h * 32);
        const uint4* vp = (const uint4*)(base + (size_t)t * 768 + 512 + h * 32);
        float kv[8];
#pragma unroll
        for (int i = 0; i < 4; i++) {
            cvt8(kp[i], kv);
            *(float4*)&Ks[t * 36 + i * 8] = make_float4(kv[0], kv[1], kv[2], kv[3]);
            *(float4*)&Ks[t * 36 + i * 8 + 4] = make_float4(kv[4], kv[5], kv[6], kv[7]);
            cvt8(vp[i], kv);
            *(float4*)&Vs[t * 36 + i * 8] = make_float4(kv[0], kv[1], kv[2], kv[3]);
            *(float4*)&Vs[t * 36 + i * 8 + 4] = make_float4(kv[4], kv[5], kv[6], kv[7]);
        }
    }
    __syncthreads();

    unsigned long long acc2[16];
#pragma unroll
    for (int d = 0; d < 16; d++) acc2[d] = 0ull;
    float mmax = -1e30f, l = 0.0f;
    const float sc = 0.17677669529663687f;

    for (int j = 0; j < 256; j++) {
        const unsigned long long* kj = (const unsigned long long*)&Ks[j * 36];
        unsigned long long s2 = 0ull;
#pragma unroll
        for (int i = 0; i < 16; i++) s2 = fma2(q2[i], kj[i], s2);
        float slo, shi;
        upk2(slo, shi, s2);
        float s = (slo + shi) * sc;
        if (s > mmax) {
            float corr = __expf(mmax - s);
            unsigned long long c2 = pk2(corr, corr);
            l *= corr;
#pragma unroll
            for (int d = 0; d < 16; d++) acc2[d] = mul2(acc2[d], c2);
            mmax = s;
        }
        float p = __expf(s - mmax);
        l += p;
        unsigned long long pp = pk2(p, p);
        const unsigned long long* vj = (const unsigned long long*)&Vs[j * 36];
#pragma unroll
        for (int i = 0; i < 16; i++) acc2[i] = fma2(pp, vj[i], acc2[i]);
    }
    float inv = 1.0f / l;
    uint32_t ov[16];
#pragma unroll
    for (int i = 0; i < 16; i++) {
        float x, y;
        upk2(x, y, acc2[i]);
        ov[i] = bf2u(x * inv, y * inv);
    }
    uint4* op = (uint4*)(out + ((size_t)(win * 256 + t)) * 256 + h * 32);
#pragma unroll
    for (int i = 0; i < 4; i++) op[i] = ((uint4*)ov)[i];
}

// ---------------------------------------------------------------------------
// Cross-attention gather/scatter and 1->16 attention
// ---------------------------------------------------------------------------
__device__ __forceinline__ void decode_f(int f, int& fw, int& base_t,
                                         int& gwin, int& tt) {
    int b = f >> 10, h = (f >> 7) & 7, w = (f >> 4) & 7;
    int r1 = (f >> 2) & 3, r2 = f & 3;
    fw = (b * 8 + h) * 8 + w;
    base_t = r1 * 64 + r2 * 4;
    int gr = h * 4 + r1, gc = w * 4 + r2;
    gwin = b * 4 + (gr >> 4) * 2 + (gc >> 4);
    tt = (gr & 15) * 16 + (gc & 15);
}

__global__ void smsa_gather_g_kernel(const float* __restrict__ x1,
                                     float* __restrict__ g) {
    int f = blockIdx.x, c = threadIdx.x;
    int fw, base_t, gwin, tt;
    decode_f(f, fw, base_t, gwin, tt);
    g[(size_t)f * 256 + c] = x1[((size_t)gwin * 256 + tt) * 256 + c];
}

__global__ void smsa_scatter_g_kernel(const float* __restrict__ g,
                                      float* __restrict__ out1) {
    int f = blockIdx.x, c = threadIdx.x;
    int fw, base_t, gwin, tt;
    decode_f(f, fw, base_t, gwin, tt);
    out1[((size_t)gwin * 256 + tt) * 256 + c] = g[(size_t)f * 256 + c];
}

__global__ __launch_bounds__(256) void smsa_xattn_kernel(
    const __nv_bfloat16* __restrict__ Q, const __nv_bfloat16* __restrict__ KV,
    __nv_bfloat16* __restrict__ AO) {
    int f = blockIdx.x;
    int h = threadIdx.x >> 5;
    int d = threadIdx.x & 31;
    int fw, base_t, gwin, tt;
    decode_f(f, fw, base_t, gwin, tt);
    float qd = __bfloat162float(Q[(size_t)f * 256 + h * 32 + d]);
    const float sc = 0.17677669529663687f;
    float s[16];
#pragma unroll
    for (int j = 0; j < 16; j++) {
        int t = base_t + (j >> 2) * 16 + (j & 3);
        float kd = __bfloat162float(KV[((size_t)(fw * 256 + t)) * 512 + h * 32 + d]);
        float pr = qd * kd;
#pragma unroll
        for (int o = 16; o > 0; o >>= 1)
            pr += __shfl_xor_sync(0xffffffffu, pr, o);
        s[j] = pr * sc;
    }
    float m = s[0];
#pragma unroll
    for (int j = 1; j < 16; j++) m = fmaxf(m, s[j]);
    float l = 0.0f, p[16];
#pragma unroll
    for (int j = 0; j < 16; j++) {
        p[j] = __expf(s[j] - m);
        l += p[j];
    }
    float inv = 1.0f / l;
    float acc = 0.0f;
#pragma unroll
    for (int j = 0; j < 16; j++) {
        int t = base_t + (j >> 2) * 16 + (j & 3);
        acc = fmaf(p[j], __bfloat162float(
                        KV[((size_t)(fw * 256 + t)) * 512 + 256 + h * 32 + d]),
                   acc);
    }
    AO[(size_t)f * 256 + h * 32 + d] = __float2bfloat16(acc * inv);
}

// ---------------------------------------------------------------------------
// Host side
// ---------------------------------------------------------------------------
static void run_hgemm(const __nv_bfloat16* A, int lda, const __nv_bfloat16* Bt,
                      void* Cm, int ldc, const float* bias,
                      const float* res, int ldr, int M, int N, int K,
                      int act, int outbf) {
    dim3 grid(N / 256, M / 128);
    smsa_hgemm_kernel<<<grid, 512, GEMM_SMEM>>>(A, lda, Bt, Cm, ldc, bias,
                                                res, ldr, K, act, outbf);
}

static void run_ln(const float* x, __nv_bfloat16* y, const float* g,
                   const float* b, int ntok) {
    smsa_ln_kernel<<<ntok / 8, 256>>>(x, y, g, b);
}

struct BlockParams {
    const float *ln1g, *ln1b;
    const __nv_bfloat16* wqkvT;
    const float* bqkv;
    const __nv_bfloat16* woT;
    const float *bo, *ln2g, *ln2b;
    const __nv_bfloat16* w1T;
    const float* b1;
    const __nv_bfloat16* w2T;
    const float* b2;
};

static void run_sattn_block(float* X, float* outC, int ntok, const BlockParams& P,
                            __nv_bfloat16* Hb, __nv_bfloat16* QKVb,
                            __nv_bfloat16* Tb) {
    run_ln(X, Hb, P.ln1g, P.ln1b, ntok);
    run_hgemm(Hb, 256, P.wqkvT, QKVb, 768, P.bqkv, nullptr, 0, ntok, 768, 256, 0, 1);
    smsa_attn_kernel<<<(ntok / 256) * 8, 256, ATTN_SMEM>>>(QKVb, Hb);
    run_hgemm(Hb, 256, P.woT, X, 256, P.bo, X, 256, ntok, 256, 256, 0, 0);
    run_ln(X, Hb, P.ln2g, P.ln2b, ntok);
    run_hgemm(Hb, 256, P.w1T, Tb, 1024, P.b1, nullptr, 0, ntok, 1024, 256, 1, 1);
    run_hgemm(Tb, 1024, P.w2T, outC, 256, P.b2, X, 256, ntok, 256, 1024, 0, 0);
}

extern "C" void kernel_launch(void* const* d_in, const int* in_sizes, int n_in,
                              void* d_out, int out_size) {
    const float* scale0 = (const float*)d_in[0];
    const float* scale1 = (const float*)d_in[1];
    const float* pe_w1 = (const float*)d_in[2];
    const float* pe_b1 = (const float*)d_in[3];
    const float* pe_w2 = (const float*)d_in[4];
    const float* ln1_g = (const float*)d_in[5];
    const float* ln1_b = (const float*)d_in[6];
    const float* wqkv = (const float*)d_in[7];
    const float* bqkv = (const float*)d_in[8];
    const float* wo = (const float*)d_in[9];
    const float* bo = (const float*)d_in[10];
    const float* ln2_g = (const float*)d_in[11];
    const float* ln2_b = (const float*)d_in[12];
    const float* mw1 = (const float*)d_in[13];
    const float* mb1 = (const float*)d_in[14];
    const float* mw2 = (const float*)d_in[15];
    const float* mb2 = (const float*)d_in[16];
    float* out = (float*)d_out;
    float* out0 = out;
    float* out1 = out + (size_t)65536 * 256;

    float *X0, *X1, *PE, *G;
    __nv_bfloat16 *Hb, *QKVb, *Tb, *WT;
    cudaGetSymbolAddress((void**)&X0, g_X0);
    cudaGetSymbolAddress((void**)&X1, g_X1);
    cudaGetSymbolAddress((void**)&PE, g_PE);
    cudaGetSymbolAddress((void**)&G, g_G);
    cudaGetSymbolAddress((void**)&Hb, g_Hb);
    cudaGetSymbolAddress((void**)&QKVb, g_QKVb);
    cudaGetSymbolAddress((void**)&Tb, g_Tb);
    cudaGetSymbolAddress((void**)&WT, g_WT);

    cudaFuncSetAttribute(smsa_attn_kernel,
                         cudaFuncAttributeMaxDynamicSharedMemorySize, ATTN_SMEM);
    cudaFuncSetAttribute(smsa_hgemm_kernel,
                         cudaFuncAttributeMaxDynamicSharedMemorySize, GEMM_SMEM);

    // 0) weight transposes, one launch ([K,N] fp32 -> [N,K] bf16)
    {
        TrJobs J;
        const float* Ws[8] = {wqkv, wqkv + 196608, wo, wo + 65536,
                              mw1, mw1 + 262144, mw2, mw2 + 262144};
        __nv_bfloat16* Wts[8] = {WT + 0, WT + 786432, WT + 196608, WT + 983040,
                                 WT + 262144, WT + 1048576, WT + 524288, WT + 1310720};
        int Ks[8] = {256, 256, 256, 256, 256, 256, 1024, 1024};
        int Ns[8] = {768, 768, 256, 256, 1024, 1024, 256, 256};
        int b0 = 0;
        for (int i = 0; i < 8; i++) {
            J.W[i] = Ws[i]; J.Wt[i] = Wts[i]; J.K[i] = Ks[i]; J.N[i] = Ns[i];
            J.blk0[i] = b0;
            b0 += (Ks[i] / 32) * (Ns[i] / 32);
        }
        smsa_transpose_all_kernel<<<b0, dim3(32, 8)>>>(J);
    }

    // 1) position embedding tables + add
    smsa_posemb_kernel<<<dim3(256, 2), 256>>>(pe_w1, pe_b1, pe_w2, PE);
    smsa_add_pe_kernel<<<16384, 256>>>(scale0, PE, X0);
    smsa_add_pe_kernel<<<1024, 256>>>(scale1, PE + 65536, X1);

    // 2) bottom-up max-pool into global tokens
    smsa_pool_kernel<<<4096, 256>>>(X0, X1);

    // 3) sattn blocks
    BlockParams P1 = {ln1_g + 256, ln1_b + 256, WT + 786432, bqkv + 768,
                      WT + 983040, bo + 256, ln2_g + 256, ln2_b + 256,
                      WT + 1048576, mb1 + 1024, WT + 1310720, mb2 + 256};
    BlockParams P0 = {ln1_g, ln1_b, WT + 0, bqkv, WT + 196608, bo,
                      ln2_g, ln2_b, WT + 262144, mb1, WT + 524288, mb2};
    run_sattn_block(X1, X1, NTOK1, P1, Hb, QKVb, Tb);
    run_sattn_block(X0, out0, NTOK0, P0, Hb, QKVb, Tb);

    // 4) one2one cross-attention (params scale 1)
    run_ln(out0, Hb, P1.ln1g, P1.ln1b, NTOK0);
    run_hgemm(Hb, 256, P1.wqkvT + 256 * 256, QKVb, 512, bqkv + 768 + 256,
              nullptr, 0, NTOK0, 512, 256, 0, 1);
    smsa_gather_g_kernel<<<4096, 256>>>(X1, G);

    __nv_bfloat16* S0b = Tb;
    __nv_bfloat16* Sqb = Tb + (size_t)4096 * 256;
    __nv_bfloat16* AOb = Tb + (size_t)2 * 4096 * 256;
    __nv_bfloat16* Sgb = Tb + (size_t)3 * 4096 * 256;
    __nv_bfloat16* Thb = Tb + (size_t)4 * 4096 * 256;

    run_ln(G, S0b, P1.ln1g, P1.ln1b, NTOK1);
    run_hgemm(S0b, 256, P1.wqkvT, Sqb, 256, bqkv + 768, nullptr, 0,
              NTOK1, 256, 256, 0, 1);
    smsa_xattn_kernel<<<4096, 256>>>(Sqb, QKVb, AOb);
    run_hgemm(AOb, 256, P1.woT, G, 256, P1.bo, G, 256, NTOK1, 256, 256, 0, 0);
    run_ln(G, Sgb, P1.ln2g, P1.ln2b, NTOK1);
    run_hgemm(Sgb, 256, P1.w1T, Thb, 1024, P1.b1, nullptr, 0, NTOK1, 1024, 256, 1, 1);
    run_hgemm(Thb, 1024, P1.w2T, G, 256, P1.b2, G, 256, NTOK1, 256, 1024, 0, 0);

    // 5) scatter g back to o1 window layout
    smsa_scatter_g_kernel<<<4096, 256>>>(G, out1);
}

// round 7
// speedup vs baseline: 4.6451x; 1.4767x over previous
#include <cuda_runtime.h>
#include <cuda_bf16.h>
#include <math.h>
#include <stdint.h>

// ---------------------------------------------------------------------------
// StackMSA round 7: single stream (R5 schedule) + fused HMMA flash attention
// (tensor pipe) replacing the fma2 SIMT attention.
// B=4, H=W=8, M=16, C=256, NH=8, HD=32, GW=2
// out: [272, 256, 256] f32 = [o0 (256 win) ; o1 (16 win)]
// ---------------------------------------------------------------------------

#define NTOK0 65536
#define NTOK1 4096
#define ATTN_SMEM 61440     // Q/K/V: 3 x 256 rows x 80B
#define GEMM_SMEM 147456    // 3 stages x (16KB A + 32KB B)

// fp32 residual streams + scratch
__device__ float g_X0[65536 * 256];
__device__ float g_X1[4096 * 256];
__device__ float g_PE[2 * 256 * 256];
__device__ float g_G[4096 * 256];
// bf16 activation streams
__device__ __nv_bfloat16 g_Hb[65536 * 256];
__device__ __nv_bfloat16 g_QKVb[65536 * 768];
__device__ __nv_bfloat16 g_Tb[65536 * 1024];
__device__ __nv_bfloat16 g_WT[1572864];   // transposed weights [N,K] bf16

__device__ __forceinline__ float gelu_exact(float x) {
    return 0.5f * x * (1.0f + erff(x * 0.70710678118654752f));
}

__device__ __forceinline__ uint32_t smem_u32(const void* p) {
    uint32_t a;
    asm("{ .reg .u64 t; cvta.to.shared.u64 t, %1; cvt.u32.u64 %0, t; }"
        : "=r"(a) : "l"(p));
    return a;
}

#define SWZ128(o) ((o) ^ (((o) >> 3) & 0x70))
#define CP16(dst, src) \
    asm volatile("cp.async.cg.shared.global [%0], [%1], 16;" :: "r"(dst), "l"(src))
#define CPCOMMIT() asm volatile("cp.async.commit_group;" ::: "memory")
#define CPWAIT1() asm volatile("cp.async.wait_group 1;" ::: "memory")

#define LDSM_X4(r, addr) \
    asm volatile("ldmatrix.sync.aligned.m8n8.x4.shared.b16 {%0,%1,%2,%3}, [%4];" \
                 : "=r"((r)[0]), "=r"((r)[1]), "=r"((r)[2]), "=r"((r)[3]) : "r"(addr))
#define LDSM_X4T(r, addr) \
    asm volatile("ldmatrix.sync.aligned.m8n8.x4.trans.shared.b16 {%0,%1,%2,%3}, [%4];" \
                 : "=r"((r)[0]), "=r"((r)[1]), "=r"((r)[2]), "=r"((r)[3]) : "r"(addr))
#define MMA16816(d, a, b0, b1) \
    asm volatile("mma.sync.aligned.m16n8k16.row.col.f32.bf16.bf16.f32 " \
                 "{%0,%1,%2,%3}, {%4,%5,%6,%7}, {%8,%9}, {%0,%1,%2,%3};" \
                 : "+f"((d)[0]), "+f"((d)[1]), "+f"((d)[2]), "+f"((d)[3]) \
                 : "r"((a)[0]), "r"((a)[1]), "r"((a)[2]), "r"((a)[3]), \
                   "r"(b0), "r"(b1))

__device__ __forceinline__ uint32_t bf2u(float x, float y) {
    __nv_bfloat162 h = __float22bfloat162_rn(make_float2(x, y));
    return *(uint32_t*)&h;
}

// ---------------------------------------------------------------------------
// Position embedding table + add (fp32)
// ---------------------------------------------------------------------------
__global__ void smsa_posemb_kernel(const float* __restrict__ w1,
                                   const float* __restrict__ b1,
                                   const float* __restrict__ w2,
                                   float* __restrict__ pe) {
    int t = blockIdx.x, s = blockIdx.y, tid = threadIdx.x;
    __shared__ float hid[512];
    float c0 = (float)((t >> 4) - 8) * 0.125f;
    float c1 = (float)((t & 15) - 8) * 0.125f;
    const float* W1 = w1 + s * 1024;
    const float* B1 = b1 + s * 512;
    for (int k = tid; k < 512; k += 256)
        hid[k] = fmaxf(fmaf(c0, W1[k], fmaf(c1, W1[512 + k], B1[k])), 0.0f);
    __syncthreads();
    const float* W2 = w2 + s * 512 * 256;
    float acc = 0.0f;
#pragma unroll 8
    for (int k = 0; k < 512; k++) acc = fmaf(hid[k], W2[k * 256 + tid], acc);
    pe[s * 65536 + t * 256 + tid] = acc;
}

__global__ void smsa_add_pe_kernel(const float* __restrict__ x,
                                   const float* __restrict__ pe,
                                   float* __restrict__ y) {
    size_t i = (size_t)blockIdx.x * 256 + threadIdx.x;
    float4 a = ((const float4*)x)[i];
    float4 p = ((const float4*)pe)[i & 16383];
    float4 r;
    r.x = a.x + p.x; r.y = a.y + p.y; r.z = a.z + p.z; r.w = a.w + p.w;
    ((float4*)y)[i] = r;
}

__global__ void smsa_pool_kernel(const float* __restrict__ x0,
                                 float* __restrict__ x1) {
    int gid = blockIdx.x, c = threadIdx.x;
    int b = gid >> 10, gr = (gid >> 5) & 31, gc = gid & 31;
    int h = gr >> 2, r1 = gr & 3, w = gc >> 2, r2 = gc & 3;
    int fw = (b * 8 + h) * 8 + w;
    const float* base = x0 + ((size_t)fw * 256 + r1 * 64 + r2 * 4) * 256 + c;
    float m = -1e30f;
#pragma unroll
    for (int p1 = 0; p1 < 4; p1++)
#pragma unroll
        for (int p2 = 0; p2 < 4; p2++)
            m = fmaxf(m, base[(p1 * 16 + p2) * 256]);
    int gwin = b * 4 + (gr >> 4) * 2 + (gc >> 4);
    int tt = (gr & 15) * 16 + (gc & 15);
    x1[((size_t)gwin * 256 + tt) * 256 + c] += m;
}

// ---------------------------------------------------------------------------
// LayerNorm over C=256 (fp32 in, bf16 out), one warp per token
// ---------------------------------------------------------------------------
__global__ __launch_bounds__(256) void smsa_ln_kernel(
    const float* __restrict__ x, __nv_bfloat16* __restrict__ y,
    const float* __restrict__ gg, const float* __restrict__ bb) {
    int tok = blockIdx.x * 8 + (threadIdx.x >> 5);
    int lane = threadIdx.x & 31;
    const float4* row = (const float4*)(x + (size_t)tok * 256);
    float4 v0 = row[lane], v1 = row[lane + 32];
    float s = v0.x + v0.y + v0.z + v0.w + v1.x + v1.y + v1.z + v1.w;
    float ss = v0.x * v0.x + v0.y * v0.y + v0.z * v0.z + v0.w * v0.w +
               v1.x * v1.x + v1.y * v1.y + v1.z * v1.z + v1.w * v1.w;
#pragma unroll
    for (int o = 16; o > 0; o >>= 1) {
        s += __shfl_xor_sync(0xffffffffu, s, o);
        ss += __shfl_xor_sync(0xffffffffu, ss, o);
    }
    float mean = s * 0.00390625f;
    float var = ss * 0.00390625f - mean * mean;
    float rstd = rsqrtf(var + 1e-5f);
    float4 g0 = ((const float4*)gg)[lane], g1 = ((const float4*)gg)[lane + 32];
    float4 b0 = ((const float4*)bb)[lane], b1 = ((const float4*)bb)[lane + 32];
    uint2 o0, o1;
    o0.x = bf2u((v0.x - mean) * rstd * g0.x + b0.x, (v0.y - mean) * rstd * g0.y + b0.y);
    o0.y = bf2u((v0.z - mean) * rstd * g0.z + b0.z, (v0.w - mean) * rstd * g0.w + b0.w);
    o1.x = bf2u((v1.x - mean) * rstd * g1.x + b1.x, (v1.y - mean) * rstd * g1.y + b1.y);
    o1.y = bf2u((v1.z - mean) * rstd * g1.z + b1.z, (v1.w - mean) * rstd * g1.w + b1.w);
    uint2* yr = (uint2*)(y + (size_t)tok * 256);
    yr[lane] = o0;
    yr[lane + 32] = o1;
}

// ---------------------------------------------------------------------------
// Fused weight transpose: 8 jobs, one launch. W[K,N] fp32 -> Wt[N,K] bf16.
// ---------------------------------------------------------------------------
struct TrJobs {
    const float* W[8];
    __nv_bfloat16* Wt[8];
    int K[8], N[8], blk0[8];
};

__global__ void smsa_transpose_all_kernel(TrJobs J) {
    __shared__ float t[32][33];
    int bid = blockIdx.x;
    int j = 0;
#pragma unroll
    for (int i = 1; i < 8; i++)
        if (bid >= J.blk0[i]) j = i;
    int rel = bid - J.blk0[j];
    int K = J.K[j], N = J.N[j];
    int nbx = N >> 5;
    int n0 = (rel % nbx) * 32, k0 = (rel / nbx) * 32;
    const float* W = J.W[j];
    __nv_bfloat16* Wt = J.Wt[j];
    int tx = threadIdx.x, ty = threadIdx.y;
#pragma unroll
    for (int i = 0; i < 32; i += 8)
        t[ty + i][tx] = W[(size_t)(k0 + ty + i) * N + n0 + tx];
    __syncthreads();
#pragma unroll
    for (int i = 0; i < 32; i += 8)
        Wt[(size_t)(n0 + ty + i) * K + k0 + tx] = __float2bfloat16(t[tx][ty + i]);
}

// ---------------------------------------------------------------------------
// bf16 HMMA GEMM, CTA tile 128x256, warp tile 32x64, 3-stage cp.async.
// ---------------------------------------------------------------------------
__global__ __launch_bounds__(512, 1) void smsa_hgemm_kernel(
    const __nv_bfloat16* __restrict__ A, int lda,
    const __nv_bfloat16* __restrict__ Bt,
    void* __restrict__ Cm, int ldc,
    const float* __restrict__ bias,
    const float* __restrict__ res, int ldr,
    int K, int act, int outbf) {
    extern __shared__ __align__(1024) char sm[];
    uint32_t sb = smem_u32(sm);
    const int tid = threadIdx.x;
    const int mb = blockIdx.y, nb = blockIdx.x;
    const int warp = tid >> 5, lane = tid & 31;
    const int wm = warp & 3, wn = warp >> 2;

    const __nv_bfloat16* Ag = A + (size_t)(mb * 128) * lda;
    const __nv_bfloat16* Bg = Bt + (size_t)(nb * 256) * K;

    const int nch = K >> 6;
    auto copy_stage = [&](int c, int s) {
        uint32_t sbase = sb + (uint32_t)s * 49152u;
        const __nv_bfloat16* ga = Ag + c * 64;
        const __nv_bfloat16* gb = Bg + c * 64;
#pragma unroll
        for (int p = 0; p < 2; p++) {
            int u = p * 512 + tid;
            int row = u >> 3, c16 = u & 7;
            CP16(sbase + SWZ128((uint32_t)row * 128 + c16 * 16),
                 ga + (size_t)row * lda + c16 * 8);
        }
#pragma unroll
        for (int p = 0; p < 4; p++) {
            int u = p * 512 + tid;
            int row = u >> 3, c16 = u & 7;
            CP16(sbase + 16384u + SWZ128((uint32_t)row * 128 + c16 * 16),
                 gb + (size_t)row * K + c16 * 8);
        }
    };

    float acc[2][8][4];
#pragma unroll
    for (int mt = 0; mt < 2; mt++)
#pragma unroll
        for (int nt = 0; nt < 8; nt++)
#pragma unroll
            for (int q = 0; q < 4; q++) acc[mt][nt][q] = 0.0f;

    const int a_row = wm * 32 + (lane & 15);
    const int b_row = wn * 64 + (lane & 15);
    const int hi = lane >> 4;

    copy_stage(0, 0);
    CPCOMMIT();
    if (nch > 1) copy_stage(1, 1);
    CPCOMMIT();

    for (int c = 0; c < nch; c++) {
        CPWAIT1();
        __syncthreads();
        if (c + 2 < nch) copy_stage(c + 2, (c + 2) % 3);
        CPCOMMIT();

        uint32_t abase = sb + (uint32_t)(c % 3) * 49152u;
        uint32_t bbase = abase + 16384u;
#pragma unroll
        for (int j = 0; j < 4; j++) {
            uint32_t af[2][4], bf[4][4];
            int ch = 2 * j + hi;
#pragma unroll
            for (int mt = 0; mt < 2; mt++) {
                uint32_t ad = abase + SWZ128((uint32_t)(a_row + mt * 16) * 128 + ch * 16);
                LDSM_X4(af[mt], ad);
            }
#pragma unroll
            for (int bt = 0; bt < 4; bt++) {
                uint32_t bd = bbase + SWZ128((uint32_t)(b_row + bt * 16) * 128 + ch * 16);
                LDSM_X4(bf[bt], bd);
            }
#pragma unroll
            for (int mt = 0; mt < 2; mt++)
#pragma unroll
                for (int nt = 0; nt < 8; nt++)
                    MMA16816(acc[mt][nt], af[mt],
                             bf[nt >> 1][nt & 1], bf[nt >> 1][(nt & 1) + 2]);
        }
        __syncthreads();
    }

    int qrow = lane >> 2, qcol = (lane & 3) * 2;
#pragma unroll
    for (int mt = 0; mt < 2; mt++)
#pragma unroll
        for (int half = 0; half < 2; half++) {
            int row = mb * 128 + wm * 32 + mt * 16 + qrow + half * 8;
#pragma unroll
            for (int nt = 0; nt < 8; nt++) {
                int col = nb * 256 + wn * 64 + nt * 8 + qcol;
                float v0 = acc[mt][nt][half * 2 + 0];
                float v1 = acc[mt][nt][half * 2 + 1];
                if (bias) {
                    float2 bv = *(const float2*)(bias + col);
                    v0 += bv.x; v1 += bv.y;
                }
                if (res) {
                    float2 rr = *(const float2*)(res + (size_t)row * ldr + col);
                    v0 += rr.x; v1 += rr.y;
                }
                if (act) { v0 = gelu_exact(v0); v1 = gelu_exact(v1); }
                if (outbf) {
                    *(uint32_t*)((__nv_bfloat16*)Cm + (size_t)row * ldc + col) =
                        bf2u(v0, v1);
                } else {
                    *(float2*)((float*)Cm + (size_t)row * ldc + col) =
                        make_float2(v0, v1);
                }
            }
        }
}

// ---------------------------------------------------------------------------
// Fused HMMA flash attention: one block per (window, head), 8 warps, each warp
// owns 32 query rows. Q/K/V bf16 in smem (80B-padded rows, conflict-free
// ldmatrix). Online softmax over 4 key-blocks of 64. P in bf16, accum fp32.
// ---------------------------------------------------------------------------
__global__ __launch_bounds__(256) void smsa_fattn_kernel(
    const __nv_bfloat16* __restrict__ qkv, __nv_bfloat16* __restrict__ out) {
    extern __shared__ __align__(128) char smc[];
    uint32_t sbq = smem_u32(smc);
    const uint32_t Qs = sbq, Ks = sbq + 20480u, Vs = sbq + 40960u;
    int win = blockIdx.x >> 3, h = blockIdx.x & 7;
    int tid = threadIdx.x, lane = tid & 31, warp = tid >> 5;
    const __nv_bfloat16* base = qkv + (size_t)win * 256 * 768 + h * 32;

    // load q/k/v rows (token = tid) into padded smem
    {
        const uint4* qp = (const uint4*)(base + (size_t)tid * 768);
        const uint4* kp = (const uint4*)(base + (size_t)tid * 768 + 256);
        const uint4* vp = (const uint4*)(base + (size_t)tid * 768 + 512);
        uint32_t qd = Qs + tid * 80, kd = Ks + tid * 80, vd = Vs + tid * 80;
#pragma unroll
        for (int c = 0; c < 4; c++) {
            uint4 v;
            v = qp[c];
            asm volatile("st.shared.v4.b32 [%0], {%1,%2,%3,%4};"
                         :: "r"(qd + c * 16), "r"(v.x), "r"(v.y), "r"(v.z), "r"(v.w));
            v = kp[c];
            asm volatile("st.shared.v4.b32 [%0], {%1,%2,%3,%4};"
                         :: "r"(kd + c * 16), "r"(v.x), "r"(v.y), "r"(v.z), "r"(v.w));
            v = vp[c];
            asm volatile("st.shared.v4.b32 [%0], {%1,%2,%3,%4};"
                         :: "r"(vd + c * 16), "r"(v.x), "r"(v.y), "r"(v.z), "r"(v.w));
        }
    }
    __syncthreads();

    const int qb = warp * 32;
    uint32_t qf[2][2][4];
#pragma unroll
    for (int mt = 0; mt < 2; mt++)
#pragma unroll
        for (int kc = 0; kc < 2; kc++) {
            uint32_t ad = Qs + (uint32_t)(qb + mt * 16 + (lane & 15)) * 80
                          + (lane >> 4) * 16 + kc * 32;
            LDSM_X4(qf[mt][kc], ad);
        }

    float oacc[2][4][4];
#pragma unroll
    for (int mt = 0; mt < 2; mt++)
#pragma unroll
        for (int nt = 0; nt < 4; nt++)
#pragma unroll
            for (int q = 0; q < 4; q++) oacc[mt][nt][q] = 0.0f;
    float mrun[2][2] = {{-1e30f, -1e30f}, {-1e30f, -1e30f}};
    float lrun[2][2] = {{0.0f, 0.0f}, {0.0f, 0.0f}};
    const float C2 = 0.17677669529663687f * 1.4426950408889634f;  // sc*log2(e)

    for (int kb = 0; kb < 4; kb++) {
        float sacc[2][8][4];
#pragma unroll
        for (int mt = 0; mt < 2; mt++)
#pragma unroll
            for (int nt = 0; nt < 8; nt++)
#pragma unroll
                for (int q = 0; q < 4; q++) sacc[mt][nt][q] = 0.0f;

        // S = Q @ K^T over 64 keys
#pragma unroll
        for (int kc = 0; kc < 2; kc++) {
            uint32_t kf[4][4];
#pragma unroll
            for (int grp = 0; grp < 4; grp++) {
                uint32_t ad = Ks + (uint32_t)(kb * 64 + grp * 16 + (lane & 15)) * 80
                              + (lane >> 4) * 16 + kc * 32;
                LDSM_X4(kf[grp], ad);
            }
#pragma unroll
            for (int mt = 0; mt < 2; mt++)
#pragma unroll
                for (int nt = 0; nt < 8; nt++)
                    MMA16816(sacc[mt][nt], qf[mt][kc],
                             kf[nt >> 1][nt & 1], kf[nt >> 1][(nt & 1) + 2]);
        }

        // online softmax (rows: (mt, hf) -> g and g+8)
#pragma unroll
        for (int mt = 0; mt < 2; mt++)
#pragma unroll
            for (int hf = 0; hf < 2; hf++) {
                float mx = -1e30f;
#pragma unroll
                for (int nt = 0; nt < 8; nt++)
                    mx = fmaxf(mx, fmaxf(sacc[mt][nt][hf * 2], sacc[mt][nt][hf * 2 + 1]));
                mx = fmaxf(mx, __shfl_xor_sync(0xffffffffu, mx, 1));
                mx = fmaxf(mx, __shfl_xor_sync(0xffffffffu, mx, 2));
                float mold = mrun[mt][hf];
                float mnew = fmaxf(mold, mx);
                float corr = exp2f(C2 * (mold - mnew));
                mrun[mt][hf] = mnew;
                float sum = 0.0f;
#pragma unroll
                for (int nt = 0; nt < 8; nt++) {
                    float p0 = exp2f(C2 * (sacc[mt][nt][hf * 2] - mnew));
                    float p1 = exp2f(C2 * (sacc[mt][nt][hf * 2 + 1] - mnew));
                    sacc[mt][nt][hf * 2] = p0;
                    sacc[mt][nt][hf * 2 + 1] = p1;
                    sum += p0 + p1;
                }
                sum += __shfl_xor_sync(0xffffffffu, sum, 1);
                sum += __shfl_xor_sync(0xffffffffu, sum, 2);
                lrun[mt][hf] = lrun[mt][hf] * corr + sum;
#pragma unroll
                for (int nt = 0; nt < 4; nt++) {
                    oacc[mt][nt][hf * 2] *= corr;
                    oacc[mt][nt][hf * 2 + 1] *= corr;
                }
            }

        // O += P @ V
#pragma unroll
        for (int kc4 = 0; kc4 < 4; kc4++) {
            uint32_t vf[2][4];
#pragma unroll
            for (int dg = 0; dg < 2; dg++) {
                uint32_t ad = Vs + (uint32_t)(kb * 64 + kc4 * 16 + (lane & 15)) * 80
                              + dg * 32 + (lane >> 4) * 16;
                LDSM_X4T(vf[dg], ad);
            }
#pragma unroll
            for (int mt = 0; mt < 2; mt++) {
                uint32_t a[4];
                a[0] = bf2u(sacc[mt][2 * kc4][0], sacc[mt][2 * kc4][1]);
                a[1] = bf2u(sacc[mt][2 * kc4][2], sacc[mt][2 * kc4][3]);
                a[2] = bf2u(sacc[mt][2 * kc4 + 1][0], sacc[mt][2 * kc4 + 1][1]);
                a[3] = bf2u(sacc[mt][2 * kc4 + 1][2], sacc[mt][2 * kc4 + 1][3]);
#pragma unroll
                for (int nt = 0; nt < 4; nt++)
                    MMA16816(oacc[mt][nt], a,
                             vf[nt >> 1][(nt & 1) * 2], vf[nt >> 1][(nt & 1) * 2 + 1]);
            }
        }
    }

    // write out (bf16)
#pragma unroll
    for (int mt = 0; mt < 2; mt++) {
        float inv0 = 1.0f / lrun[mt][0];
        float inv1 = 1.0f / lrun[mt][1];
        int row0 = win * 256 + qb + mt * 16 + (lane >> 2);
        int col = h * 32 + (lane & 3) * 2;
#pragma unroll
        for (int nt = 0; nt < 4; nt++) {
            *(uint32_t*)(out + (size_t)row0 * 256 + col + nt * 8) =
                bf2u(oacc[mt][nt][0] * inv0, oacc[mt][nt][1] * inv0);
            *(uint32_t*)(out + (size_t)(row0 + 8) * 256 + col + nt * 8) =
                bf2u(oacc[mt][nt][2] * inv1, oacc[mt][nt][3] * inv1);
        }
    }
}

// ---------------------------------------------------------------------------
// Cross-attention gather/scatter and 1->16 attention
// ---------------------------------------------------------------------------
__device__ __forceinline__ void decode_f(int f, int& fw, int& base_t,
                                         int& gwin, int& tt) {
    int b = f >> 10, h = (f >> 7) & 7, w = (f >> 4) & 7;
    int r1 = (f >> 2) & 3, r2 = f & 3;
    fw = (b * 8 + h) * 8 + w;
    base_t = r1 * 64 + r2 * 4;
    int gr = h * 4 + r1, gc = w * 4 + r2;
    gwin = b * 4 + (gr >> 4) * 2 + (gc >> 4);
    tt = (gr & 15) * 16 + (gc & 15);
}

__global__ void smsa_gather_g_kernel(const float* __restrict__ x1,
                                     float* __restrict__ g) {
    int f = blockIdx.x, c = threadIdx.x;
    int fw, base_t, gwin, tt;
    decode_f(f, fw, base_t, gwin, tt);
    g[(size_t)f * 256 + c] = x1[((size_t)gwin * 256 + tt) * 256 + c];
}

__global__ void smsa_scatter_g_kernel(const float* __restrict__ g,
                                      float* __restrict__ out1) {
    int f = blockIdx.x, c = threadIdx.x;
    int fw, base_t, gwin, tt;
    decode_f(f, fw, base_t, gwin, tt);
    out1[((size_t)gwin * 256 + tt) * 256 + c] = g[(size_t)f * 256 + c];
}

__global__ __launch_bounds__(256) void smsa_xattn_kernel(
    const __nv_bfloat16* __restrict__ Q, const __nv_bfloat16* __restrict__ KV,
    __nv_bfloat16* __restrict__ AO) {
    int f = blockIdx.x;
    int h = threadIdx.x >> 5;
    int d = threadIdx.x & 31;
    int fw, base_t, gwin, tt;
    decode_f(f, fw, base_t, gwin, tt);
    float qd = __bfloat162float(Q[(size_t)f * 256 + h * 32 + d]);
    const float sc = 0.17677669529663687f;
    float s[16];
#pragma unroll
    for (int j = 0; j < 16; j++) {
        int t = base_t + (j >> 2) * 16 + (j & 3);
        float kd = __bfloat162float(KV[((size_t)(fw * 256 + t)) * 512 + h * 32 + d]);
        float pr = qd * kd;
#pragma unroll
        for (int o = 16; o > 0; o >>= 1)
            pr += __shfl_xor_sync(0xffffffffu, pr, o);
        s[j] = pr * sc;
    }
    float m = s[0];
#pragma unroll
    for (int j = 1; j < 16; j++) m = fmaxf(m, s[j]);
    float l = 0.0f, p[16];
#pragma unroll
    for (int j = 0; j < 16; j++) {
        p[j] = __expf(s[j] - m);
        l += p[j];
    }
    float inv = 1.0f / l;
    float acc = 0.0f;
#pragma unroll
    for (int j = 0; j < 16; j++) {
        int t = base_t + (j >> 2) * 16 + (j & 3);
        acc = fmaf(p[j], __bfloat162float(
                        KV[((size_t)(fw * 256 + t)) * 512 + 256 + h * 32 + d]),
                   acc);
    }
    AO[(size_t)f * 256 + h * 32 + d] = __float2bfloat16(acc * inv);
}

// ---------------------------------------------------------------------------
// Host side
// ---------------------------------------------------------------------------
static void run_hgemm(const __nv_bfloat16* A, int lda, const __nv_bfloat16* Bt,
                      void* Cm, int ldc, const float* bias,
                      const float* res, int ldr, int M, int N, int K,
                      int act, int outbf) {
    dim3 grid(N / 256, M / 128);
    smsa_hgemm_kernel<<<grid, 512, GEMM_SMEM>>>(A, lda, Bt, Cm, ldc, bias,
                                                res, ldr, K, act, outbf);
}

static void run_ln(const float* x, __nv_bfloat16* y, const float* g,
                   const float* b, int ntok) {
    smsa_ln_kernel<<<ntok / 8, 256>>>(x, y, g, b);
}

struct BlockParams {
    const float *ln1g, *ln1b;
    const __nv_bfloat16* wqkvT;
    const float* bqkv;
    const __nv_bfloat16* woT;
    const float *bo, *ln2g, *ln2b;
    const __nv_bfloat16* w1T;
    const float* b1;
    const __nv_bfloat16* w2T;
    const float* b2;
};

static void run_sattn_block(float* X, float* outC, int ntok, const BlockParams& P,
                            __nv_bfloat16* Hb, __nv_bfloat16* QKVb,
                            __nv_bfloat16* Tb) {
    run_ln(X, Hb, P.ln1g, P.ln1b, ntok);
    run_hgemm(Hb, 256, P.wqkvT, QKVb, 768, P.bqkv, nullptr, 0, ntok, 768, 256, 0, 1);
    smsa_fattn_kernel<<<(ntok / 256) * 8, 256, ATTN_SMEM>>>(QKVb, Hb);
    run_hgemm(Hb, 256, P.woT, X, 256, P.bo, X, 256, ntok, 256, 256, 0, 0);
    run_ln(X, Hb, P.ln2g, P.ln2b, ntok);
    run_hgemm(Hb, 256, P.w1T, Tb, 1024, P.b1, nullptr, 0, ntok, 1024, 256, 1, 1);
    run_hgemm(Tb, 1024, P.w2T, outC, 256, P.b2, X, 256, ntok, 256, 1024, 0, 0);
}

extern "C" void kernel_launch(void* const* d_in, const int* in_sizes, int n_in,
                              void* d_out, int out_size) {
    const float* scale0 = (const float*)d_in[0];
    const float* scale1 = (const float*)d_in[1];
    const float* pe_w1 = (const float*)d_in[2];
    const float* pe_b1 = (const float*)d_in[3];
    const float* pe_w2 = (const float*)d_in[4];
    const float* ln1_g = (const float*)d_in[5];
    const float* ln1_b = (const float*)d_in[6];
    const float* wqkv = (const float*)d_in[7];
    const float* bqkv = (const float*)d_in[8];
    const float* wo = (const float*)d_in[9];
    const float* bo = (const float*)d_in[10];
    const float* ln2_g = (const float*)d_in[11];
    const float* ln2_b = (const float*)d_in[12];
    const float* mw1 = (const float*)d_in[13];
    const float* mb1 = (const float*)d_in[14];
    const float* mw2 = (const float*)d_in[15];
    const float* mb2 = (const float*)d_in[16];
    float* out = (float*)d_out;
    float* out0 = out;
    float* out1 = out + (size_t)65536 * 256;

    float *X0, *X1, *PE, *G;
    __nv_bfloat16 *Hb, *QKVb, *Tb, *WT;
    cudaGetSymbolAddress((void**)&X0, g_X0);
    cudaGetSymbolAddress((void**)&X1, g_X1);
    cudaGetSymbolAddress((void**)&PE, g_PE);
    cudaGetSymbolAddress((void**)&G, g_G);
    cudaGetSymbolAddress((void**)&Hb, g_Hb);
    cudaGetSymbolAddress((void**)&QKVb, g_QKVb);
    cudaGetSymbolAddress((void**)&Tb, g_Tb);
    cudaGetSymbolAddress((void**)&WT, g_WT);

    cudaFuncSetAttribute(smsa_fattn_kernel,
                         cudaFuncAttributeMaxDynamicSharedMemorySize, ATTN_SMEM);
    cudaFuncSetAttribute(smsa_hgemm_kernel,
                         cudaFuncAttributeMaxDynamicSharedMemorySize, GEMM_SMEM);

    // 0) weight transposes, one launch ([K,N] fp32 -> [N,K] bf16)
    {
        TrJobs J;
        const float* Ws[8] = {wqkv, wqkv + 196608, wo, wo + 65536,
                              mw1, mw1 + 262144, mw2, mw2 + 262144};
        __nv_bfloat16* Wts[8] = {WT + 0, WT + 786432, WT + 196608, WT + 983040,
                                 WT + 262144, WT + 1048576, WT + 524288, WT + 1310720};
        int Ks[8] = {256, 256, 256, 256, 256, 256, 1024, 1024};
        int Ns[8] = {768, 768, 256, 256, 1024, 1024, 256, 256};
        int b0 = 0;
        for (int i = 0; i < 8; i++) {
            J.W[i] = Ws[i]; J.Wt[i] = Wts[i]; J.K[i] = Ks[i]; J.N[i] = Ns[i];
            J.blk0[i] = b0;
            b0 += (Ks[i] / 32) * (Ns[i] / 32);
        }
        smsa_transpose_all_kernel<<<b0, dim3(32, 8)>>>(J);
    }

    // 1) position embedding tables + add
    smsa_posemb_kernel<<<dim3(256, 2), 256>>>(pe_w1, pe_b1, pe_w2, PE);
    smsa_add_pe_kernel<<<16384, 256>>>(scale0, PE, X0);
    smsa_add_pe_kernel<<<1024, 256>>>(scale1, PE + 65536, X1);

    // 2) bottom-up max-pool into global tokens
    smsa_pool_kernel<<<4096, 256>>>(X0, X1);

    // 3) sattn blocks
    BlockParams P1 = {ln1_g + 256, ln1_b + 256, WT + 786432, bqkv + 768,
                      WT + 983040, bo + 256, ln2_g + 256, ln2_b + 256,
                      WT + 1048576, mb1 + 1024, WT + 1310720, mb2 + 256};
    BlockParams P0 = {ln1_g, ln1_b, WT + 0, bqkv, WT + 196608, bo,
                      ln2_g, ln2_b, WT + 262144, mb1, WT + 524288, mb2};
    run_sattn_block(X1, X1, NTOK1, P1, Hb, QKVb, Tb);
    run_sattn_block(X0, out0, NTOK0, P0, Hb, QKVb, Tb);

    // 4) one2one cross-attention (params scale 1)
    run_ln(out0, Hb, P1.ln1g, P1.ln1b, NTOK0);
    run_hgemm(Hb, 256, P1.wqkvT + 256 * 256, QKVb, 512, bqkv + 768 + 256,
              nullptr, 0, NTOK0, 512, 256, 0, 1);
    smsa_gather_g_kernel<<<4096, 256>>>(X1, G);

    __nv_bfloat16* S0b = Tb;
    __nv_bfloat16* Sqb = Tb + (size_t)4096 * 256;
    __nv_bfloat16* AOb = Tb + (size_t)2 * 4096 * 256;
    __nv_bfloat16* Sgb = Tb + (size_t)3 * 4096 * 256;
    __nv_bfloat16* Thb = Tb + (size_t)4 * 4096 * 256;

    run_ln(G, S0b, P1.ln1g, P1.ln1b, NTOK1);
    run_hgemm(S0b, 256, P1.wqkvT, Sqb, 256, bqkv + 768, nullptr, 0,
              NTOK1, 256, 256, 0, 1);
    smsa_xattn_kernel<<<4096, 256>>>(Sqb, QKVb, AOb);
    run_hgemm(AOb, 256, P1.woT, G, 256, P1.bo, G, 256, NTOK1, 256, 256, 0, 0);
    run_ln(G, Sgb, P1.ln2g, P1.ln2b, NTOK1);
    run_hgemm(Sgb, 256, P1.w1T, Thb, 1024, P1.b1, nullptr, 0, NTOK1, 1024, 256, 1, 1);
    run_hgemm(Thb, 1024, P1.w2T, G, 256, P1.b2, G, 256, NTOK1, 256, 1024, 0, 0);

    // 5) scatter g back to o1 window layout
    smsa_scatter_g_kernel<<<4096, 256>>>(G, out1);
}

// round 8
// speedup vs baseline: 4.6544x; 1.0020x over previous
#include <cuda_runtime.h>
#include <cuda_bf16.h>
#include <math.h>
#include <stdint.h>

// ---------------------------------------------------------------------------
// StackMSA round 8: LN fused everywhere — GEMM-epilogue LN (wo/mlp2), 
// add_pe+LN (scale0), pool+LN (scale1). HMMA GEMM + HMMA flash attention.
// B=4, H=W=8, M=16, C=256, NH=8, HD=32, GW=2
// out: [272, 256, 256] f32 = [o0 (256 win) ; o1 (16 win)]
// ---------------------------------------------------------------------------

#define NTOK0 65536
#define NTOK1 4096
#define ATTN_SMEM 61440     // Q/K/V: 3 x 256 rows x 80B
#define GEMM_SMEM 147456    // 3 stages x (16KB A + 32KB B)

// fp32 residual streams + scratch
__device__ float g_X0[65536 * 256];
__device__ float g_X1[4096 * 256];
__device__ float g_PE[2 * 256 * 256];
__device__ float g_G[4096 * 256];
// bf16 activation streams
__device__ __nv_bfloat16 g_Hb[65536 * 256];
__device__ __nv_bfloat16 g_H1b[4096 * 256];    // scale1 chain LN/attn outputs
__device__ __nv_bfloat16 g_QKVb[65536 * 768];
__device__ __nv_bfloat16 g_Tb[65536 * 1024];
__device__ __nv_bfloat16 g_WT[1572864];   // transposed weights [N,K] bf16

__device__ __forceinline__ float gelu_exact(float x) {
    return 0.5f * x * (1.0f + erff(x * 0.70710678118654752f));
}

__device__ __forceinline__ uint32_t smem_u32(const void* p) {
    uint32_t a;
    asm("{ .reg .u64 t; cvta.to.shared.u64 t, %1; cvt.u32.u64 %0, t; }"
        : "=r"(a) : "l"(p));
    return a;
}

#define SWZ128(o) ((o) ^ (((o) >> 3) & 0x70))
#define CP16(dst, src) \
    asm volatile("cp.async.cg.shared.global [%0], [%1], 16;" :: "r"(dst), "l"(src))
#define CPCOMMIT() asm volatile("cp.async.commit_group;" ::: "memory")
#define CPWAIT1() asm volatile("cp.async.wait_group 1;" ::: "memory")

#define LDSM_X4(r, addr) \
    asm volatile("ldmatrix.sync.aligned.m8n8.x4.shared.b16 {%0,%1,%2,%3}, [%4];" \
                 : "=r"((r)[0]), "=r"((r)[1]), "=r"((r)[2]), "=r"((r)[3]) : "r"(addr))
#define LDSM_X4T(r, addr) \
    asm volatile("ldmatrix.sync.aligned.m8n8.x4.trans.shared.b16 {%0,%1,%2,%3}, [%4];" \
                 : "=r"((r)[0]), "=r"((r)[1]), "=r"((r)[2]), "=r"((r)[3]) : "r"(addr))
#define MMA16816(d, a, b0, b1) \
    asm volatile("mma.sync.aligned.m16n8k16.row.col.f32.bf16.bf16.f32 " \
                 "{%0,%1,%2,%3}, {%4,%5,%6,%7}, {%8,%9}, {%0,%1,%2,%3};" \
                 : "+f"((d)[0]), "+f"((d)[1]), "+f"((d)[2]), "+f"((d)[3]) \
                 : "r"((a)[0]), "r"((a)[1]), "r"((a)[2]), "r"((a)[3]), \
                   "r"(b0), "r"(b1))

__device__ __forceinline__ uint32_t bf2u(float x, float y) {
    __nv_bfloat162 h = __float22bfloat162_rn(make_float2(x, y));
    return *(uint32_t*)&h;
}

// ---------------------------------------------------------------------------
// Position embedding table (fp32)
// ---------------------------------------------------------------------------
__global__ void smsa_posemb_kernel(const float* __restrict__ w1,
                                   const float* __restrict__ b1,
                                   const float* __restrict__ w2,
                                   float* __restrict__ pe) {
    int t = blockIdx.x, s = blockIdx.y, tid = threadIdx.x;
    __shared__ float hid[512];
    float c0 = (float)((t >> 4) - 8) * 0.125f;
    float c1 = (float)((t & 15) - 8) * 0.125f;
    const float* W1 = w1 + s * 1024;
    const float* B1 = b1 + s * 512;
    for (int k = tid; k < 512; k += 256)
        hid[k] = fmaxf(fmaf(c0, W1[k], fmaf(c1, W1[512 + k], B1[k])), 0.0f);
    __syncthreads();
    const float* W2 = w2 + s * 512 * 256;
    float acc = 0.0f;
#pragma unroll 8
    for (int k = 0; k < 512; k++) acc = fmaf(hid[k], W2[k * 256 + tid], acc);
    pe[s * 65536 + t * 256 + tid] = acc;
}

// plain add_pe (scale1 path: LN comes after pool)
__global__ void smsa_add_pe_kernel(const float* __restrict__ x,
                                   const float* __restrict__ pe,
                                   float* __restrict__ y) {
    size_t i = (size_t)blockIdx.x * 256 + threadIdx.x;
    float4 a = ((const float4*)x)[i];
    float4 p = ((const float4*)pe)[i & 16383];
    float4 r;
    r.x = a.x + p.x; r.y = a.y + p.y; r.z = a.z + p.z; r.w = a.w + p.w;
    ((float4*)y)[i] = r;
}

// fused add_pe + LN1 (scale0): one warp per token, writes X0 fp32 + Hb bf16
__global__ __launch_bounds__(256) void smsa_add_pe_ln_kernel(
    const float* __restrict__ x, const float* __restrict__ pe,
    float* __restrict__ y, __nv_bfloat16* __restrict__ hb,
    const float* __restrict__ gg, const float* __restrict__ bb) {
    int tok = blockIdx.x * 8 + (threadIdx.x >> 5);
    int lane = threadIdx.x & 31;
    const float4* xr = (const float4*)(x + (size_t)tok * 256);
    const float4* pr = (const float4*)(pe + (size_t)(tok & 255) * 256);
    float4 v0 = xr[lane], v1 = xr[lane + 32];
    float4 p0 = pr[lane], p1 = pr[lane + 32];
    v0.x += p0.x; v0.y += p0.y; v0.z += p0.z; v0.w += p0.w;
    v1.x += p1.x; v1.y += p1.y; v1.z += p1.z; v1.w += p1.w;
    float4* yr = (float4*)(y + (size_t)tok * 256);
    yr[lane] = v0;
    yr[lane + 32] = v1;
    float s = v0.x + v0.y + v0.z + v0.w + v1.x + v1.y + v1.z + v1.w;
    float ss = v0.x * v0.x + v0.y * v0.y + v0.z * v0.z + v0.w * v0.w +
               v1.x * v1.x + v1.y * v1.y + v1.z * v1.z + v1.w * v1.w;
#pragma unroll
    for (int o = 16; o > 0; o >>= 1) {
        s += __shfl_xor_sync(0xffffffffu, s, o);
        ss += __shfl_xor_sync(0xffffffffu, ss, o);
    }
    float mean = s * 0.00390625f;
    float var = ss * 0.00390625f - mean * mean;
    float rstd = rsqrtf(var + 1e-5f);
    float4 g0 = ((const float4*)gg)[lane], g1 = ((const float4*)gg)[lane + 32];
    float4 b0 = ((const float4*)bb)[lane], b1 = ((const float4*)bb)[lane + 32];
    uint2 o0, o1;
    o0.x = bf2u((v0.x - mean) * rstd * g0.x + b0.x, (v0.y - mean) * rstd * g0.y + b0.y);
    o0.y = bf2u((v0.z - mean) * rstd * g0.z + b0.z, (v0.w - mean) * rstd * g0.w + b0.w);
    o1.x = bf2u((v1.x - mean) * rstd * g1.x + b1.x, (v1.y - mean) * rstd * g1.y + b1.y);
    o1.y = bf2u((v1.z - mean) * rstd * g1.z + b1.z, (v1.w - mean) * rstd * g1.w + b1.w);
    uint2* hr = (uint2*)(hb + (size_t)tok * 256);
    hr[lane] = o0;
    hr[lane + 32] = o1;
}

// fused pool + LN1(scale1): one block per global token, writes X1 += max and
// H1b = LN(row)
__global__ __launch_bounds__(256) void smsa_pool_ln_kernel(
    const float* __restrict__ x0, float* __restrict__ x1,
    __nv_bfloat16* __restrict__ hb,
    const float* __restrict__ gg, const float* __restrict__ bb) {
    __shared__ float red[16];
    int gid = blockIdx.x, c = threadIdx.x;
    int b = gid >> 10, gr = (gid >> 5) & 31, gc = gid & 31;
    int h = gr >> 2, r1 = gr & 3, w = gc >> 2, r2 = gc & 3;
    int fw = (b * 8 + h) * 8 + w;
    const float* base = x0 + ((size_t)fw * 256 + r1 * 64 + r2 * 4) * 256 + c;
    float m = -1e30f;
#pragma unroll
    for (int p1 = 0; p1 < 4; p1++)
#pragma unroll
        for (int p2 = 0; p2 < 4; p2++)
            m = fmaxf(m, base[(p1 * 16 + p2) * 256]);
    int gwin = b * 4 + (gr >> 4) * 2 + (gc >> 4);
    int tt = (gr & 15) * 16 + (gc & 15);
    size_t idx = ((size_t)gwin * 256 + tt) * 256 + c;
    float v = x1[idx] + m;
    x1[idx] = v;
    // block LN over 256 channels
    float s = v, q = v * v;
#pragma unroll
    for (int o = 16; o > 0; o >>= 1) {
        s += __shfl_xor_sync(0xffffffffu, s, o);
        q += __shfl_xor_sync(0xffffffffu, q, o);
    }
    int warp = c >> 5, lane = c & 31;
    if (lane == 0) { red[warp] = s; red[warp + 8] = q; }
    __syncthreads();
    float S = 0.0f, Q = 0.0f;
#pragma unroll
    for (int wi = 0; wi < 8; wi++) { S += red[wi]; Q += red[wi + 8]; }
    float mean = S * 0.00390625f;
    float var = Q * 0.00390625f - mean * mean;
    float rstd = rsqrtf(var + 1e-5f);
    hb[idx] = __float2bfloat16((v - mean) * rstd * gg[c] + bb[c]);
}

// ---------------------------------------------------------------------------
// LayerNorm (standalone, used only for gathered G): fp32 in, bf16 out
// ---------------------------------------------------------------------------
__global__ __launch_bounds__(256) void smsa_ln_kernel(
    const float* __restrict__ x, __nv_bfloat16* __restrict__ y,
    const float* __restrict__ gg, const float* __restrict__ bb) {
    int tok = blockIdx.x * 8 + (threadIdx.x >> 5);
    int lane = threadIdx.x & 31;
    const float4* row = (const float4*)(x + (size_t)tok * 256);
    float4 v0 = row[lane], v1 = row[lane + 32];
    float s = v0.x + v0.y + v0.z + v0.w + v1.x + v1.y + v1.z + v1.w;
    float ss = v0.x * v0.x + v0.y * v0.y + v0.z * v0.z + v0.w * v0.w +
               v1.x * v1.x + v1.y * v1.y + v1.z * v1.z + v1.w * v1.w;
#pragma unroll
    for (int o = 16; o > 0; o >>= 1) {
        s += __shfl_xor_sync(0xffffffffu, s, o);
        ss += __shfl_xor_sync(0xffffffffu, ss, o);
    }
    float mean = s * 0.00390625f;
    float var = ss * 0.00390625f - mean * mean;
    float rstd = rsqrtf(var + 1e-5f);
    float4 g0 = ((const float4*)gg)[lane], g1 = ((const float4*)gg)[lane + 32];
    float4 b0 = ((const float4*)bb)[lane], b1 = ((const float4*)bb)[lane + 32];
    uint2 o0, o1;
    o0.x = bf2u((v0.x - mean) * rstd * g0.x + b0.x, (v0.y - mean) * rstd * g0.y + b0.y);
    o0.y = bf2u((v0.z - mean) * rstd * g0.z + b0.z, (v0.w - mean) * rstd * g0.w + b0.w);
    o1.x = bf2u((v1.x - mean) * rstd * g1.x + b1.x, (v1.y - mean) * rstd * g1.y + b1.y);
    o1.y = bf2u((v1.z - mean) * rstd * g1.z + b1.z, (v1.w - mean) * rstd * g1.w + b1.w);
    uint2* yr = (uint2*)(y + (size_t)tok * 256);
    yr[lane] = o0;
    yr[lane + 32] = o1;
}

// ---------------------------------------------------------------------------
// Fused weight transpose: 8 jobs, one launch. W[K,N] fp32 -> Wt[N,K] bf16.
// ---------------------------------------------------------------------------
struct TrJobs {
    const float* W[8];
    __nv_bfloat16* Wt[8];
    int K[8], N[8], blk0[8];
};

__global__ void smsa_transpose_all_kernel(TrJobs J) {
    __shared__ float t[32][33];
    int bid = blockIdx.x;
    int j = 0;
#pragma unroll
    for (int i = 1; i < 8; i++)
        if (bid >= J.blk0[i]) j = i;
    int rel = bid - J.blk0[j];
    int K = J.K[j], N = J.N[j];
    int nbx = N >> 5;
    int n0 = (rel % nbx) * 32, k0 = (rel / nbx) * 32;
    const float* W = J.W[j];
    __nv_bfloat16* Wt = J.Wt[j];
    int tx = threadIdx.x, ty = threadIdx.y;
#pragma unroll
    for (int i = 0; i < 32; i += 8)
        t[ty + i][tx] = W[(size_t)(k0 + ty + i) * N + n0 + tx];
    __syncthreads();
#pragma unroll
    for (int i = 0; i < 32; i += 8)
        Wt[(size_t)(n0 + ty + i) * K + k0 + tx] = __float2bfloat16(t[tx][ty + i]);
}

// ---------------------------------------------------------------------------
// bf16 HMMA GEMM, CTA tile 128x256, warp tile 32x64, 3-stage cp.async.
// Optional fused epilogue LN (requires N==256, ldc==256): writes lnout bf16.
// ---------------------------------------------------------------------------
__global__ __launch_bounds__(512, 1) void smsa_hgemm_kernel(
    const __nv_bfloat16* __restrict__ A, int lda,
    const __nv_bfloat16* __restrict__ Bt,
    void* __restrict__ Cm, int ldc,
    const float* __restrict__ bias,
    const float* __restrict__ res, int ldr,
    int K, int act, int outbf,
    const float* __restrict__ lng, const float* __restrict__ lnb,
    __nv_bfloat16* __restrict__ lnout) {
    extern __shared__ __align__(1024) char sm[];
    uint32_t sb = smem_u32(sm);
    const int tid = threadIdx.x;
    const int mb = blockIdx.y, nb = blockIdx.x;
    const int warp = tid >> 5, lane = tid & 31;
    const int wm = warp & 3, wn = warp >> 2;

    const __nv_bfloat16* Ag = A + (size_t)(mb * 128) * lda;
    const __nv_bfloat16* Bg = Bt + (size_t)(nb * 256) * K;

    const int nch = K >> 6;
    auto copy_stage = [&](int c, int s) {
        uint32_t sbase = sb + (uint32_t)s * 49152u;
        const __nv_bfloat16* ga = Ag + c * 64;
        const __nv_bfloat16* gb = Bg + c * 64;
#pragma unroll
        for (int p = 0; p < 2; p++) {
            int u = p * 512 + tid;
            int row = u >> 3, c16 = u & 7;
            CP16(sbase + SWZ128((uint32_t)row * 128 + c16 * 16),
                 ga + (size_t)row * lda + c16 * 8);
        }
#pragma unroll
        for (int p = 0; p < 4; p++) {
            int u = p * 512 + tid;
            int row = u >> 3, c16 = u & 7;
            CP16(sbase + 16384u + SWZ128((uint32_t)row * 128 + c16 * 16),
                 gb + (size_t)row * K + c16 * 8);
        }
    };

    float acc[2][8][4];
#pragma unroll
    for (int mt = 0; mt < 2; mt++)
#pragma unroll
        for (int nt = 0; nt < 8; nt++)
#pragma unroll
            for (int q = 0; q < 4; q++) acc[mt][nt][q] = 0.0f;

    const int a_row = wm * 32 + (lane & 15);
    const int b_row = wn * 64 + (lane & 15);
    const int hi = lane >> 4;

    copy_stage(0, 0);
    CPCOMMIT();
    if (nch > 1) copy_stage(1, 1);
    CPCOMMIT();

    for (int c = 0; c < nch; c++) {
        CPWAIT1();
        __syncthreads();
        if (c + 2 < nch) copy_stage(c + 2, (c + 2) % 3);
        CPCOMMIT();

        uint32_t abase = sb + (uint32_t)(c % 3) * 49152u;
        uint32_t bbase = abase + 16384u;
#pragma unroll
        for (int j = 0; j < 4; j++) {
            uint32_t af[2][4], bf[4][4];
            int ch = 2 * j + hi;
#pragma unroll
            for (int mt = 0; mt < 2; mt++) {
                uint32_t ad = abase + SWZ128((uint32_t)(a_row + mt * 16) * 128 + ch * 16);
                LDSM_X4(af[mt], ad);
            }
#pragma unroll
            for (int bt = 0; bt < 4; bt++) {
                uint32_t bd = bbase + SWZ128((uint32_t)(b_row + bt * 16) * 128 + ch * 16);
                LDSM_X4(bf[bt], bd);
            }
#pragma unroll
            for (int mt = 0; mt < 2; mt++)
#pragma unroll
                for (int nt = 0; nt < 8; nt++)
                    MMA16816(acc[mt][nt], af[mt],
                             bf[nt >> 1][nt & 1], bf[nt >> 1][(nt & 1) + 2]);
        }
        __syncthreads();
    }

    // epilogue: bias/res/act applied in place, then store
    int qrow = lane >> 2, qcol = (lane & 3) * 2;
#pragma unroll
    for (int mt = 0; mt < 2; mt++)
#pragma unroll
        for (int half = 0; half < 2; half++) {
            int row = mb * 128 + wm * 32 + mt * 16 + qrow + half * 8;
#pragma unroll
            for (int nt = 0; nt < 8; nt++) {
                int col = nb * 256 + wn * 64 + nt * 8 + qcol;
                float v0 = acc[mt][nt][half * 2 + 0];
                float v1 = acc[mt][nt][half * 2 + 1];
                if (bias) {
                    float2 bv = *(const float2*)(bias + col);
                    v0 += bv.x; v1 += bv.y;
                }
                if (res) {
                    float2 rr = *(const float2*)(res + (size_t)row * ldr + col);
                    v0 += rr.x; v1 += rr.y;
                }
                if (act) { v0 = gelu_exact(v0); v1 = gelu_exact(v1); }
                acc[mt][nt][half * 2 + 0] = v0;
                acc[mt][nt][half * 2 + 1] = v1;
                if (outbf) {
                    *(uint32_t*)((__nv_bfloat16*)Cm + (size_t)row * ldc + col) =
                        bf2u(v0, v1);
                } else {
                    *(float2*)((float*)Cm + (size_t)row * ldc + col) =
                        make_float2(v0, v1);
                }
            }
        }

    // fused LN over the full row (N==256, nb==0)
    if (lnout) {
        float* stats = (float*)sm;   // [128 rows][4 wn][2]
        float ps[2][2] = {{0, 0}, {0, 0}}, pq[2][2] = {{0, 0}, {0, 0}};
#pragma unroll
        for (int mt = 0; mt < 2; mt++)
#pragma unroll
            for (int half = 0; half < 2; half++)
#pragma unroll
                for (int nt = 0; nt < 8; nt++) {
                    float v0 = acc[mt][nt][half * 2], v1 = acc[mt][nt][half * 2 + 1];
                    ps[mt][half] += v0 + v1;
                    pq[mt][half] += v0 * v0 + v1 * v1;
                }
#pragma unroll
        for (int o = 1; o <= 2; o <<= 1)
#pragma unroll
            for (int mt = 0; mt < 2; mt++)
#pragma unroll
                for (int half = 0; half < 2; half++) {
                    ps[mt][half] += __shfl_xor_sync(0xffffffffu, ps[mt][half], o);
                    pq[mt][half] += __shfl_xor_sync(0xffffffffu, pq[mt][half], o);
                }
        if ((lane & 3) == 0) {
#pragma unroll
            for (int mt = 0; mt < 2; mt++)
#pragma unroll
                for (int half = 0; half < 2; half++) {
                    int rl = wm * 32 + mt * 16 + qrow + half * 8;
                    stats[rl * 8 + wn * 2] = ps[mt][half];
                    stats[rl * 8 + wn * 2 + 1] = pq[mt][half];
                }
        }
        __syncthreads();
#pragma unroll
        for (int mt = 0; mt < 2; mt++)
#pragma unroll
            for (int half = 0; half < 2; half++) {
                int rl = wm * 32 + mt * 16 + qrow + half * 8;
                float S = 0.0f, Q = 0.0f;
#pragma unroll
                for (int w2 = 0; w2 < 4; w2++) {
                    S += stats[rl * 8 + w2 * 2];
                    Q += stats[rl * 8 + w2 * 2 + 1];
                }
                float mean = S * 0.00390625f;
                float var = Q * 0.00390625f - mean * mean;
                float rstd = rsqrtf(var + 1e-5f);
                int row = mb * 128 + rl;
#pragma unroll
                for (int nt = 0; nt < 8; nt++) {
                    int col = wn * 64 + nt * 8 + qcol;
                    float2 gv = *(const float2*)(lng + col);
                    float2 bv2 = *(const float2*)(lnb + col);
                    float o0 = (acc[mt][nt][half * 2] - mean) * rstd * gv.x + bv2.x;
                    float o1 = (acc[mt][nt][half * 2 + 1] - mean) * rstd * gv.y + bv2.y;
                    *(uint32_t*)(lnout + (size_t)row * 256 + col) = bf2u(o0, o1);
                }
            }
    }
}

// ---------------------------------------------------------------------------
// Fused HMMA flash attention (unchanged from round 7)
// ---------------------------------------------------------------------------
__global__ __launch_bounds__(256) void smsa_fattn_kernel(
    const __nv_bfloat16* __restrict__ qkv, __nv_bfloat16* __restrict__ out) {
    extern __shared__ __align__(128) char smc[];
    uint32_t sbq = smem_u32(smc);
    const uint32_t Qs = sbq, Ks = sbq + 20480u, Vs = sbq + 40960u;
    int win = blockIdx.x >> 3, h = blockIdx.x & 7;
    int tid = threadIdx.x, lane = tid & 31, warp = tid >> 5;
    const __nv_bfloat16* base = qkv + (size_t)win * 256 * 768 + h * 32;

    {
        const uint4* qp = (const uint4*)(base + (size_t)tid * 768);
        const uint4* kp = (const uint4*)(base + (size_t)tid * 768 + 256);
        const uint4* vp = (const uint4*)(base + (size_t)tid * 768 + 512);
        uint32_t qd = Qs + tid * 80, kd = Ks + tid * 80, vd = Vs + tid * 80;
#pragma unroll
        for (int c = 0; c < 4; c++) {
            uint4 v;
            v = qp[c];
            asm volatile("st.shared.v4.b32 [%0], {%1,%2,%3,%4};"
                         :: "r"(qd + c * 16), "r"(v.x), "r"(v.y), "r"(v.z), "r"(v.w));
            v = kp[c];
            asm volatile("st.shared.v4.b32 [%0], {%1,%2,%3,%4};"
                         :: "r"(kd + c * 16), "r"(v.x), "r"(v.y), "r"(v.z), "r"(v.w));
            v = vp[c];
            asm volatile("st.shared.v4.b32 [%0], {%1,%2,%3,%4};"
                         :: "r"(vd + c * 16), "r"(v.x), "r"(v.y), "r"(v.z), "r"(v.w));
        }
    }
    __syncthreads();

    const int qb = warp * 32;
    uint32_t qf[2][2][4];
#pragma unroll
    for (int mt = 0; mt < 2; mt++)
#pragma unroll
        for (int kc = 0; kc < 2; kc++) {
            uint32_t ad = Qs + (uint32_t)(qb + mt * 16 + (lane & 15)) * 80
                          + (lane >> 4) * 16 + kc * 32;
            LDSM_X4(qf[mt][kc], ad);
        }

    float oacc[2][4][4];
#pragma unroll
    for (int mt = 0; mt < 2; mt++)
#pragma unroll
        for (int nt = 0; nt < 4; nt++)
#pragma unroll
            for (int q = 0; q < 4; q++) oacc[mt][nt][q] = 0.0f;
    float mrun[2][2] = {{-1e30f, -1e30f}, {-1e30f, -1e30f}};
    float lrun[2][2] = {{0.0f, 0.0f}, {0.0f, 0.0f}};
    const float C2 = 0.17677669529663687f * 1.4426950408889634f;

    for (int kb = 0; kb < 4; kb++) {
        float sacc[2][8][4];
#pragma unroll
        for (int mt = 0; mt < 2; mt++)
#pragma unroll
            for (int nt = 0; nt < 8; nt++)
#pragma unroll
                for (int q = 0; q < 4; q++) sacc[mt][nt][q] = 0.0f;

#pragma unroll
        for (int kc = 0; kc < 2; kc++) {
            uint32_t kf[4][4];
#pragma unroll
            for (int grp = 0; grp < 4; grp++) {
                uint32_t ad = Ks + (uint32_t)(kb * 64 + grp * 16 + (lane & 15)) * 80
                              + (lane >> 4) * 16 + kc * 32;
                LDSM_X4(kf[grp], ad);
            }
#pragma unroll
            for (int mt = 0; mt < 2; mt++)
#pragma unroll
                for (int nt = 0; nt < 8; nt++)
                    MMA16816(sacc[mt][nt], qf[mt][kc],
                             kf[nt >> 1][nt & 1], kf[nt >> 1][(nt & 1) + 2]);
        }

#pragma unroll
        for (int mt = 0; mt < 2; mt++)
#pragma unroll
            for (int hf = 0; hf < 2; hf++) {
                float mx = -1e30f;
#pragma unroll
                for (int nt = 0; nt < 8; nt++)
                    mx = fmaxf(mx, fmaxf(sacc[mt][nt][hf * 2], sacc[mt][nt][hf * 2 + 1]));
                mx = fmaxf(mx, __shfl_xor_sync(0xffffffffu, mx, 1));
                mx = fmaxf(mx, __shfl_xor_sync(0xffffffffu, mx, 2));
                float mold = mrun[mt][hf];
                float mnew = fmaxf(mold, mx);
                float corr = exp2f(C2 * (mold - mnew));
                mrun[mt][hf] = mnew;
                float sum = 0.0f;
#pragma unroll
                for (int nt = 0; nt < 8; nt++) {
                    float p0 = exp2f(C2 * (sacc[mt][nt][hf * 2] - mnew));
                    float p1 = exp2f(C2 * (sacc[mt][nt][hf * 2 + 1] - mnew));
                    sacc[mt][nt][hf * 2] = p0;
                    sacc[mt][nt][hf * 2 + 1] = p1;
                    sum += p0 + p1;
                }
                sum += __shfl_xor_sync(0xffffffffu, sum, 1);
                sum += __shfl_xor_sync(0xffffffffu, sum, 2);
                lrun[mt][hf] = lrun[mt][hf] * corr + sum;
#pragma unroll
                for (int nt = 0; nt < 4; nt++) {
                    oacc[mt][nt][hf * 2] *= corr;
                    oacc[mt][nt][hf * 2 + 1] *= corr;
                }
            }

#pragma unroll
        for (int kc4 = 0; kc4 < 4; kc4++) {
            uint32_t vf[2][4];
#pragma unroll
            for (int dg = 0; dg < 2; dg++) {
                uint32_t ad = Vs + (uint32_t)(kb * 64 + kc4 * 16 + (lane & 15)) * 80
                              + dg * 32 + (lane >> 4) * 16;
                LDSM_X4T(vf[dg], ad);
            }
#pragma unroll
            for (int mt = 0; mt < 2; mt++) {
                uint32_t a[4];
                a[0] = bf2u(sacc[mt][2 * kc4][0], sacc[mt][2 * kc4][1]);
                a[1] = bf2u(sacc[mt][2 * kc4][2], sacc[mt][2 * kc4][3]);
                a[2] = bf2u(sacc[mt][2 * kc4 + 1][0], sacc[mt][2 * kc4 + 1][1]);
                a[3] = bf2u(sacc[mt][2 * kc4 + 1][2], sacc[mt][2 * kc4 + 1][3]);
#pragma unroll
                for (int nt = 0; nt < 4; nt++)
                    MMA16816(oacc[mt][nt], a,
                             vf[nt >> 1][(nt & 1) * 2], vf[nt >> 1][(nt & 1) * 2 + 1]);
            }
        }
    }

#pragma unroll
    for (int mt = 0; mt < 2; mt++) {
        float inv0 = 1.0f / lrun[mt][0];
        float inv1 = 1.0f / lrun[mt][1];
        int row0 = win * 256 + qb + mt * 16 + (lane >> 2);
        int col = h * 32 + (lane & 3) * 2;
#pragma unroll
        for (int nt = 0; nt < 4; nt++) {
            *(uint32_t*)(out + (size_t)row0 * 256 + col + nt * 8) =
                bf2u(oacc[mt][nt][0] * inv0, oacc[mt][nt][1] * inv0);
            *(uint32_t*)(out + (size_t)(row0 + 8) * 256 + col + nt * 8) =
                bf2u(oacc[mt][nt][2] * inv1, oacc[mt][nt][3] * inv1);
        }
    }
}

// ---------------------------------------------------------------------------
// Cross-attention gather/scatter and 1->16 attention
// ---------------------------------------------------------------------------
__device__ __forceinline__ void decode_f(int f, int& fw, int& base_t,
                                         int& gwin, int& tt) {
    int b = f >> 10, h = (f >> 7) & 7, w = (f >> 4) & 7;
    int r1 = (f >> 2) & 3, r2 = f & 3;
    fw = (b * 8 + h) * 8 + w;
    base_t = r1 * 64 + r2 * 4;
    int gr = h * 4 + r1, gc = w * 4 + r2;
    gwin = b * 4 + (gr >> 4) * 2 + (gc >> 4);
    tt = (gr & 15) * 16 + (gc & 15);
}

__global__ void smsa_gather_g_kernel(const float* __restrict__ x1,
                                     float* __restrict__ g) {
    int f = blockIdx.x, c = threadIdx.x;
    int fw, base_t, gwin, tt;
    decode_f(f, fw, base_t, gwin, tt);
    g[(size_t)f * 256 + c] = x1[((size_t)gwin * 256 + tt) * 256 + c];
}

__global__ void smsa_scatter_g_kernel(const float* __restrict__ g,
                                      float* __restrict__ out1) {
    int f = blockIdx.x, c = threadIdx.x;
    int fw, base_t, gwin, tt;
    decode_f(f, fw, base_t, gwin, tt);
    out1[((size_t)gwin * 256 + tt) * 256 + c] = g[(size_t)f * 256 + c];
}

__global__ __launch_bounds__(256) void smsa_xattn_kernel(
    const __nv_bfloat16* __restrict__ Q, const __nv_bfloat16* __restrict__ KV,
    __nv_bfloat16* __restrict__ AO) {
    int f = blockIdx.x;
    int h = threadIdx.x >> 5;
    int d = threadIdx.x & 31;
    int fw, base_t, gwin, tt;
    decode_f(f, fw, base_t, gwin, tt);
    float qd = __bfloat162float(Q[(size_t)f * 256 + h * 32 + d]);
    const float sc = 0.17677669529663687f;
    float s[16];
#pragma unroll
    for (int j = 0; j < 16; j++) {
        int t = base_t + (j >> 2) * 16 + (j & 3);
        float kd = __bfloat162float(KV[((size_t)(fw * 256 + t)) * 512 + h * 32 + d]);
        float pr = qd * kd;
#pragma unroll
        for (int o = 16; o > 0; o >>= 1)
            pr += __shfl_xor_sync(0xffffffffu, pr, o);
        s[j] = pr * sc;
    }
    float m = s[0];
#pragma unroll
    for (int j = 1; j < 16; j++) m = fmaxf(m, s[j]);
    float l = 0.0f, p[16];
#pragma unroll
    for (int j = 0; j < 16; j++) {
        p[j] = __expf(s[j] - m);
        l += p[j];
    }
    float inv = 1.0f / l;
    float acc = 0.0f;
#pragma unroll
    for (int j = 0; j < 16; j++) {
        int t = base_t + (j >> 2) * 16 + (j & 3);
        acc = fmaf(p[j], __bfloat162float(
                        KV[((size_t)(fw * 256 + t)) * 512 + 256 + h * 32 + d]),
                   acc);
    }
    AO[(size_t)f * 256 + h * 32 + d] = __float2bfloat16(acc * inv);
}

// ---------------------------------------------------------------------------
// Host side
// ---------------------------------------------------------------------------
static void run_hgemm(const __nv_bfloat16* A, int lda, const __nv_bfloat16* Bt,
                      void* Cm, int ldc, const float* bias,
                      const float* res, int ldr, int M, int N, int K,
                      int act, int outbf,
                      const float* lng = nullptr, const float* lnb = nullptr,
                      __nv_bfloat16* lnout = nullptr) {
    dim3 grid(N / 256, M / 128);
    smsa_hgemm_kernel<<<grid, 512, GEMM_SMEM>>>(A, lda, Bt, Cm, ldc, bias,
                                                res, ldr, K, act, outbf,
                                                lng, lnb, lnout);
}

static void run_ln(const float* x, __nv_bfloat16* y, const float* g,
                   const float* b, int ntok) {
    smsa_ln_kernel<<<ntok / 8, 256>>>(x, y, g, b);
}

extern "C" void kernel_launch(void* const* d_in, const int* in_sizes, int n_in,
                              void* d_out, int out_size) {
    const float* scale0 = (const float*)d_in[0];
    const float* scale1 = (const float*)d_in[1];
    const float* pe_w1 = (const float*)d_in[2];
    const float* pe_b1 = (const float*)d_in[3];
    const float* pe_w2 = (const float*)d_in[4];
    const float* ln1_g = (const float*)d_in[5];
    const float* ln1_b = (const float*)d_in[6];
    const float* wqkv = (const float*)d_in[7];
    const float* bqkv = (const float*)d_in[8];
    const float* wo = (const float*)d_in[9];
    const float* bo = (const float*)d_in[10];
    const float* ln2_g = (const float*)d_in[11];
    const float* ln2_b = (const float*)d_in[12];
    const float* mw1 = (const float*)d_in[13];
    const float* mb1 = (const float*)d_in[14];
    const float* mw2 = (const float*)d_in[15];
    const float* mb2 = (const float*)d_in[16];
    float* out = (float*)d_out;
    float* out0 = out;
    float* out1 = out + (size_t)65536 * 256;

    float *X0, *X1, *PE, *G;
    __nv_bfloat16 *Hb, *H1b, *QKVb, *Tb, *WT;
    cudaGetSymbolAddress((void**)&X0, g_X0);
    cudaGetSymbolAddress((void**)&X1, g_X1);
    cudaGetSymbolAddress((void**)&PE, g_PE);
    cudaGetSymbolAddress((void**)&G, g_G);
    cudaGetSymbolAddress((void**)&Hb, g_Hb);
    cudaGetSymbolAddress((void**)&H1b, g_H1b);
    cudaGetSymbolAddress((void**)&QKVb, g_QKVb);
    cudaGetSymbolAddress((void**)&Tb, g_Tb);
    cudaGetSymbolAddress((void**)&WT, g_WT);

    cudaFuncSetAttribute(smsa_fattn_kernel,
                         cudaFuncAttributeMaxDynamicSharedMemorySize, ATTN_SMEM);
    cudaFuncSetAttribute(smsa_hgemm_kernel,
                         cudaFuncAttributeMaxDynamicSharedMemorySize, GEMM_SMEM);

    // weight param pointers (transposed bf16)
    const __nv_bfloat16 *wqkvT0 = WT + 0, *woT0 = WT + 196608;
    const __nv_bfloat16 *w1T0 = WT + 262144, *w2T0 = WT + 524288;
    const __nv_bfloat16 *wqkvT1 = WT + 786432, *woT1 = WT + 983040;
    const __nv_bfloat16 *w1T1 = WT + 1048576, *w2T1 = WT + 1310720;
    const float *ln1g0 = ln1_g, *ln1b0 = ln1_b;
    const float *ln2g0 = ln2_g, *ln2b0 = ln2_b;
    const float *ln1g1 = ln1_g + 256, *ln1b1 = ln1_b + 256;
    const float *ln2g1 = ln2_g + 256, *ln2b1 = ln2_b + 256;

    // 0) weight transposes, one launch ([K,N] fp32 -> [N,K] bf16)
    {
        TrJobs J;
        const float* Ws[8] = {wqkv, wqkv + 196608, wo, wo + 65536,
                              mw1, mw1 + 262144, mw2, mw2 + 262144};
        __nv_bfloat16* Wts[8] = {WT + 0, WT + 786432, WT + 196608, WT + 983040,
                                 WT + 262144, WT + 1048576, WT + 524288, WT + 1310720};
        int Ks[8] = {256, 256, 256, 256, 256, 256, 1024, 1024};
        int Ns[8] = {768, 768, 256, 256, 1024, 1024, 256, 256};
        int b0 = 0;
        for (int i = 0; i < 8; i++) {
            J.W[i] = Ws[i]; J.Wt[i] = Wts[i]; J.K[i] = Ks[i]; J.N[i] = Ns[i];
            J.blk0[i] = b0;
            b0 += (Ks[i] / 32) * (Ns[i] / 32);
        }
        smsa_transpose_all_kernel<<<b0, dim3(32, 8)>>>(J);
    }

    // 1) position embeddings; scale0 add+LN1 fused; scale1 add plain
    smsa_posemb_kernel<<<dim3(256, 2), 256>>>(pe_w1, pe_b1, pe_w2, PE);
    smsa_add_pe_ln_kernel<<<8192, 256>>>(scale0, PE, X0, Hb, ln1g0, ln1b0);
    smsa_add_pe_kernel<<<1024, 256>>>(scale1, PE + 65536, X1);

    // 2) pool + LN1(scale1) fused -> X1, H1b
    smsa_pool_ln_kernel<<<4096, 256>>>(X0, X1, H1b, ln1g1, ln1b1);

    // 3a) scale1 sattn chain (uses H1b; QKVb/Tb low rows, freed before scale0)
    run_hgemm(H1b, 256, wqkvT1, QKVb, 768, bqkv + 768, nullptr, 0,
              NTOK1, 768, 256, 0, 1);
    smsa_fattn_kernel<<<(NTOK1 / 256) * 8, 256, ATTN_SMEM>>>(QKVb, H1b);
    run_hgemm(H1b, 256, woT1, X1, 256, bo + 256, X1, 256,
              NTOK1, 256, 256, 0, 0, ln2g1, ln2b1, H1b);   // + fused LN2
    run_hgemm(H1b, 256, w1T1, Tb, 1024, mb1 + 1024, nullptr, 0,
              NTOK1, 1024, 256, 1, 1);
    run_hgemm(Tb, 1024, w2T1, X1, 256, mb2 + 256, X1, 256,
              NTOK1, 256, 1024, 0, 0);

    // 3b) scale0 sattn chain (Hb already made by add_pe_ln)
    run_hgemm(Hb, 256, wqkvT0, QKVb, 768, bqkv, nullptr, 0,
              NTOK0, 768, 256, 0, 1);
    smsa_fattn_kernel<<<(NTOK0 / 256) * 8, 256, ATTN_SMEM>>>(QKVb, Hb);
    run_hgemm(Hb, 256, woT0, X0, 256, bo, X0, 256,
              NTOK0, 256, 256, 0, 0, ln2g0, ln2b0, Hb);    // + fused LN2
    run_hgemm(Hb, 256, w1T0, Tb, 1024, mb1, nullptr, 0,
              NTOK0, 1024, 256, 1, 1);
    run_hgemm(Tb, 1024, w2T0, out0, 256, mb2, X0, 256,
              NTOK0, 256, 1024, 0, 0, ln1g1, ln1b1, Hb);   // + fused cross-LN(kn)

    // 4) cross-attention: K|V = Hb @ wqkv1[:,256:768] -> [65536,512] bf16
    run_hgemm(Hb, 256, wqkvT1 + 256 * 256, QKVb, 512, bqkv + 768 + 256,
              nullptr, 0, NTOK0, 512, 256, 0, 1);
    smsa_gather_g_kernel<<<4096, 256>>>(X1, G);

    __nv_bfloat16* S0b = Tb;
    __nv_bfloat16* Sqb = Tb + (size_t)4096 * 256;
    __nv_bfloat16* AOb = Tb + (size_t)2 * 4096 * 256;
    __nv_bfloat16* Sgb = Tb + (size_t)3 * 4096 * 256;
    __nv_bfloat16* Thb = Tb + (size_t)4 * 4096 * 256;

    run_ln(G, S0b, ln1g1, ln1b1, NTOK1);
    run_hgemm(S0b, 256, wqkvT1, Sqb, 256, bqkv + 768, nullptr, 0,
              NTOK1, 256, 256, 0, 1);
    smsa_xattn_kernel<<<4096, 256>>>(Sqb, QKVb, AOb);
    run_hgemm(AOb, 256, woT1, G, 256, bo + 256, G, 256,
              NTOK1, 256, 256, 0, 0, ln2g1, ln2b1, Sgb);   // + fused LN2
    run_hgemm(Sgb, 256, w1T1, Thb, 1024, mb1 + 1024, nullptr, 0,
              NTOK1, 1024, 256, 1, 1);
    run_hgemm(Thb, 1024, w2T1, G, 256, mb2 + 256, G, 256,
              NTOK1, 256, 1024, 0, 0);

    // 5) scatter g back to o1 window layout
    smsa_scatter_g_kernel<<<4096, 256>>>(G, out1);
}

// round 9
// speedup vs baseline: 5.1902x; 1.1151x over previous
#include <cuda_runtime.h>
#include <cuda_bf16.h>
#include <math.h>
#include <stdint.h>

// ---------------------------------------------------------------------------
// StackMSA round 9: occupancy-2 HMMA GEMM (128x128 tile, 256 thr, 3-stage
// cp.async, 2 CTAs/SM) to cover sync/epilogue stalls. LN-in-GEMM dropped
// (proven neutral); upstream add_pe+LN / pool+LN fusions kept.
// ---------------------------------------------------------------------------

#define NTOK0 65536
#define NTOK1 4096
#define ATTN_SMEM 61440     // Q/K/V: 3 x 256 rows x 80B
#define GEMM_SMEM 98304     // 3 stages x (16KB A + 16KB B)

// fp32 residual streams + scratch
__device__ float g_X0[65536 * 256];
__device__ float g_X1[4096 * 256];
__device__ float g_PE[2 * 256 * 256];
__device__ float g_G[4096 * 256];
// bf16 activation streams
__device__ __nv_bfloat16 g_Hb[65536 * 256];
__device__ __nv_bfloat16 g_H1b[4096 * 256];
__device__ __nv_bfloat16 g_QKVb[65536 * 768];
__device__ __nv_bfloat16 g_Tb[65536 * 1024];
__device__ __nv_bfloat16 g_WT[1572864];   // transposed weights [N,K] bf16

__device__ __forceinline__ float gelu_exact(float x) {
    return 0.5f * x * (1.0f + erff(x * 0.70710678118654752f));
}

__device__ __forceinline__ uint32_t smem_u32(const void* p) {
    uint32_t a;
    asm("{ .reg .u64 t; cvta.to.shared.u64 t, %1; cvt.u32.u64 %0, t; }"
        : "=r"(a) : "l"(p));
    return a;
}

#define SWZ128(o) ((o) ^ (((o) >> 3) & 0x70))
#define CP16(dst, src) \
    asm volatile("cp.async.cg.shared.global [%0], [%1], 16;" :: "r"(dst), "l"(src))
#define CPCOMMIT() asm volatile("cp.async.commit_group;" ::: "memory")
#define CPWAIT1() asm volatile("cp.async.wait_group 1;" ::: "memory")

#define LDSM_X4(r, addr) \
    asm volatile("ldmatrix.sync.aligned.m8n8.x4.shared.b16 {%0,%1,%2,%3}, [%4];" \
                 : "=r"((r)[0]), "=r"((r)[1]), "=r"((r)[2]), "=r"((r)[3]) : "r"(addr))
#define LDSM_X4T(r, addr) \
    asm volatile("ldmatrix.sync.aligned.m8n8.x4.trans.shared.b16 {%0,%1,%2,%3}, [%4];" \
                 : "=r"((r)[0]), "=r"((r)[1]), "=r"((r)[2]), "=r"((r)[3]) : "r"(addr))
#define MMA16816(d, a, b0, b1) \
    asm volatile("mma.sync.aligned.m16n8k16.row.col.f32.bf16.bf16.f32 " \
                 "{%0,%1,%2,%3}, {%4,%5,%6,%7}, {%8,%9}, {%0,%1,%2,%3};" \
                 : "+f"((d)[0]), "+f"((d)[1]), "+f"((d)[2]), "+f"((d)[3]) \
                 : "r"((a)[0]), "r"((a)[1]), "r"((a)[2]), "r"((a)[3]), \
                   "r"(b0), "r"(b1))

__device__ __forceinline__ uint32_t bf2u(float x, float y) {
    __nv_bfloat162 h = __float22bfloat162_rn(make_float2(x, y));
    return *(uint32_t*)&h;
}

// ---------------------------------------------------------------------------
// Position embedding table (fp32)
// ---------------------------------------------------------------------------
__global__ void smsa_posemb_kernel(const float* __restrict__ w1,
                                   const float* __restrict__ b1,
                                   const float* __restrict__ w2,
                                   float* __restrict__ pe) {
    int t = blockIdx.x, s = blockIdx.y, tid = threadIdx.x;
    __shared__ float hid[512];
    float c0 = (float)((t >> 4) - 8) * 0.125f;
    float c1 = (float)((t & 15) - 8) * 0.125f;
    const float* W1 = w1 + s * 1024;
    const float* B1 = b1 + s * 512;
    for (int k = tid; k < 512; k += 256)
        hid[k] = fmaxf(fmaf(c0, W1[k], fmaf(c1, W1[512 + k], B1[k])), 0.0f);
    __syncthreads();
    const float* W2 = w2 + s * 512 * 256;
    float acc = 0.0f;
#pragma unroll 8
    for (int k = 0; k < 512; k++) acc = fmaf(hid[k], W2[k * 256 + tid], acc);
    pe[s * 65536 + t * 256 + tid] = acc;
}

__global__ void smsa_add_pe_kernel(const float* __restrict__ x,
                                   const float* __restrict__ pe,
                                   float* __restrict__ y) {
    size_t i = (size_t)blockIdx.x * 256 + threadIdx.x;
    float4 a = ((const float4*)x)[i];
    float4 p = ((const float4*)pe)[i & 16383];
    float4 r;
    r.x = a.x + p.x; r.y = a.y + p.y; r.z = a.z + p.z; r.w = a.w + p.w;
    ((float4*)y)[i] = r;
}

// fused add_pe + LN1 (scale0)
__global__ __launch_bounds__(256) void smsa_add_pe_ln_kernel(
    const float* __restrict__ x, const float* __restrict__ pe,
    float* __restrict__ y, __nv_bfloat16* __restrict__ hb,
    const float* __restrict__ gg, const float* __restrict__ bb) {
    int tok = blockIdx.x * 8 + (threadIdx.x >> 5);
    int lane = threadIdx.x & 31;
    const float4* xr = (const float4*)(x + (size_t)tok * 256);
    const float4* pr = (const float4*)(pe + (size_t)(tok & 255) * 256);
    float4 v0 = xr[lane], v1 = xr[lane + 32];
    float4 p0 = pr[lane], p1 = pr[lane + 32];
    v0.x += p0.x; v0.y += p0.y; v0.z += p0.z; v0.w += p0.w;
    v1.x += p1.x; v1.y += p1.y; v1.z += p1.z; v1.w += p1.w;
    float4* yr = (float4*)(y + (size_t)tok * 256);
    yr[lane] = v0;
    yr[lane + 32] = v1;
    float s = v0.x + v0.y + v0.z + v0.w + v1.x + v1.y + v1.z + v1.w;
    float ss = v0.x * v0.x + v0.y * v0.y + v0.z * v0.z + v0.w * v0.w +
               v1.x * v1.x + v1.y * v1.y + v1.z * v1.z + v1.w * v1.w;
#pragma unroll
    for (int o = 16; o > 0; o >>= 1) {
        s += __shfl_xor_sync(0xffffffffu, s, o);
        ss += __shfl_xor_sync(0xffffffffu, ss, o);
    }
    float mean = s * 0.00390625f;
    float var = ss * 0.00390625f - mean * mean;
    float rstd = rsqrtf(var + 1e-5f);
    float4 g0 = ((const float4*)gg)[lane], g1 = ((const float4*)gg)[lane + 32];
    float4 b0 = ((const float4*)bb)[lane], b1 = ((const float4*)bb)[lane + 32];
    uint2 o0, o1;
    o0.x = bf2u((v0.x - mean) * rstd * g0.x + b0.x, (v0.y - mean) * rstd * g0.y + b0.y);
    o0.y = bf2u((v0.z - mean) * rstd * g0.z + b0.z, (v0.w - mean) * rstd * g0.w + b0.w);
    o1.x = bf2u((v1.x - mean) * rstd * g1.x + b1.x, (v1.y - mean) * rstd * g1.y + b1.y);
    o1.y = bf2u((v1.z - mean) * rstd * g1.z + b1.z, (v1.w - mean) * rstd * g1.w + b1.w);
    uint2* hr = (uint2*)(hb + (size_t)tok * 256);
    hr[lane] = o0;
    hr[lane + 32] = o1;
}

// fused pool + LN1(scale1)
__global__ __launch_bounds__(256) void smsa_pool_ln_kernel(
    const float* __restrict__ x0, float* __restrict__ x1,
    __nv_bfloat16* __restrict__ hb,
    const float* __restrict__ gg, const float* __restrict__ bb) {
    __shared__ float red[16];
    int gid = blockIdx.x, c = threadIdx.x;
    int b = gid >> 10, gr = (gid >> 5) & 31, gc = gid & 31;
    int h = gr >> 2, r1 = gr & 3, w = gc >> 2, r2 = gc & 3;
    int fw = (b * 8 + h) * 8 + w;
    const float* base = x0 + ((size_t)fw * 256 + r1 * 64 + r2 * 4) * 256 + c;
    float m = -1e30f;
#pragma unroll
    for (int p1 = 0; p1 < 4; p1++)
#pragma unroll
        for (int p2 = 0; p2 < 4; p2++)
            m = fmaxf(m, base[(p1 * 16 + p2) * 256]);
    int gwin = b * 4 + (gr >> 4) * 2 + (gc >> 4);
    int tt = (gr & 15) * 16 + (gc & 15);
    size_t idx = ((size_t)gwin * 256 + tt) * 256 + c;
    float v = x1[idx] + m;
    x1[idx] = v;
    float s = v, q = v * v;
#pragma unroll
    for (int o = 16; o > 0; o >>= 1) {
        s += __shfl_xor_sync(0xffffffffu, s, o);
        q += __shfl_xor_sync(0xffffffffu, q, o);
    }
    int warp = c >> 5, lane = c & 31;
    if (lane == 0) { red[warp] = s; red[warp + 8] = q; }
    __syncthreads();
    float S = 0.0f, Q = 0.0f;
#pragma unroll
    for (int wi = 0; wi < 8; wi++) { S += red[wi]; Q += red[wi + 8]; }
    float mean = S * 0.00390625f;
    float var = Q * 0.00390625f - mean * mean;
    float rstd = rsqrtf(var + 1e-5f);
    hb[idx] = __float2bfloat16((v - mean) * rstd * gg[c] + bb[c]);
}

// ---------------------------------------------------------------------------
// LayerNorm standalone: fp32 in, bf16 out
// ---------------------------------------------------------------------------
__global__ __launch_bounds__(256) void smsa_ln_kernel(
    const float* __restrict__ x, __nv_bfloat16* __restrict__ y,
    const float* __restrict__ gg, const float* __restrict__ bb) {
    int tok = blockIdx.x * 8 + (threadIdx.x >> 5);
    int lane = threadIdx.x & 31;
    const float4* row = (const float4*)(x + (size_t)tok * 256);
    float4 v0 = row[lane], v1 = row[lane + 32];
    float s = v0.x + v0.y + v0.z + v0.w + v1.x + v1.y + v1.z + v1.w;
    float ss = v0.x * v0.x + v0.y * v0.y + v0.z * v0.z + v0.w * v0.w +
               v1.x * v1.x + v1.y * v1.y + v1.z * v1.z + v1.w * v1.w;
#pragma unroll
    for (int o = 16; o > 0; o >>= 1) {
        s += __shfl_xor_sync(0xffffffffu, s, o);
        ss += __shfl_xor_sync(0xffffffffu, ss, o);
    }
    float mean = s * 0.00390625f;
    float var = ss * 0.00390625f - mean * mean;
    float rstd = rsqrtf(var + 1e-5f);
    float4 g0 = ((const float4*)gg)[lane], g1 = ((const float4*)gg)[lane + 32];
    float4 b0 = ((const float4*)bb)[lane], b1 = ((const float4*)bb)[lane + 32];
    uint2 o0, o1;
    o0.x = bf2u((v0.x - mean) * rstd * g0.x + b0.x, (v0.y - mean) * rstd * g0.y + b0.y);
    o0.y = bf2u((v0.z - mean) * rstd * g0.z + b0.z, (v0.w - mean) * rstd * g0.w + b0.w);
    o1.x = bf2u((v1.x - mean) * rstd * g1.x + b1.x, (v1.y - mean) * rstd * g1.y + b1.y);
    o1.y = bf2u((v1.z - mean) * rstd * g1.z + b1.z, (v1.w - mean) * rstd * g1.w + b1.w);
    uint2* yr = (uint2*)(y + (size_t)tok * 256);
    yr[lane] = o0;
    yr[lane + 32] = o1;
}

// ---------------------------------------------------------------------------
// Fused weight transpose: 8 jobs, one launch. W[K,N] fp32 -> Wt[N,K] bf16.
// ---------------------------------------------------------------------------
struct TrJobs {
    const float* W[8];
    __nv_bfloat16* Wt[8];
    int K[8], N[8], blk0[8];
};

__global__ void smsa_transpose_all_kernel(TrJobs J) {
    __shared__ float t[32][33];
    int bid = blockIdx.x;
    int j = 0;
#pragma unroll
    for (int i = 1; i < 8; i++)
        if (bid >= J.blk0[i]) j = i;
    int rel = bid - J.blk0[j];
    int K = J.K[j], N = J.N[j];
    int nbx = N >> 5;
    int n0 = (rel % nbx) * 32, k0 = (rel / nbx) * 32;
    const float* W = J.W[j];
    __nv_bfloat16* Wt = J.Wt[j];
    int tx = threadIdx.x, ty = threadIdx.y;
#pragma unroll
    for (int i = 0; i < 32; i += 8)
        t[ty + i][tx] = W[(size_t)(k0 + ty + i) * N + n0 + tx];
    __syncthreads();
#pragma unroll
    for (int i = 0; i < 32; i += 8)
        Wt[(size_t)(n0 + ty + i) * K + k0 + tx] = __float2bfloat16(t[tx][ty + i]);
}

// ---------------------------------------------------------------------------
// bf16 HMMA GEMM, CTA tile 128x128, 256 threads (8 warps: 4m x 2n, warp tile
// 32x64), 3-stage cp.async, occupancy 2 (96KB smem/CTA).
// ---------------------------------------------------------------------------
__global__ __launch_bounds__(256, 2) void smsa_hgemm_kernel(
    const __nv_bfloat16* __restrict__ A, int lda,
    const __nv_bfloat16* __restrict__ Bt,
    void* __restrict__ Cm, int ldc,
    const float* __restrict__ bias,
    const float* __restrict__ res, int ldr,
    int K, int act, int outbf) {
    extern __shared__ __align__(1024) char sm[];
    uint32_t sb = smem_u32(sm);
    const int tid = threadIdx.x;
    const int mb = blockIdx.y, nb = blockIdx.x;
    const int warp = tid >> 5, lane = tid & 31;
    const int wm = warp & 3, wn = warp >> 2;   // wm 0-3, wn 0-1

    const __nv_bfloat16* Ag = A + (size_t)(mb * 128) * lda;
    const __nv_bfloat16* Bg = Bt + (size_t)(nb * 128) * K;

    const int nch = K >> 6;
    auto copy_stage = [&](int c, int s) {
        uint32_t sbase = sb + (uint32_t)s * 32768u;
        const __nv_bfloat16* ga = Ag + c * 64;
        const __nv_bfloat16* gb = Bg + c * 64;
#pragma unroll
        for (int p = 0; p < 4; p++) {
            int u = p * 256 + tid;
            int row = u >> 3, c16 = u & 7;
            CP16(sbase + SWZ128((uint32_t)row * 128 + c16 * 16),
                 ga + (size_t)row * lda + c16 * 8);
        }
#pragma unroll
        for (int p = 0; p < 4; p++) {
            int u = p * 256 + tid;
            int row = u >> 3, c16 = u & 7;
            CP16(sbase + 16384u + SWZ128((uint32_t)row * 128 + c16 * 16),
                 gb + (size_t)row * K + c16 * 8);
        }
    };

    float acc[2][8][4];
#pragma unroll
    for (int mt = 0; mt < 2; mt++)
#pragma unroll
        for (int nt = 0; nt < 8; nt++)
#pragma unroll
            for (int q = 0; q < 4; q++) acc[mt][nt][q] = 0.0f;

    const int a_row = wm * 32 + (lane & 15);
    const int b_row = wn * 64 + (lane & 15);
    const int hi = lane >> 4;

    copy_stage(0, 0);
    CPCOMMIT();
    if (nch > 1) copy_stage(1, 1);
    CPCOMMIT();

    for (int c = 0; c < nch; c++) {
        CPWAIT1();
        __syncthreads();
        if (c + 2 < nch) copy_stage(c + 2, (c + 2) % 3);
        CPCOMMIT();

        uint32_t abase = sb + (uint32_t)(c % 3) * 32768u;
        uint32_t bbase = abase + 16384u;
#pragma unroll
        for (int j = 0; j < 4; j++) {
            uint32_t af[2][4], bf[4][4];
            int ch = 2 * j + hi;
#pragma unroll
            for (int mt = 0; mt < 2; mt++) {
                uint32_t ad = abase + SWZ128((uint32_t)(a_row + mt * 16) * 128 + ch * 16);
                LDSM_X4(af[mt], ad);
            }
#pragma unroll
            for (int bt = 0; bt < 4; bt++) {
                uint32_t bd = bbase + SWZ128((uint32_t)(b_row + bt * 16) * 128 + ch * 16);
                LDSM_X4(bf[bt], bd);
            }
#pragma unroll
            for (int mt = 0; mt < 2; mt++)
#pragma unroll
                for (int nt = 0; nt < 8; nt++)
                    MMA16816(acc[mt][nt], af[mt],
                             bf[nt >> 1][nt & 1], bf[nt >> 1][(nt & 1) + 2]);
        }
        __syncthreads();
    }

    int qrow = lane >> 2, qcol = (lane & 3) * 2;
#pragma unroll
    for (int mt = 0; mt < 2; mt++)
#pragma unroll
        for (int half = 0; half < 2; half++) {
            int row = mb * 128 + wm * 32 + mt * 16 + qrow + half * 8;
#pragma unroll
            for (int nt = 0; nt < 8; nt++) {
                int col = nb * 128 + wn * 64 + nt * 8 + qcol;
                float v0 = acc[mt][nt][half * 2 + 0];
                float v1 = acc[mt][nt][half * 2 + 1];
                if (bias) {
                    float2 bv = *(const float2*)(bias + col);
                    v0 += bv.x; v1 += bv.y;
                }
                if (res) {
                    float2 rr = *(const float2*)(res + (size_t)row * ldr + col);
                    v0 += rr.x; v1 += rr.y;
                }
                if (act) { v0 = gelu_exact(v0); v1 = gelu_exact(v1); }
                if (outbf) {
                    *(uint32_t*)((__nv_bfloat16*)Cm + (size_t)row * ldc + col) =
                        bf2u(v0, v1);
                } else {
                    *(float2*)((float*)Cm + (size_t)row * ldc + col) =
                        make_float2(v0, v1);
                }
            }
        }
}

// ---------------------------------------------------------------------------
// Fused HMMA flash attention (unchanged from round 7)
// ---------------------------------------------------------------------------
__global__ __launch_bounds__(256) void smsa_fattn_kernel(
    const __nv_bfloat16* __restrict__ qkv, __nv_bfloat16* __restrict__ out) {
    extern __shared__ __align__(128) char smc[];
    uint32_t sbq = smem_u32(smc);
    const uint32_t Qs = sbq, Ks = sbq + 20480u, Vs = sbq + 40960u;
    int win = blockIdx.x >> 3, h = blockIdx.x & 7;
    int tid = threadIdx.x, lane = tid & 31, warp = tid >> 5;
    const __nv_bfloat16* base = qkv + (size_t)win * 256 * 768 + h * 32;

    {
        const uint4* qp = (const uint4*)(base + (size_t)tid * 768);
        const uint4* kp = (const uint4*)(base + (size_t)tid * 768 + 256);
        const uint4* vp = (const uint4*)(base + (size_t)tid * 768 + 512);
        uint32_t qd = Qs + tid * 80, kd = Ks + tid * 80, vd = Vs + tid * 80;
#pragma unroll
        for (int c = 0; c < 4; c++) {
            uint4 v;
            v = qp[c];
            asm volatile("st.shared.v4.b32 [%0], {%1,%2,%3,%4};"
                         :: "r"(qd + c * 16), "r"(v.x), "r"(v.y), "r"(v.z), "r"(v.w));
            v = kp[c];
            asm volatile("st.shared.v4.b32 [%0], {%1,%2,%3,%4};"
                         :: "r"(kd + c * 16), "r"(v.x), "r"(v.y), "r"(v.z), "r"(v.w));
            v = vp[c];
            asm volatile("st.shared.v4.b32 [%0], {%1,%2,%3,%4};"
                         :: "r"(vd + c * 16), "r"(v.x), "r"(v.y), "r"(v.z), "r"(v.w));
        }
    }
    __syncthreads();

    const int qb = warp * 32;
    uint32_t qf[2][2][4];
#pragma unroll
    for (int mt = 0; mt < 2; mt++)
#pragma unroll
        for (int kc = 0; kc < 2; kc++) {
            uint32_t ad = Qs + (uint32_t)(qb + mt * 16 + (lane & 15)) * 80
                          + (lane >> 4) * 16 + kc * 32;
            LDSM_X4(qf[mt][kc], ad);
        }

    float oacc[2][4][4];
#pragma unroll
    for (int mt = 0; mt < 2; mt++)
#pragma unroll
        for (int nt = 0; nt < 4; nt++)
#pragma unroll
            for (int q = 0; q < 4; q++) oacc[mt][nt][q] = 0.0f;
    float mrun[2][2] = {{-1e30f, -1e30f}, {-1e30f, -1e30f}};
    float lrun[2][2] = {{0.0f, 0.0f}, {0.0f, 0.0f}};
    const float C2 = 0.17677669529663687f * 1.4426950408889634f;

    for (int kb = 0; kb < 4; kb++) {
        float sacc[2][8][4];
#pragma unroll
        for (int mt = 0; mt < 2; mt++)
#pragma unroll
            for (int nt = 0; nt < 8; nt++)
#pragma unroll
                for (int q = 0; q < 4; q++) sacc[mt][nt][q] = 0.0f;

#pragma unroll
        for (int kc = 0; kc < 2; kc++) {
            uint32_t kf[4][4];
#pragma unroll
            for (int grp = 0; grp < 4; grp++) {
                uint32_t ad = Ks + (uint32_t)(kb * 64 + grp * 16 + (lane & 15)) * 80
                              + (lane >> 4) * 16 + kc * 32;
                LDSM_X4(kf[grp], ad);
            }
#pragma unroll
            for (int mt = 0; mt < 2; mt++)
#pragma unroll
                for (int nt = 0; nt < 8; nt++)
                    MMA16816(sacc[mt][nt], qf[mt][kc],
                             kf[nt >> 1][nt & 1], kf[nt >> 1][(nt & 1) + 2]);
        }

#pragma unroll
        for (int mt = 0; mt < 2; mt++)
#pragma unroll
            for (int hf = 0; hf < 2; hf++) {
                float mx = -1e30f;
#pragma unroll
                for (int nt = 0; nt < 8; nt++)
                    mx = fmaxf(mx, fmaxf(sacc[mt][nt][hf * 2], sacc[mt][nt][hf * 2 + 1]));
                mx = fmaxf(mx, __shfl_xor_sync(0xffffffffu, mx, 1));
                mx = fmaxf(mx, __shfl_xor_sync(0xffffffffu, mx, 2));
                float mold = mrun[mt][hf];
                float mnew = fmaxf(mold, mx);
                float corr = exp2f(C2 * (mold - mnew));
                mrun[mt][hf] = mnew;
                float sum = 0.0f;
#pragma unroll
                for (int nt = 0; nt < 8; nt++) {
                    float p0 = exp2f(C2 * (sacc[mt][nt][hf * 2] - mnew));
                    float p1 = exp2f(C2 * (sacc[mt][nt][hf * 2 + 1] - mnew));
                    sacc[mt][nt][hf * 2] = p0;
                    sacc[mt][nt][hf * 2 + 1] = p1;
                    sum += p0 + p1;
                }
                sum += __shfl_xor_sync(0xffffffffu, sum, 1);
                sum += __shfl_xor_sync(0xffffffffu, sum, 2);
                lrun[mt][hf] = lrun[mt][hf] * corr + sum;
#pragma unroll
                for (int nt = 0; nt < 4; nt++) {
                    oacc[mt][nt][hf * 2] *= corr;
                    oacc[mt][nt][hf * 2 + 1] *= corr;
                }
            }

#pragma unroll
        for (int kc4 = 0; kc4 < 4; kc4++) {
            uint32_t vf[2][4];
#pragma unroll
            for (int dg = 0; dg < 2; dg++) {
                uint32_t ad = Vs + (uint32_t)(kb * 64 + kc4 * 16 + (lane & 15)) * 80
                              + dg * 32 + (lane >> 4) * 16;
                LDSM_X4T(vf[dg], ad);
            }
#pragma unroll
            for (int mt = 0; mt < 2; mt++) {
                uint32_t a[4];
                a[0] = bf2u(sacc[mt][2 * kc4][0], sacc[mt][2 * kc4][1]);
                a[1] = bf2u(sacc[mt][2 * kc4][2], sacc[mt][2 * kc4][3]);
                a[2] = bf2u(sacc[mt][2 * kc4 + 1][0], sacc[mt][2 * kc4 + 1][1]);
                a[3] = bf2u(sacc[mt][2 * kc4 + 1][2], sacc[mt][2 * kc4 + 1][3]);
#pragma unroll
                for (int nt = 0; nt < 4; nt++)
                    MMA16816(oacc[mt][nt], a,
                             vf[nt >> 1][(nt & 1) * 2], vf[nt >> 1][(nt & 1) * 2 + 1]);
            }
        }
    }

#pragma unroll
    for (int mt = 0; mt < 2; mt++) {
        float inv0 = 1.0f / lrun[mt][0];
        float inv1 = 1.0f / lrun[mt][1];
        int row0 = win * 256 + qb + mt * 16 + (lane >> 2);
        int col = h * 32 + (lane & 3) * 2;
#pragma unroll
        for (int nt = 0; nt < 4; nt++) {
            *(uint32_t*)(out + (size_t)row0 * 256 + col + nt * 8) =
                bf2u(oacc[mt][nt][0] * inv0, oacc[mt][nt][1] * inv0);
            *(uint32_t*)(out + (size_t)(row0 + 8) * 256 + col + nt * 8) =
                bf2u(oacc[mt][nt][2] * inv1, oacc[mt][nt][3] * inv1);
        }
    }
}

// ---------------------------------------------------------------------------
// Cross-attention gather/scatter and 1->16 attention
// ---------------------------------------------------------------------------
__device__ __forceinline__ void decode_f(int f, int& fw, int& base_t,
                                         int& gwin, int& tt) {
    int b = f >> 10, h = (f >> 7) & 7, w = (f >> 4) & 7;
    int r1 = (f >> 2) & 3, r2 = f & 3;
    fw = (b * 8 + h) * 8 + w;
    base_t = r1 * 64 + r2 * 4;
    int gr = h * 4 + r1, gc = w * 4 + r2;
    gwin = b * 4 + (gr >> 4) * 2 + (gc >> 4);
    tt = (gr & 15) * 16 + (gc & 15);
}

__global__ void smsa_gather_g_kernel(const float* __restrict__ x1,
                                     float* __restrict__ g) {
    int f = blockIdx.x, c = threadIdx.x;
    int fw, base_t, gwin, tt;
    decode_f(f, fw, base_t, gwin, tt);
    g[(size_t)f * 256 + c] = x1[((size_t)gwin * 256 + tt) * 256 + c];
}

__global__ void smsa_scatter_g_kernel(const float* __restrict__ g,
                                      float* __restrict__ out1) {
    int f = blockIdx.x, c = threadIdx.x;
    int fw, base_t, gwin, tt;
    decode_f(f, fw, base_t, gwin, tt);
    out1[((size_t)gwin * 256 + tt) * 256 + c] = g[(size_t)f * 256 + c];
}

__global__ __launch_bounds__(256) void smsa_xattn_kernel(
    const __nv_bfloat16* __restrict__ Q, const __nv_bfloat16* __restrict__ KV,
    __nv_bfloat16* __restrict__ AO) {
    int f = blockIdx.x;
    int h = threadIdx.x >> 5;
    int d = threadIdx.x & 31;
    int fw, base_t, gwin, tt;
    decode_f(f, fw, base_t, gwin, tt);
    float qd = __bfloat162float(Q[(size_t)f * 256 + h * 32 + d]);
    const float sc = 0.17677669529663687f;
    float s[16];
#pragma unroll
    for (int j = 0; j < 16; j++) {
        int t = base_t + (j >> 2) * 16 + (j & 3);
        float kd = __bfloat162float(KV[((size_t)(fw * 256 + t)) * 512 + h * 32 + d]);
        float pr = qd * kd;
#pragma unroll
        for (int o = 16; o > 0; o >>= 1)
            pr += __shfl_xor_sync(0xffffffffu, pr, o);
        s[j] = pr * sc;
    }
    float m = s[0];
#pragma unroll
    for (int j = 1; j < 16; j++) m = fmaxf(m, s[j]);
    float l = 0.0f, p[16];
#pragma unroll
    for (int j = 0; j < 16; j++) {
        p[j] = __expf(s[j] - m);
        l += p[j];
    }
    float inv = 1.0f / l;
    float acc = 0.0f;
#pragma unroll
    for (int j = 0; j < 16; j++) {
        int t = base_t + (j >> 2) * 16 + (j & 3);
        acc = fmaf(p[j], __bfloat162float(
                        KV[((size_t)(fw * 256 + t)) * 512 + 256 + h * 32 + d]),
                   acc);
    }
    AO[(size_t)f * 256 + h * 32 + d] = __float2bfloat16(acc * inv);
}

// ---------------------------------------------------------------------------
// Host side
// ---------------------------------------------------------------------------
static void run_hgemm(const __nv_bfloat16* A, int lda, const __nv_bfloat16* Bt,
                      void* Cm, int ldc, const float* bias,
                      const float* res, int ldr, int M, int N, int K,
                      int act, int outbf) {
    dim3 grid(N / 128, M / 128);
    smsa_hgemm_kernel<<<grid, 256, GEMM_SMEM>>>(A, lda, Bt, Cm, ldc, bias,
                                                res, ldr, K, act, outbf);
}

static void run_ln(const float* x, __nv_bfloat16* y, const float* g,
                   const float* b, int ntok) {
    smsa_ln_kernel<<<ntok / 8, 256>>>(x, y, g, b);
}

extern "C" void kernel_launch(void* const* d_in, const int* in_sizes, int n_in,
                              void* d_out, int out_size) {
    const float* scale0 = (const float*)d_in[0];
    const float* scale1 = (const float*)d_in[1];
    const float* pe_w1 = (const float*)d_in[2];
    const float* pe_b1 = (const float*)d_in[3];
    const float* pe_w2 = (const float*)d_in[4];
    const float* ln1_g = (const float*)d_in[5];
    const float* ln1_b = (const float*)d_in[6];
    const float* wqkv = (const float*)d_in[7];
    const float* bqkv = (const float*)d_in[8];
    const float* wo = (const float*)d_in[9];
    const float* bo = (const float*)d_in[10];
    const float* ln2_g = (const float*)d_in[11];
    const float* ln2_b = (const float*)d_in[12];
    const float* mw1 = (const float*)d_in[13];
    const float* mb1 = (const float*)d_in[14];
    const float* mw2 = (const float*)d_in[15];
    const float* mb2 = (const float*)d_in[16];
    float* out = (float*)d_out;
    float* out0 = out;
    float* out1 = out + (size_t)65536 * 256;

    float *X0, *X1, *PE, *G;
    __nv_bfloat16 *Hb, *H1b, *QKVb, *Tb, *WT;
    cudaGetSymbolAddress((void**)&X0, g_X0);
    cudaGetSymbolAddress((void**)&X1, g_X1);
    cudaGetSymbolAddress((void**)&PE, g_PE);
    cudaGetSymbolAddress((void**)&G, g_G);
    cudaGetSymbolAddress((void**)&Hb, g_Hb);
    cudaGetSymbolAddress((void**)&H1b, g_H1b);
    cudaGetSymbolAddress((void**)&QKVb, g_QKVb);
    cudaGetSymbolAddress((void**)&Tb, g_Tb);
    cudaGetSymbolAddress((void**)&WT, g_WT);

    cudaFuncSetAttribute(smsa_fattn_kernel,
                         cudaFuncAttributeMaxDynamicSharedMemorySize, ATTN_SMEM);
    cudaFuncSetAttribute(smsa_hgemm_kernel,
                         cudaFuncAttributeMaxDynamicSharedMemorySize, GEMM_SMEM);

    const __nv_bfloat16 *wqkvT0 = WT + 0, *woT0 = WT + 196608;
    const __nv_bfloat16 *w1T0 = WT + 262144, *w2T0 = WT + 524288;
    const __nv_bfloat16 *wqkvT1 = WT + 786432, *woT1 = WT + 983040;
    const __nv_bfloat16 *w1T1 = WT + 1048576, *w2T1 = WT + 1310720;
    const float *ln1g0 = ln1_g, *ln1b0 = ln1_b;
    const float *ln2g0 = ln2_g, *ln2b0 = ln2_b;
    const float *ln1g1 = ln1_g + 256, *ln1b1 = ln1_b + 256;
    const float *ln2g1 = ln2_g + 256, *ln2b1 = ln2_b + 256;

    // 0) weight transposes, one launch
    {
        TrJobs J;
        const float* Ws[8] = {wqkv, wqkv + 196608, wo, wo + 65536,
                              mw1, mw1 + 262144, mw2, mw2 + 262144};
        __nv_bfloat16* Wts[8] = {WT + 0, WT + 786432, WT + 196608, WT + 983040,
                                 WT + 262144, WT + 1048576, WT + 524288, WT + 1310720};
        int Ks[8] = {256, 256, 256, 256, 256, 256, 1024, 1024};
        int Ns[8] = {768, 768, 256, 256, 1024, 1024, 256, 256};
        int b0 = 0;
        for (int i = 0; i < 8; i++) {
            J.W[i] = Ws[i]; J.Wt[i] = Wts[i]; J.K[i] = Ks[i]; J.N[i] = Ns[i];
            J.blk0[i] = b0;
            b0 += (Ks[i] / 32) * (Ns[i] / 32);
        }
        smsa_transpose_all_kernel<<<b0, dim3(32, 8)>>>(J);
    }

    // 1) position embeddings; scale0 add+LN1 fused; scale1 add plain
    smsa_posemb_kernel<<<dim3(256, 2), 256>>>(pe_w1, pe_b1, pe_w2, PE);
    smsa_add_pe_ln_kernel<<<8192, 256>>>(scale0, PE, X0, Hb, ln1g0, ln1b0);
    smsa_add_pe_kernel<<<1024, 256>>>(scale1, PE + 65536, X1);

    // 2) pool + LN1(scale1) fused -> X1, H1b
    smsa_pool_ln_kernel<<<4096, 256>>>(X0, X1, H1b, ln1g1, ln1b1);

    // 3a) scale1 sattn chain
    run_hgemm(H1b, 256, wqkvT1, QKVb, 768, bqkv + 768, nullptr, 0,
              NTOK1, 768, 256, 0, 1);
    smsa_fattn_kernel<<<(NTOK1 / 256) * 8, 256, ATTN_SMEM>>>(QKVb, H1b);
    run_hgemm(H1b, 256, woT1, X1, 256, bo + 256, X1, 256,
              NTOK1, 256, 256, 0, 0);
    run_ln(X1, H1b, ln2g1, ln2b1, NTOK1);
    run_hgemm(H1b, 256, w1T1, Tb, 1024, mb1 + 1024, nullptr, 0,
              NTOK1, 1024, 256, 1, 1);
    run_hgemm(Tb, 1024, w2T1, X1, 256, mb2 + 256, X1, 256,
              NTOK1, 256, 1024, 0, 0);

    // 3b) scale0 sattn chain
    run_hgemm(Hb, 256, wqkvT0, QKVb, 768, bqkv, nullptr, 0,
              NTOK0, 768, 256, 0, 1);
    smsa_fattn_kernel<<<(NTOK0 / 256) * 8, 256, ATTN_SMEM>>>(QKVb, Hb);
    run_hgemm(Hb, 256, woT0, X0, 256, bo, X0, 256,
              NTOK0, 256, 256, 0, 0);
    run_ln(X0, Hb, ln2g0, ln2b0, NTOK0);
    run_hgemm(Hb, 256, w1T0, Tb, 1024, mb1, nullptr, 0,
              NTOK0, 1024, 256, 1, 1);
    run_hgemm(Tb, 1024, w2T0, out0, 256, mb2, X0, 256,
              NTOK0, 256, 1024, 0, 0);
    run_ln(out0, Hb, ln1g1, ln1b1, NTOK0);   // cross kn LN

    // 4) cross-attention
    run_hgemm(Hb, 256, wqkvT1 + 256 * 256, QKVb, 512, bqkv + 768 + 256,
              nullptr, 0, NTOK0, 512, 256, 0, 1);
    smsa_gather_g_kernel<<<4096, 256>>>(X1, G);

    __nv_bfloat16* S0b = Tb;
    __nv_bfloat16* Sqb = Tb + (size_t)4096 * 256;
    __nv_bfloat16* AOb = Tb + (size_t)2 * 4096 * 256;
    __nv_bfloat16* Sgb = Tb + (size_t)3 * 4096 * 256;
    __nv_bfloat16* Thb = Tb + (size_t)4 * 4096 * 256;

    run_ln(G, S0b, ln1g1, ln1b1, NTOK1);
    run_hgemm(S0b, 256, wqkvT1, Sqb, 256, bqkv + 768, nullptr, 0,
              NTOK1, 256, 256, 0, 1);
    smsa_xattn_kernel<<<4096, 256>>>(Sqb, QKVb, AOb);
    run_hgemm(AOb, 256, woT1, G, 256, bo + 256, G, 256, NTOK1, 256, 256, 0, 0);
    run_ln(G, Sgb, ln2g1, ln2b1, NTOK1);
    run_hgemm(Sgb, 256, w1T1, Thb, 1024, mb1 + 1024, nullptr, 0,
              NTOK1, 1024, 256, 1, 1);
    run_hgemm(Thb, 1024, w2T1, G, 256, mb2 + 256, G, 256, NTOK1, 256, 1024, 0, 0);

    // 5) scatter g back to o1 window layout
    smsa_scatter_g_kernel<<<4096, 256>>>(G, out1);
}

// round 10
// speedup vs baseline: 5.3301x; 1.0270x over previous
#include <cuda_runtime.h>
#include <cuda_bf16.h>
#include <math.h>
#include <stdint.h>

// ---------------------------------------------------------------------------
// StackMSA round 10: merged scale0+scale1 chain (segmented GEMM/LN/attention,
// scale1 rows appended after scale0), single-sync GEMM mainloop, occ-2 HMMA.
// B=4, H=W=8, M=16, C=256, NH=8, HD=32, GW=2
// out: [272, 256, 256] f32 = [o0 (256 win) ; o1 (16 win)]
// ---------------------------------------------------------------------------

#define NTOK0 65536
#define NTOK1 4096
#define NTOKA 69632           // merged rows
#define MB1T 512              // tile boundary (65536/128)
#define ATTN_SMEM 61440       // Q/K/V: 3 x 256 rows x 80B
#define GEMM_SMEM 98304       // 3 stages x (16KB A + 16KB B)

// fp32 residual stream: X = [X0 (65536) ; X1 (4096)]
__device__ float g_X[69632 * 256];
__device__ float g_PE[2 * 256 * 256];
__device__ float g_G[4096 * 256];
// bf16 activation streams (merged rows)
__device__ __nv_bfloat16 g_Hb[69632 * 256];
__device__ __nv_bfloat16 g_QKVb[69632 * 768];
__device__ __nv_bfloat16 g_Tb[69632 * 1024];
__device__ __nv_bfloat16 g_WT[1572864];   // transposed weights [N,K] bf16

__device__ __forceinline__ float gelu_exact(float x) {
    return 0.5f * x * (1.0f + erff(x * 0.70710678118654752f));
}

__device__ __forceinline__ uint32_t smem_u32(const void* p) {
    uint32_t a;
    asm("{ .reg .u64 t; cvta.to.shared.u64 t, %1; cvt.u32.u64 %0, t; }"
        : "=r"(a) : "l"(p));
    return a;
}

#define SWZ128(o) ((o) ^ (((o) >> 3) & 0x70))
#define CP16(dst, src) \
    asm volatile("cp.async.cg.shared.global [%0], [%1], 16;" :: "r"(dst), "l"(src))
#define CPCOMMIT() asm volatile("cp.async.commit_group;" ::: "memory")
#define CPWAIT1() asm volatile("cp.async.wait_group 1;" ::: "memory")

#define LDSM_X4(r, addr) \
    asm volatile("ldmatrix.sync.aligned.m8n8.x4.shared.b16 {%0,%1,%2,%3}, [%4];" \
                 : "=r"((r)[0]), "=r"((r)[1]), "=r"((r)[2]), "=r"((r)[3]) : "r"(addr))
#define LDSM_X4T(r, addr) \
    asm volatile("ldmatrix.sync.aligned.m8n8.x4.trans.shared.b16 {%0,%1,%2,%3}, [%4];" \
                 : "=r"((r)[0]), "=r"((r)[1]), "=r"((r)[2]), "=r"((r)[3]) : "r"(addr))
#define MMA16816(d, a, b0, b1) \
    asm volatile("mma.sync.aligned.m16n8k16.row.col.f32.bf16.bf16.f32 " \
                 "{%0,%1,%2,%3}, {%4,%5,%6,%7}, {%8,%9}, {%0,%1,%2,%3};" \
                 : "+f"((d)[0]), "+f"((d)[1]), "+f"((d)[2]), "+f"((d)[3]) \
                 : "r"((a)[0]), "r"((a)[1]), "r"((a)[2]), "r"((a)[3]), \
                   "r"(b0), "r"(b1))

__device__ __forceinline__ uint32_t bf2u(float x, float y) {
    __nv_bfloat162 h = __float22bfloat162_rn(make_float2(x, y));
    return *(uint32_t*)&h;
}

// ---------------------------------------------------------------------------
// Position embedding table (fp32)
// ---------------------------------------------------------------------------
__global__ void smsa_posemb_kernel(const float* __restrict__ w1,
                                   const float* __restrict__ b1,
                                   const float* __restrict__ w2,
                                   float* __restrict__ pe) {
    int t = blockIdx.x, s = blockIdx.y, tid = threadIdx.x;
    __shared__ float hid[512];
    float c0 = (float)((t >> 4) - 8) * 0.125f;
    float c1 = (float)((t & 15) - 8) * 0.125f;
    const float* W1 = w1 + s * 1024;
    const float* B1 = b1 + s * 512;
    for (int k = tid; k < 512; k += 256)
        hid[k] = fmaxf(fmaf(c0, W1[k], fmaf(c1, W1[512 + k], B1[k])), 0.0f);
    __syncthreads();
    const float* W2 = w2 + s * 512 * 256;
    float acc = 0.0f;
#pragma unroll 8
    for (int k = 0; k < 512; k++) acc = fmaf(hid[k], W2[k * 256 + tid], acc);
    pe[s * 65536 + t * 256 + tid] = acc;
}

__global__ void smsa_add_pe_kernel(const float* __restrict__ x,
                                   const float* __restrict__ pe,
                                   float* __restrict__ y) {
    size_t i = (size_t)blockIdx.x * 256 + threadIdx.x;
    float4 a = ((const float4*)x)[i];
    float4 p = ((const float4*)pe)[i & 16383];
    float4 r;
    r.x = a.x + p.x; r.y = a.y + p.y; r.z = a.z + p.z; r.w = a.w + p.w;
    ((float4*)y)[i] = r;
}

// fused add_pe + LN1 (scale0)
__global__ __launch_bounds__(256) void smsa_add_pe_ln_kernel(
    const float* __restrict__ x, const float* __restrict__ pe,
    float* __restrict__ y, __nv_bfloat16* __restrict__ hb,
    const float* __restrict__ gg, const float* __restrict__ bb) {
    int tok = blockIdx.x * 8 + (threadIdx.x >> 5);
    int lane = threadIdx.x & 31;
    const float4* xr = (const float4*)(x + (size_t)tok * 256);
    const float4* pr = (const float4*)(pe + (size_t)(tok & 255) * 256);
    float4 v0 = xr[lane], v1 = xr[lane + 32];
    float4 p0 = pr[lane], p1 = pr[lane + 32];
    v0.x += p0.x; v0.y += p0.y; v0.z += p0.z; v0.w += p0.w;
    v1.x += p1.x; v1.y += p1.y; v1.z += p1.z; v1.w += p1.w;
    float4* yr = (float4*)(y + (size_t)tok * 256);
    yr[lane] = v0;
    yr[lane + 32] = v1;
    float s = v0.x + v0.y + v0.z + v0.w + v1.x + v1.y + v1.z + v1.w;
    float ss = v0.x * v0.x + v0.y * v0.y + v0.z * v0.z + v0.w * v0.w +
               v1.x * v1.x + v1.y * v1.y + v1.z * v1.z + v1.w * v1.w;
#pragma unroll
    for (int o = 16; o > 0; o >>= 1) {
        s += __shfl_xor_sync(0xffffffffu, s, o);
        ss += __shfl_xor_sync(0xffffffffu, ss, o);
    }
    float mean = s * 0.00390625f;
    float var = ss * 0.00390625f - mean * mean;
    float rstd = rsqrtf(var + 1e-5f);
    float4 g0 = ((const float4*)gg)[lane], g1 = ((const float4*)gg)[lane + 32];
    float4 b0 = ((const float4*)bb)[lane], b1 = ((const float4*)bb)[lane + 32];
    uint2 o0, o1;
    o0.x = bf2u((v0.x - mean) * rstd * g0.x + b0.x, (v0.y - mean) * rstd * g0.y + b0.y);
    o0.y = bf2u((v0.z - mean) * rstd * g0.z + b0.z, (v0.w - mean) * rstd * g0.w + b0.w);
    o1.x = bf2u((v1.x - mean) * rstd * g1.x + b1.x, (v1.y - mean) * rstd * g1.y + b1.y);
    o1.y = bf2u((v1.z - mean) * rstd * g1.z + b1.z, (v1.w - mean) * rstd * g1.w + b1.w);
    uint2* hr = (uint2*)(hb + (size_t)tok * 256);
    hr[lane] = o0;
    hr[lane + 32] = o1;
}

// fused pool + LN1(scale1): writes X1 region and Hb rows 65536+
__global__ __launch_bounds__(256) void smsa_pool_ln_kernel(
    const float* __restrict__ x0, float* __restrict__ x1,
    __nv_bfloat16* __restrict__ hb1,
    const float* __restrict__ gg, const float* __restrict__ bb) {
    __shared__ float red[16];
    int gid = blockIdx.x, c = threadIdx.x;
    int b = gid >> 10, gr = (gid >> 5) & 31, gc = gid & 31;
    int h = gr >> 2, r1 = gr & 3, w = gc >> 2, r2 = gc & 3;
    int fw = (b * 8 + h) * 8 + w;
    const float* base = x0 + ((size_t)fw * 256 + r1 * 64 + r2 * 4) * 256 + c;
    float m = -1e30f;
#pragma unroll
    for (int p1 = 0; p1 < 4; p1++)
#pragma unroll
        for (int p2 = 0; p2 < 4; p2++)
            m = fmaxf(m, base[(p1 * 16 + p2) * 256]);
    int gwin = b * 4 + (gr >> 4) * 2 + (gc >> 4);
    int tt = (gr & 15) * 16 + (gc & 15);
    size_t idx = ((size_t)gwin * 256 + tt) * 256 + c;
    float v = x1[idx] + m;
    x1[idx] = v;
    float s = v, q = v * v;
#pragma unroll
    for (int o = 16; o > 0; o >>= 1) {
        s += __shfl_xor_sync(0xffffffffu, s, o);
        q += __shfl_xor_sync(0xffffffffu, q, o);
    }
    int warp = c >> 5, lane = c & 31;
    if (lane == 0) { red[warp] = s; red[warp + 8] = q; }
    __syncthreads();
    float S = 0.0f, Q = 0.0f;
#pragma unroll
    for (int wi = 0; wi < 8; wi++) { S += red[wi]; Q += red[wi + 8]; }
    float mean = S * 0.00390625f;
    float var = Q * 0.00390625f - mean * mean;
    float rstd = rsqrtf(var + 1e-5f);
    hb1[idx] = __float2bfloat16((v - mean) * rstd * gg[c] + bb[c]);
}

// ---------------------------------------------------------------------------
// LayerNorm, segmented params: tokens >= bnd use g1/b1. fp32 in, bf16 out.
// ---------------------------------------------------------------------------
__global__ __launch_bounds__(256) void smsa_ln_kernel(
    const float* __restrict__ x, __nv_bfloat16* __restrict__ y,
    const float* __restrict__ gg0, const float* __restrict__ bb0,
    const float* __restrict__ gg1, const float* __restrict__ bb1, int bnd) {
    int tok = blockIdx.x * 8 + (threadIdx.x >> 5);
    int lane = threadIdx.x & 31;
    const float* gg = tok < bnd ? gg0 : gg1;
    const float* bb = tok < bnd ? bb0 : bb1;
    const float4* row = (const float4*)(x + (size_t)tok * 256);
    float4 v0 = row[lane], v1 = row[lane + 32];
    float s = v0.x + v0.y + v0.z + v0.w + v1.x + v1.y + v1.z + v1.w;
    float ss = v0.x * v0.x + v0.y * v0.y + v0.z * v0.z + v0.w * v0.w +
               v1.x * v1.x + v1.y * v1.y + v1.z * v1.z + v1.w * v1.w;
#pragma unroll
    for (int o = 16; o > 0; o >>= 1) {
        s += __shfl_xor_sync(0xffffffffu, s, o);
        ss += __shfl_xor_sync(0xffffffffu, ss, o);
    }
    float mean = s * 0.00390625f;
    float var = ss * 0.00390625f - mean * mean;
    float rstd = rsqrtf(var + 1e-5f);
    float4 g0 = ((const float4*)gg)[lane], g1 = ((const float4*)gg)[lane + 32];
    float4 b0 = ((const float4*)bb)[lane], b1 = ((const float4*)bb)[lane + 32];
    uint2 o0, o1;
    o0.x = bf2u((v0.x - mean) * rstd * g0.x + b0.x, (v0.y - mean) * rstd * g0.y + b0.y);
    o0.y = bf2u((v0.z - mean) * rstd * g0.z + b0.z, (v0.w - mean) * rstd * g0.w + b0.w);
    o1.x = bf2u((v1.x - mean) * rstd * g1.x + b1.x, (v1.y - mean) * rstd * g1.y + b1.y);
    o1.y = bf2u((v1.z - mean) * rstd * g1.z + b1.z, (v1.w - mean) * rstd * g1.w + b1.w);
    uint2* yr = (uint2*)(y + (size_t)tok * 256);
    yr[lane] = o0;
    yr[lane + 32] = o1;
}

// ---------------------------------------------------------------------------
// Fused weight transpose: 8 jobs, one launch. W[K,N] fp32 -> Wt[N,K] bf16.
// ---------------------------------------------------------------------------
struct TrJobs {
    const float* W[8];
    __nv_bfloat16* Wt[8];
    int K[8], N[8], blk0[8];
};

__global__ void smsa_transpose_all_kernel(TrJobs J) {
    __shared__ float t[32][33];
    int bid = blockIdx.x;
    int j = 0;
#pragma unroll
    for (int i = 1; i < 8; i++)
        if (bid >= J.blk0[i]) j = i;
    int rel = bid - J.blk0[j];
    int K = J.K[j], N = J.N[j];
    int nbx = N >> 5;
    int n0 = (rel % nbx) * 32, k0 = (rel / nbx) * 32;
    const float* W = J.W[j];
    __nv_bfloat16* Wt = J.Wt[j];
    int tx = threadIdx.x, ty = threadIdx.y;
#pragma unroll
    for (int i = 0; i < 32; i += 8)
        t[ty + i][tx] = W[(size_t)(k0 + ty + i) * N + n0 + tx];
    __syncthreads();
#pragma unroll
    for (int i = 0; i < 32; i += 8)
        Wt[(size_t)(n0 + ty + i) * K + k0 + tx] = __float2bfloat16(t[tx][ty + i]);
}

// ---------------------------------------------------------------------------
// Segmented bf16 HMMA GEMM, CTA tile 128x128, 256 threads, 3-stage cp.async,
// occupancy 2, ONE sync per K-chunk. CTAs with mb >= mb1 use segment-1 params
// (weights/bias/C/res, locally row-indexed).
// ---------------------------------------------------------------------------
__global__ __launch_bounds__(256, 2) void smsa_hgemm_kernel(
    const __nv_bfloat16* __restrict__ A, int lda,
    const __nv_bfloat16* __restrict__ Bt0, const __nv_bfloat16* __restrict__ Bt1,
    void* __restrict__ C0, void* __restrict__ C1, int ldc,
    const float* __restrict__ bias0, const float* __restrict__ bias1,
    const float* __restrict__ res0, const float* __restrict__ res1, int ldr,
    int K, int act, int outbf, int mb1) {
    extern __shared__ __align__(1024) char sm[];
    uint32_t sb = smem_u32(sm);
    const int tid = threadIdx.x;
    const int mb = blockIdx.y, nb = blockIdx.x;
    const int warp = tid >> 5, lane = tid & 31;
    const int wm = warp & 3, wn = warp >> 2;

    const int seg = (mb >= mb1);
    const __nv_bfloat16* Bt = seg ? Bt1 : Bt0;
    const float* bias = seg ? bias1 : bias0;
    const float* res = seg ? res1 : res0;
    void* Cm = seg ? C1 : C0;
    const int lrow0 = (seg ? (mb - mb1) : mb) * 128;   // local C/res row base

    const __nv_bfloat16* Ag = A + (size_t)(mb * 128) * lda;
    const __nv_bfloat16* Bg = Bt + (size_t)(nb * 128) * K;

    const int nch = K >> 6;
    auto copy_stage = [&](int c, int s) {
        uint32_t sbase = sb + (uint32_t)s * 32768u;
        const __nv_bfloat16* ga = Ag + c * 64;
        const __nv_bfloat16* gb = Bg + c * 64;
#pragma unroll
        for (int p = 0; p < 4; p++) {
            int u = p * 256 + tid;
            int row = u >> 3, c16 = u & 7;
            CP16(sbase + SWZ128((uint32_t)row * 128 + c16 * 16),
                 ga + (size_t)row * lda + c16 * 8);
        }
#pragma unroll
        for (int p = 0; p < 4; p++) {
            int u = p * 256 + tid;
            int row = u >> 3, c16 = u & 7;
            CP16(sbase + 16384u + SWZ128((uint32_t)row * 128 + c16 * 16),
                 gb + (size_t)row * K + c16 * 8);
        }
    };

    float acc[2][8][4];
#pragma unroll
    for (int mt = 0; mt < 2; mt++)
#pragma unroll
        for (int nt = 0; nt < 8; nt++)
#pragma unroll
            for (int q = 0; q < 4; q++) acc[mt][nt][q] = 0.0f;

    const int a_row = wm * 32 + (lane & 15);
    const int b_row = wn * 64 + (lane & 15);
    const int hi = lane >> 4;

    copy_stage(0, 0);
    CPCOMMIT();
    if (nch > 1) copy_stage(1, 1);
    CPCOMMIT();

    for (int c = 0; c < nch; c++) {
        CPWAIT1();
        __syncthreads();
        // buffer (c+2)%3 == (c-1)%3: freed because every thread finished
        // compute(c-1) before this barrier.
        if (c + 2 < nch) copy_stage(c + 2, (c + 2) % 3);
        CPCOMMIT();

        uint32_t abase = sb + (uint32_t)(c % 3) * 32768u;
        uint32_t bbase = abase + 16384u;
#pragma unroll
        for (int j = 0; j < 4; j++) {
            uint32_t af[2][4], bf[4][4];
            int ch = 2 * j + hi;
#pragma unroll
            for (int mt = 0; mt < 2; mt++) {
                uint32_t ad = abase + SWZ128((uint32_t)(a_row + mt * 16) * 128 + ch * 16);
                LDSM_X4(af[mt], ad);
            }
#pragma unroll
            for (int bt = 0; bt < 4; bt++) {
                uint32_t bd = bbase + SWZ128((uint32_t)(b_row + bt * 16) * 128 + ch * 16);
                LDSM_X4(bf[bt], bd);
            }
#pragma unroll
            for (int mt = 0; mt < 2; mt++)
#pragma unroll
                for (int nt = 0; nt < 8; nt++)
                    MMA16816(acc[mt][nt], af[mt],
                             bf[nt >> 1][nt & 1], bf[nt >> 1][(nt & 1) + 2]);
        }
    }

    int qrow = lane >> 2, qcol = (lane & 3) * 2;
#pragma unroll
    for (int mt = 0; mt < 2; mt++)
#pragma unroll
        for (int half = 0; half < 2; half++) {
            int row = lrow0 + wm * 32 + mt * 16 + qrow + half * 8;
#pragma unroll
            for (int nt = 0; nt < 8; nt++) {
                int col = nb * 128 + wn * 64 + nt * 8 + qcol;
                float v0 = acc[mt][nt][half * 2 + 0];
                float v1 = acc[mt][nt][half * 2 + 1];
                if (bias) {
                    float2 bv = *(const float2*)(bias + col);
                    v0 += bv.x; v1 += bv.y;
                }
                if (res) {
                    float2 rr = *(const float2*)(res + (size_t)row * ldr + col);
                    v0 += rr.x; v1 += rr.y;
                }
                if (act) { v0 = gelu_exact(v0); v1 = gelu_exact(v1); }
                if (outbf) {
                    *(uint32_t*)((__nv_bfloat16*)Cm + (size_t)row * ldc + col) =
                        bf2u(v0, v1);
                } else {
                    *(float2*)((float*)Cm + (size_t)row * ldc + col) =
                        make_float2(v0, v1);
                }
            }
        }
}

// ---------------------------------------------------------------------------
// Fused HMMA flash attention (unchanged math; windows cover merged rows)
// ---------------------------------------------------------------------------
__global__ __launch_bounds__(256) void smsa_fattn_kernel(
    const __nv_bfloat16* __restrict__ qkv, __nv_bfloat16* __restrict__ out) {
    extern __shared__ __align__(128) char smc[];
    uint32_t sbq = smem_u32(smc);
    const uint32_t Qs = sbq, Ks = sbq + 20480u, Vs = sbq + 40960u;
    int win = blockIdx.x >> 3, h = blockIdx.x & 7;
    int tid = threadIdx.x, lane = tid & 31, warp = tid >> 5;
    const __nv_bfloat16* base = qkv + (size_t)win * 256 * 768 + h * 32;

    {
        const uint4* qp = (const uint4*)(base + (size_t)tid * 768);
        const uint4* kp = (const uint4*)(base + (size_t)tid * 768 + 256);
        const uint4* vp = (const uint4*)(base + (size_t)tid * 768 + 512);
        uint32_t qd = Qs + tid * 80, kd = Ks + tid * 80, vd = Vs + tid * 80;
#pragma unroll
        for (int c = 0; c < 4; c++) {
            uint4 v;
            v = qp[c];
            asm volatile("st.shared.v4.b32 [%0], {%1,%2,%3,%4};"
                         :: "r"(qd + c * 16), "r"(v.x), "r"(v.y), "r"(v.z), "r"(v.w));
            v = kp[c];
            asm volatile("st.shared.v4.b32 [%0], {%1,%2,%3,%4};"
                         :: "r"(kd + c * 16), "r"(v.x), "r"(v.y), "r"(v.z), "r"(v.w));
            v = vp[c];
            asm volatile("st.shared.v4.b32 [%0], {%1,%2,%3,%4};"
                         :: "r"(vd + c * 16), "r"(v.x), "r"(v.y), "r"(v.z), "r"(v.w));
        }
    }
    __syncthreads();

    const int qb = warp * 32;
    uint32_t qf[2][2][4];
#pragma unroll
    for (int mt = 0; mt < 2; mt++)
#pragma unroll
        for (int kc = 0; kc < 2; kc++) {
            uint32_t ad = Qs + (uint32_t)(qb + mt * 16 + (lane & 15)) * 80
                          + (lane >> 4) * 16 + kc * 32;
            LDSM_X4(qf[mt][kc], ad);
        }

    float oacc[2][4][4];
#pragma unroll
    for (int mt = 0; mt < 2; mt++)
#pragma unroll
        for (int nt = 0; nt < 4; nt++)
#pragma unroll
            for (int q = 0; q < 4; q++) oacc[mt][nt][q] = 0.0f;
    float mrun[2][2] = {{-1e30f, -1e30f}, {-1e30f, -1e30f}};
    float lrun[2][2] = {{0.0f, 0.0f}, {0.0f, 0.0f}};
    const float C2 = 0.17677669529663687f * 1.4426950408889634f;

    for (int kb = 0; kb < 4; kb++) {
        float sacc[2][8][4];
#pragma unroll
        for (int mt = 0; mt < 2; mt++)
#pragma unroll
            for (int nt = 0; nt < 8; nt++)
#pragma unroll
                for (int q = 0; q < 4; q++) sacc[mt][nt][q] = 0.0f;

#pragma unroll
        for (int kc = 0; kc < 2; kc++) {
            uint32_t kf[4][4];
#pragma unroll
            for (int grp = 0; grp < 4; grp++) {
                uint32_t ad = Ks + (uint32_t)(kb * 64 + grp * 16 + (lane & 15)) * 80
                              + (lane >> 4) * 16 + kc * 32;
                LDSM_X4(kf[grp], ad);
            }
#pragma unroll
            for (int mt = 0; mt < 2; mt++)
#pragma unroll
                for (int nt = 0; nt < 8; nt++)
                    MMA16816(sacc[mt][nt], qf[mt][kc],
                             kf[nt >> 1][nt & 1], kf[nt >> 1][(nt & 1) + 2]);
        }

#pragma unroll
        for (int mt = 0; mt < 2; mt++)
#pragma unroll
            for (int hf = 0; hf < 2; hf++) {
                float mx = -1e30f;
#pragma unroll
                for (int nt = 0; nt < 8; nt++)
                    mx = fmaxf(mx, fmaxf(sacc[mt][nt][hf * 2], sacc[mt][nt][hf * 2 + 1]));
                mx = fmaxf(mx, __shfl_xor_sync(0xffffffffu, mx, 1));
                mx = fmaxf(mx, __shfl_xor_sync(0xffffffffu, mx, 2));
                float mold = mrun[mt][hf];
                float mnew = fmaxf(mold, mx);
                float corr = exp2f(C2 * (mold - mnew));
                mrun[mt][hf] = mnew;
                float sum = 0.0f;
#pragma unroll
                for (int nt = 0; nt < 8; nt++) {
                    float p0 = exp2f(C2 * (sacc[mt][nt][hf * 2] - mnew));
                    float p1 = exp2f(C2 * (sacc[mt][nt][hf * 2 + 1] - mnew));
                    sacc[mt][nt][hf * 2] = p0;
                    sacc[mt][nt][hf * 2 + 1] = p1;
                    sum += p0 + p1;
                }
                sum += __shfl_xor_sync(0xffffffffu, sum, 1);
                sum += __shfl_xor_sync(0xffffffffu, sum, 2);
                lrun[mt][hf] = lrun[mt][hf] * corr + sum;
#pragma unroll
                for (int nt = 0; nt < 4; nt++) {
                    oacc[mt][nt][hf * 2] *= corr;
                    oacc[mt][nt][hf * 2 + 1] *= corr;
                }
            }

#pragma unroll
        for (int kc4 = 0; kc4 < 4; kc4++) {
            uint32_t vf[2][4];
#pragma unroll
            for (int dg = 0; dg < 2; dg++) {
                uint32_t ad = Vs + (uint32_t)(kb * 64 + kc4 * 16 + (lane & 15)) * 80
                              + dg * 32 + (lane >> 4) * 16;
                LDSM_X4T(vf[dg], ad);
            }
#pragma unroll
            for (int mt = 0; mt < 2; mt++) {
                uint32_t a[4];
                a[0] = bf2u(sacc[mt][2 * kc4][0], sacc[mt][2 * kc4][1]);
                a[1] = bf2u(sacc[mt][2 * kc4][2], sacc[mt][2 * kc4][3]);
                a[2] = bf2u(sacc[mt][2 * kc4 + 1][0], sacc[mt][2 * kc4 + 1][1]);
                a[3] = bf2u(sacc[mt][2 * kc4 + 1][2], sacc[mt][2 * kc4 + 1][3]);
#pragma unroll
                for (int nt = 0; nt < 4; nt++)
                    MMA16816(oacc[mt][nt], a,
                             vf[nt >> 1][(nt & 1) * 2], vf[nt >> 1][(nt & 1) * 2 + 1]);
            }
        }
    }

#pragma unroll
    for (int mt = 0; mt < 2; mt++) {
        float inv0 = 1.0f / lrun[mt][0];
        float inv1 = 1.0f / lrun[mt][1];
        int row0 = win * 256 + qb + mt * 16 + (lane >> 2);
        int col = h * 32 + (lane & 3) * 2;
#pragma unroll
        for (int nt = 0; nt < 4; nt++) {
            *(uint32_t*)(out + (size_t)row0 * 256 + col + nt * 8) =
                bf2u(oacc[mt][nt][0] * inv0, oacc[mt][nt][1] * inv0);
            *(uint32_t*)(out + (size_t)(row0 + 8) * 256 + col + nt * 8) =
                bf2u(oacc[mt][nt][2] * inv1, oacc[mt][nt][3] * inv1);
        }
    }
}

// ---------------------------------------------------------------------------
// Cross-attention gather/scatter and 1->16 attention
// ---------------------------------------------------------------------------
__device__ __forceinline__ void decode_f(int f, int& fw, int& base_t,
                                         int& gwin, int& tt) {
    int b = f >> 10, h = (f >> 7) & 7, w = (f >> 4) & 7;
    int r1 = (f >> 2) & 3, r2 = f & 3;
    fw = (b * 8 + h) * 8 + w;
    base_t = r1 * 64 + r2 * 4;
    int gr = h * 4 + r1, gc = w * 4 + r2;
    gwin = b * 4 + (gr >> 4) * 2 + (gc >> 4);
    tt = (gr & 15) * 16 + (gc & 15);
}

__global__ void smsa_gather_g_kernel(const float* __restrict__ x1,
                                     float* __restrict__ g) {
    int f = blockIdx.x, c = threadIdx.x;
    int fw, base_t, gwin, tt;
    decode_f(f, fw, base_t, gwin, tt);
    g[(size_t)f * 256 + c] = x1[((size_t)gwin * 256 + tt) * 256 + c];
}

__global__ void smsa_scatter_g_kernel(const float* __restrict__ g,
                                      float* __restrict__ out1) {
    int f = blockIdx.x, c = threadIdx.x;
    int fw, base_t, gwin, tt;
    decode_f(f, fw, base_t, gwin, tt);
    out1[((size_t)gwin * 256 + tt) * 256 + c] = g[(size_t)f * 256 + c];
}

__global__ __launch_bounds__(256) void smsa_xattn_kernel(
    const __nv_bfloat16* __restrict__ Q, const __nv_bfloat16* __restrict__ KV,
    __nv_bfloat16* __restrict__ AO) {
    int f = blockIdx.x;
    int h = threadIdx.x >> 5;
    int d = threadIdx.x & 31;
    int fw, base_t, gwin, tt;
    decode_f(f, fw, base_t, gwin, tt);
    float qd = __bfloat162float(Q[(size_t)f * 256 + h * 32 + d]);
    const float sc = 0.17677669529663687f;
    float s[16];
#pragma unroll
    for (int j = 0; j < 16; j++) {
        int t = base_t + (j >> 2) * 16 + (j & 3);
        float kd = __bfloat162float(KV[((size_t)(fw * 256 + t)) * 512 + h * 32 + d]);
        float pr = qd * kd;
#pragma unroll
        for (int o = 16; o > 0; o >>= 1)
            pr += __shfl_xor_sync(0xffffffffu, pr, o);
        s[j] = pr * sc;
    }
    float m = s[0];
#pragma unroll
    for (int j = 1; j < 16; j++) m = fmaxf(m, s[j]);
    float l = 0.0f, p[16];
#pragma unroll
    for (int j = 0; j < 16; j++) {
        p[j] = __expf(s[j] - m);
        l += p[j];
    }
    float inv = 1.0f / l;
    float acc = 0.0f;
#pragma unroll
    for (int j = 0; j < 16; j++) {
        int t = base_t + (j >> 2) * 16 + (j & 3);
        acc = fmaf(p[j], __bfloat162float(
                        KV[((size_t)(fw * 256 + t)) * 512 + 256 + h * 32 + d]),
                   acc);
    }
    AO[(size_t)f * 256 + h * 32 + d] = __float2bfloat16(acc * inv);
}

// ---------------------------------------------------------------------------
// Host side
// ---------------------------------------------------------------------------
static void run_hgemm2(const __nv_bfloat16* A, int lda,
                       const __nv_bfloat16* Bt0, const __nv_bfloat16* Bt1,
                       void* C0, void* C1, int ldc,
                       const float* bias0, const float* bias1,
                       const float* res0, const float* res1, int ldr,
                       int M, int N, int K, int act, int outbf, int mb1) {
    dim3 grid(N / 128, M / 128);
    smsa_hgemm_kernel<<<grid, 256, GEMM_SMEM>>>(A, lda, Bt0, Bt1, C0, C1, ldc,
                                                bias0, bias1, res0, res1, ldr,
                                                K, act, outbf, mb1);
}

static void run_hgemm(const __nv_bfloat16* A, int lda, const __nv_bfloat16* Bt,
                      void* Cm, int ldc, const float* bias,
                      const float* res, int ldr, int M, int N, int K,
                      int act, int outbf) {
    run_hgemm2(A, lda, Bt, Bt, Cm, Cm, ldc, bias, bias, res, res, ldr,
               M, N, K, act, outbf, 1 << 30);
}

static void run_ln2(const float* x, __nv_bfloat16* y,
                    const float* g0, const float* b0,
                    const float* g1, const float* b1, int ntok, int bnd) {
    smsa_ln_kernel<<<ntok / 8, 256>>>(x, y, g0, b0, g1, b1, bnd);
}

extern "C" void kernel_launch(void* const* d_in, const int* in_sizes, int n_in,
                              void* d_out, int out_size) {
    const float* scale0 = (const float*)d_in[0];
    const float* scale1 = (const float*)d_in[1];
    const float* pe_w1 = (const float*)d_in[2];
    const float* pe_b1 = (const float*)d_in[3];
    const float* pe_w2 = (const float*)d_in[4];
    const float* ln1_g = (const float*)d_in[5];
    const float* ln1_b = (const float*)d_in[6];
    const float* wqkv = (const float*)d_in[7];
    const float* bqkv = (const float*)d_in[8];
    const float* wo = (const float*)d_in[9];
    const float* bo = (const float*)d_in[10];
    const float* ln2_g = (const float*)d_in[11];
    const float* ln2_b = (const float*)d_in[12];
    const float* mw1 = (const float*)d_in[13];
    const float* mb1 = (const float*)d_in[14];
    const float* mw2 = (const float*)d_in[15];
    const float* mb2 = (const float*)d_in[16];
    float* out = (float*)d_out;
    float* out0 = out;
    float* out1 = out + (size_t)65536 * 256;

    float *X, *PE, *G;
    __nv_bfloat16 *Hb, *QKVb, *Tb, *WT;
    cudaGetSymbolAddress((void**)&X, g_X);
    cudaGetSymbolAddress((void**)&PE, g_PE);
    cudaGetSymbolAddress((void**)&G, g_G);
    cudaGetSymbolAddress((void**)&Hb, g_Hb);
    cudaGetSymbolAddress((void**)&QKVb, g_QKVb);
    cudaGetSymbolAddress((void**)&Tb, g_Tb);
    cudaGetSymbolAddress((void**)&WT, g_WT);
    float* X1 = X + (size_t)65536 * 256;

    cudaFuncSetAttribute(smsa_fattn_kernel,
                         cudaFuncAttributeMaxDynamicSharedMemorySize, ATTN_SMEM);
    cudaFuncSetAttribute(smsa_hgemm_kernel,
                         cudaFuncAttributeMaxDynamicSharedMemorySize, GEMM_SMEM);

    const __nv_bfloat16 *wqkvT0 = WT + 0, *woT0 = WT + 196608;
    const __nv_bfloat16 *w1T0 = WT + 262144, *w2T0 = WT + 524288;
    const __nv_bfloat16 *wqkvT1 = WT + 786432, *woT1 = WT + 983040;
    const __nv_bfloat16 *w1T1 = WT + 1048576, *w2T1 = WT + 1310720;
    const float *ln1g0 = ln1_g, *ln1b0 = ln1_b;
    const float *ln2g0 = ln2_g, *ln2b0 = ln2_b;
    const float *ln1g1 = ln1_g + 256, *ln1b1 = ln1_b + 256;
    const float *ln2g1 = ln2_g + 256, *ln2b1 = ln2_b + 256;

    // 0) weight transposes, one launch
    {
        TrJobs J;
        const float* Ws[8] = {wqkv, wqkv + 196608, wo, wo + 65536,
                              mw1, mw1 + 262144, mw2, mw2 + 262144};
        __nv_bfloat16* Wts[8] = {WT + 0, WT + 786432, WT + 196608, WT + 983040,
                                 WT + 262144, WT + 1048576, WT + 524288, WT + 1310720};
        int Ks[8] = {256, 256, 256, 256, 256, 256, 1024, 1024};
        int Ns[8] = {768, 768, 256, 256, 1024, 1024, 256, 256};
        int b0 = 0;
        for (int i = 0; i < 8; i++) {
            J.W[i] = Ws[i]; J.Wt[i] = Wts[i]; J.K[i] = Ks[i]; J.N[i] = Ns[i];
            J.blk0[i] = b0;
            b0 += (Ks[i] / 32) * (Ns[i] / 32);
        }
        smsa_transpose_all_kernel<<<b0, dim3(32, 8)>>>(J);
    }

    // 1) position embeddings; scale0 add+LN1 fused; scale1 add plain
    smsa_posemb_kernel<<<dim3(256, 2), 256>>>(pe_w1, pe_b1, pe_w2, PE);
    smsa_add_pe_ln_kernel<<<8192, 256>>>(scale0, PE, X, Hb, ln1g0, ln1b0);
    smsa_add_pe_kernel<<<1024, 256>>>(scale1, PE + 65536, X1);

    // 2) pool + LN1(scale1) -> X1, Hb rows 65536+
    smsa_pool_ln_kernel<<<4096, 256>>>(X, X1, Hb + (size_t)65536 * 256,
                                       ln1g1, ln1b1);

    // 3) MERGED sattn chain over 69632 rows (seg0 = scale0, seg1 = scale1)
    run_hgemm2(Hb, 256, wqkvT0, wqkvT1,
               QKVb, QKVb + (size_t)65536 * 768, 768,
               bqkv, bqkv + 768, nullptr, nullptr, 0,
               NTOKA, 768, 256, 0, 1, MB1T);
    smsa_fattn_kernel<<<(NTOKA / 256) * 8, 256, ATTN_SMEM>>>(QKVb, Hb);
    run_hgemm2(Hb, 256, woT0, woT1,
               X, X1, 256,
               bo, bo + 256, X, X1, 256,
               NTOKA, 256, 256, 0, 0, MB1T);
    run_ln2(X, Hb, ln2g0, ln2b0, ln2g1, ln2b1, NTOKA, NTOK0);
    run_hgemm2(Hb, 256, w1T0, w1T1,
               Tb, Tb + (size_t)65536 * 1024, 1024,
               mb1, mb1 + 1024, nullptr, nullptr, 0,
               NTOKA, 1024, 256, 1, 1, MB1T);
    run_hgemm2(Tb, 1024, w2T0, w2T1,
               out0, X1, 256,
               mb2, mb2 + 256, X, X1, 256,
               NTOKA, 256, 1024, 0, 0, MB1T);

    // cross kn LN: out0 -> Hb (scale-1 ln1 params)
    run_ln2(out0, Hb, ln1g1, ln1b1, ln1g1, ln1b1, NTOK0, NTOK0);

    // 4) cross-attention K|V (rows of o0)
    run_hgemm(Hb, 256, wqkvT1 + 256 * 256, QKVb, 512, bqkv + 768 + 256,
              nullptr, 0, NTOK0, 512, 256, 0, 1);
    smsa_gather_g_kernel<<<4096, 256>>>(X1, G);

    __nv_bfloat16* S0b = Tb;
    __nv_bfloat16* Sqb = Tb + (size_t)4096 * 256;
    __nv_bfloat16* AOb = Tb + (size_t)2 * 4096 * 256;
    __nv_bfloat16* Sgb = Tb + (size_t)3 * 4096 * 256;
    __nv_bfloat16* Thb = Tb + (size_t)4 * 4096 * 256;

    run_ln2(G, S0b, ln1g1, ln1b1, ln1g1, ln1b1, NTOK1, NTOK1);
    run_hgemm(S0b, 256, wqkvT1, Sqb, 256, bqkv + 768, nullptr, 0,
              NTOK1, 256, 256, 0, 1);
    smsa_xattn_kernel<<<4096, 256>>>(Sqb, QKVb, AOb);
    run_hgemm(AOb, 256, woT1, G, 256, bo + 256, G, 256, NTOK1, 256, 256, 0, 0);
    run_ln2(G, Sgb, ln2g1, ln2b1, ln2g1, ln2b1, NTOK1, NTOK1);
    run_hgemm(Sgb, 256, w1T1, Thb, 1024, mb1 + 1024, nullptr, 0,
              NTOK1, 1024, 256, 1, 1);
    run_hgemm(Thb, 1024, w2T1, G, 256, mb2 + 256, G, 256, NTOK1, 256, 1024, 0, 0);

    // 5) scatter g back to o1 window layout
    smsa_scatter_g_kernel<<<4096, 256>>>(G, out1);
}

// round 11
// speedup vs baseline: 5.3369x; 1.0013x over previous
#include <cuda_runtime.h>
#include <cuda_bf16.h>
#include <math.h>
#include <stdint.h>

// ---------------------------------------------------------------------------
// StackMSA round 11: GEMM warp tile 64x64 (4 warps, 128 thr, -33% LDSM),
// occ-2, one sync/chunk; tail packing (gather+LN fused, Sq folded into the
// cross-KV GEMM launch). Merged scale0+scale1 chain as round 10.
// ---------------------------------------------------------------------------

#define NTOK0 65536
#define NTOK1 4096
#define NTOKA 69632
#define MB1T 512
#define ATTN_SMEM 61440
#define GEMM_SMEM 98304     // 3 stages x (16KB A + 16KB B)

__device__ float g_X[69632 * 256];
__device__ float g_PE[2 * 256 * 256];
__device__ float g_G[4096 * 256];
__device__ __nv_bfloat16 g_Hb[69632 * 256];
__device__ __nv_bfloat16 g_QKVb[69632 * 768];
__device__ __nv_bfloat16 g_Tb[69632 * 1024];
__device__ __nv_bfloat16 g_WT[1572864];

__device__ __forceinline__ float gelu_exact(float x) {
    return 0.5f * x * (1.0f + erff(x * 0.70710678118654752f));
}

__device__ __forceinline__ uint32_t smem_u32(const void* p) {
    uint32_t a;
    asm("{ .reg .u64 t; cvta.to.shared.u64 t, %1; cvt.u32.u64 %0, t; }"
        : "=r"(a) : "l"(p));
    return a;
}

#define SWZ128(o) ((o) ^ (((o) >> 3) & 0x70))
#define CP16(dst, src) \
    asm volatile("cp.async.cg.shared.global [%0], [%1], 16;" :: "r"(dst), "l"(src))
#define CPCOMMIT() asm volatile("cp.async.commit_group;" ::: "memory")
#define CPWAIT1() asm volatile("cp.async.wait_group 1;" ::: "memory")

#define LDSM_X4(r, addr) \
    asm volatile("ldmatrix.sync.aligned.m8n8.x4.shared.b16 {%0,%1,%2,%3}, [%4];" \
                 : "=r"((r)[0]), "=r"((r)[1]), "=r"((r)[2]), "=r"((r)[3]) : "r"(addr))
#define LDSM_X4T(r, addr) \
    asm volatile("ldmatrix.sync.aligned.m8n8.x4.trans.shared.b16 {%0,%1,%2,%3}, [%4];" \
                 : "=r"((r)[0]), "=r"((r)[1]), "=r"((r)[2]), "=r"((r)[3]) : "r"(addr))
#define MMA16816(d, a, b0, b1) \
    asm volatile("mma.sync.aligned.m16n8k16.row.col.f32.bf16.bf16.f32 " \
                 "{%0,%1,%2,%3}, {%4,%5,%6,%7}, {%8,%9}, {%0,%1,%2,%3};" \
                 : "+f"((d)[0]), "+f"((d)[1]), "+f"((d)[2]), "+f"((d)[3]) \
                 : "r"((a)[0]), "r"((a)[1]), "r"((a)[2]), "r"((a)[3]), \
                   "r"(b0), "r"(b1))

__device__ __forceinline__ uint32_t bf2u(float x, float y) {
    __nv_bfloat162 h = __float22bfloat162_rn(make_float2(x, y));
    return *(uint32_t*)&h;
}

// ---------------------------------------------------------------------------
__global__ void smsa_posemb_kernel(const float* __restrict__ w1,
                                   const float* __restrict__ b1,
                                   const float* __restrict__ w2,
                                   float* __restrict__ pe) {
    int t = blockIdx.x, s = blockIdx.y, tid = threadIdx.x;
    __shared__ float hid[512];
    float c0 = (float)((t >> 4) - 8) * 0.125f;
    float c1 = (float)((t & 15) - 8) * 0.125f;
    const float* W1 = w1 + s * 1024;
    const float* B1 = b1 + s * 512;
    for (int k = tid; k < 512; k += 256)
        hid[k] = fmaxf(fmaf(c0, W1[k], fmaf(c1, W1[512 + k], B1[k])), 0.0f);
    __syncthreads();
    const float* W2 = w2 + s * 512 * 256;
    float acc = 0.0f;
#pragma unroll 8
    for (int k = 0; k < 512; k++) acc = fmaf(hid[k], W2[k * 256 + tid], acc);
    pe[s * 65536 + t * 256 + tid] = acc;
}

__global__ void smsa_add_pe_kernel(const float* __restrict__ x,
                                   const float* __restrict__ pe,
                                   float* __restrict__ y) {
    size_t i = (size_t)blockIdx.x * 256 + threadIdx.x;
    float4 a = ((const float4*)x)[i];
    float4 p = ((const float4*)pe)[i & 16383];
    float4 r;
    r.x = a.x + p.x; r.y = a.y + p.y; r.z = a.z + p.z; r.w = a.w + p.w;
    ((float4*)y)[i] = r;
}

__global__ __launch_bounds__(256) void smsa_add_pe_ln_kernel(
    const float* __restrict__ x, const float* __restrict__ pe,
    float* __restrict__ y, __nv_bfloat16* __restrict__ hb,
    const float* __restrict__ gg, const float* __restrict__ bb) {
    int tok = blockIdx.x * 8 + (threadIdx.x >> 5);
    int lane = threadIdx.x & 31;
    const float4* xr = (const float4*)(x + (size_t)tok * 256);
    const float4* pr = (const float4*)(pe + (size_t)(tok & 255) * 256);
    float4 v0 = xr[lane], v1 = xr[lane + 32];
    float4 p0 = pr[lane], p1 = pr[lane + 32];
    v0.x += p0.x; v0.y += p0.y; v0.z += p0.z; v0.w += p0.w;
    v1.x += p1.x; v1.y += p1.y; v1.z += p1.z; v1.w += p1.w;
    float4* yr = (float4*)(y + (size_t)tok * 256);
    yr[lane] = v0;
    yr[lane + 32] = v1;
    float s = v0.x + v0.y + v0.z + v0.w + v1.x + v1.y + v1.z + v1.w;
    float ss = v0.x * v0.x + v0.y * v0.y + v0.z * v0.z + v0.w * v0.w +
               v1.x * v1.x + v1.y * v1.y + v1.z * v1.z + v1.w * v1.w;
#pragma unroll
    for (int o = 16; o > 0; o >>= 1) {
        s += __shfl_xor_sync(0xffffffffu, s, o);
        ss += __shfl_xor_sync(0xffffffffu, ss, o);
    }
    float mean = s * 0.00390625f;
    float var = ss * 0.00390625f - mean * mean;
    float rstd = rsqrtf(var + 1e-5f);
    float4 g0 = ((const float4*)gg)[lane], g1 = ((const float4*)gg)[lane + 32];
    float4 b0 = ((const float4*)bb)[lane], b1 = ((const float4*)bb)[lane + 32];
    uint2 o0, o1;
    o0.x = bf2u((v0.x - mean) * rstd * g0.x + b0.x, (v0.y - mean) * rstd * g0.y + b0.y);
    o0.y = bf2u((v0.z - mean) * rstd * g0.z + b0.z, (v0.w - mean) * rstd * g0.w + b0.w);
    o1.x = bf2u((v1.x - mean) * rstd * g1.x + b1.x, (v1.y - mean) * rstd * g1.y + b1.y);
    o1.y = bf2u((v1.z - mean) * rstd * g1.z + b1.z, (v1.w - mean) * rstd * g1.w + b1.w);
    uint2* hr = (uint2*)(hb + (size_t)tok * 256);
    hr[lane] = o0;
    hr[lane + 32] = o1;
}

__global__ __launch_bounds__(256) void smsa_pool_ln_kernel(
    const float* __restrict__ x0, float* __restrict__ x1,
    __nv_bfloat16* __restrict__ hb1,
    const float* __restrict__ gg, const float* __restrict__ bb) {
    __shared__ float red[16];
    int gid = blockIdx.x, c = threadIdx.x;
    int b = gid >> 10, gr = (gid >> 5) & 31, gc = gid & 31;
    int h = gr >> 2, r1 = gr & 3, w = gc >> 2, r2 = gc & 3;
    int fw = (b * 8 + h) * 8 + w;
    const float* base = x0 + ((size_t)fw * 256 + r1 * 64 + r2 * 4) * 256 + c;
    float m = -1e30f;
#pragma unroll
    for (int p1 = 0; p1 < 4; p1++)
#pragma unroll
        for (int p2 = 0; p2 < 4; p2++)
            m = fmaxf(m, base[(p1 * 16 + p2) * 256]);
    int gwin = b * 4 + (gr >> 4) * 2 + (gc >> 4);
    int tt = (gr & 15) * 16 + (gc & 15);
    size_t idx = ((size_t)gwin * 256 + tt) * 256 + c;
    float v = x1[idx] + m;
    x1[idx] = v;
    float s = v, q = v * v;
#pragma unroll
    for (int o = 16; o > 0; o >>= 1) {
        s += __shfl_xor_sync(0xffffffffu, s, o);
        q += __shfl_xor_sync(0xffffffffu, q, o);
    }
    int warp = c >> 5, lane = c & 31;
    if (lane == 0) { red[warp] = s; red[warp + 8] = q; }
    __syncthreads();
    float S = 0.0f, Q = 0.0f;
#pragma unroll
    for (int wi = 0; wi < 8; wi++) { S += red[wi]; Q += red[wi + 8]; }
    float mean = S * 0.00390625f;
    float var = Q * 0.00390625f - mean * mean;
    float rstd = rsqrtf(var + 1e-5f);
    hb1[idx] = __float2bfloat16((v - mean) * rstd * gg[c] + bb[c]);
}

// LayerNorm, segmented params
__global__ __launch_bounds__(256) void smsa_ln_kernel(
    const float* __restrict__ x, __nv_bfloat16* __restrict__ y,
    const float* __restrict__ gg0, const float* __restrict__ bb0,
    const float* __restrict__ gg1, const float* __restrict__ bb1, int bnd) {
    int tok = blockIdx.x * 8 + (threadIdx.x >> 5);
    int lane = threadIdx.x & 31;
    const float* gg = tok < bnd ? gg0 : gg1;
    const float* bb = tok < bnd ? bb0 : bb1;
    const float4* row = (const float4*)(x + (size_t)tok * 256);
    float4 v0 = row[lane], v1 = row[lane + 32];
    float s = v0.x + v0.y + v0.z + v0.w + v1.x + v1.y + v1.z + v1.w;
    float ss = v0.x * v0.x + v0.y * v0.y + v0.z * v0.z + v0.w * v0.w +
               v1.x * v1.x + v1.y * v1.y + v1.z * v1.z + v1.w * v1.w;
#pragma unroll
    for (int o = 16; o > 0; o >>= 1) {
        s += __shfl_xor_sync(0xffffffffu, s, o);
        ss += __shfl_xor_sync(0xffffffffu, ss, o);
    }
    float mean = s * 0.00390625f;
    float var = ss * 0.00390625f - mean * mean;
    float rstd = rsqrtf(var + 1e-5f);
    float4 g0 = ((const float4*)gg)[lane], g1 = ((const float4*)gg)[lane + 32];
    float4 b0 = ((const float4*)bb)[lane], b1 = ((const float4*)bb)[lane + 32];
    uint2 o0, o1;
    o0.x = bf2u((v0.x - mean) * rstd * g0.x + b0.x, (v0.y - mean) * rstd * g0.y + b0.y);
    o0.y = bf2u((v0.z - mean) * rstd * g0.z + b0.z, (v0.w - mean) * rstd * g0.w + b0.w);
    o1.x = bf2u((v1.x - mean) * rstd * g1.x + b1.x, (v1.y - mean) * rstd * g1.y + b1.y);
    o1.y = bf2u((v1.z - mean) * rstd * g1.z + b1.z, (v1.w - mean) * rstd * g1.w + b1.w);
    uint2* yr = (uint2*)(y + (size_t)tok * 256);
    yr[lane] = o0;
    yr[lane + 32] = o1;
}

// fused gather + LN: g[f] = x1[map(f)]; hbo[f] = LN(g[f]) bf16 (warp/token)
__global__ __launch_bounds__(256) void smsa_gather_ln_kernel(
    const float* __restrict__ x1, float* __restrict__ g,
    __nv_bfloat16* __restrict__ hbo,
    const float* __restrict__ gg, const float* __restrict__ bb) {
    int f = blockIdx.x * 8 + (threadIdx.x >> 5);
    int lane = threadIdx.x & 31;
    int b = f >> 10, h = (f >> 7) & 7, w = (f >> 4) & 7;
    int r1 = (f >> 2) & 3, r2 = f & 3;
    int gr = h * 4 + r1, gc = w * 4 + r2;
    int gwin = b * 4 + (gr >> 4) * 2 + (gc >> 4);
    int tt = (gr & 15) * 16 + (gc & 15);
    const float4* row = (const float4*)(x1 + ((size_t)gwin * 256 + tt) * 256);
    float4 v0 = row[lane], v1 = row[lane + 32];
    float4* grow = (float4*)(g + (size_t)f * 256);
    grow[lane] = v0;
    grow[lane + 32] = v1;
    float s = v0.x + v0.y + v0.z + v0.w + v1.x + v1.y + v1.z + v1.w;
    float ss = v0.x * v0.x + v0.y * v0.y + v0.z * v0.z + v0.w * v0.w +
               v1.x * v1.x + v1.y * v1.y + v1.z * v1.z + v1.w * v1.w;
#pragma unroll
    for (int o = 16; o > 0; o >>= 1) {
        s += __shfl_xor_sync(0xffffffffu, s, o);
        ss += __shfl_xor_sync(0xffffffffu, ss, o);
    }
    float mean = s * 0.00390625f;
    float var = ss * 0.00390625f - mean * mean;
    float rstd = rsqrtf(var + 1e-5f);
    float4 g0 = ((const float4*)gg)[lane], g1 = ((const float4*)gg)[lane + 32];
    float4 b0 = ((const float4*)bb)[lane], b1 = ((const float4*)bb)[lane + 32];
    uint2 o0, o1;
    o0.x = bf2u((v0.x - mean) * rstd * g0.x + b0.x, (v0.y - mean) * rstd * g0.y + b0.y);
    o0.y = bf2u((v0.z - mean) * rstd * g0.z + b0.z, (v0.w - mean) * rstd * g0.w + b0.w);
    o1.x = bf2u((v1.x - mean) * rstd * g1.x + b1.x, (v1.y - mean) * rstd * g1.y + b1.y);
    o1.y = bf2u((v1.z - mean) * rstd * g1.z + b1.z, (v1.w - mean) * rstd * g1.w + b1.w);
    uint2* hr = (uint2*)(hbo + (size_t)f * 256);
    hr[lane] = o0;
    hr[lane + 32] = o1;
}

// ---------------------------------------------------------------------------
struct TrJobs {
    const float* W[8];
    __nv_bfloat16* Wt[8];
    int K[8], N[8], blk0[8];
};

__global__ void smsa_transpose_all_kernel(TrJobs J) {
    __shared__ float t[32][33];
    int bid = blockIdx.x;
    int j = 0;
#pragma unroll
    for (int i = 1; i < 8; i++)
        if (bid >= J.blk0[i]) j = i;
    int rel = bid - J.blk0[j];
    int K = J.K[j], N = J.N[j];
    int nbx = N >> 5;
    int n0 = (rel % nbx) * 32, k0 = (rel / nbx) * 32;
    const float* W = J.W[j];
    __nv_bfloat16* Wt = J.Wt[j];
    int tx = threadIdx.x, ty = threadIdx.y;
#pragma unroll
    for (int i = 0; i < 32; i += 8)
        t[ty + i][tx] = W[(size_t)(k0 + ty + i) * N + n0 + tx];
    __syncthreads();
#pragma unroll
    for (int i = 0; i < 32; i += 8)
        Wt[(size_t)(n0 + ty + i) * K + k0 + tx] = __float2bfloat16(t[tx][ty + i]);
}

// ---------------------------------------------------------------------------
// Segmented bf16 HMMA GEMM: CTA tile 128x128, 128 threads (4 warps 2m x 2n,
// warp tile 64x64), 3-stage cp.async, occ 2, one sync per chunk.
// Segment 1 (mb >= mb1): own Bt/bias/C/ldc; CTAs with nb >= nbmax1 exit.
// ---------------------------------------------------------------------------
__global__ __launch_bounds__(128, 2) void smsa_hgemm_kernel(
    const __nv_bfloat16* __restrict__ A, int lda,
    const __nv_bfloat16* __restrict__ Bt0, const __nv_bfloat16* __restrict__ Bt1,
    void* __restrict__ C0, void* __restrict__ C1, int ldc0, int ldc1,
    const float* __restrict__ bias0, const float* __restrict__ bias1,
    const float* __restrict__ res0, const float* __restrict__ res1, int ldr,
    int K, int act, int outbf, int mb1, int nbmax1) {
    extern __shared__ __align__(1024) char sm[];
    uint32_t sb = smem_u32(sm);
    const int tid = threadIdx.x;
    const int mb = blockIdx.y, nb = blockIdx.x;
    const int warp = tid >> 5, lane = tid & 31;
    const int wm = warp & 1, wn = warp >> 1;

    const int seg = (mb >= mb1);
    if (seg && nb >= nbmax1) return;
    const __nv_bfloat16* Bt = seg ? Bt1 : Bt0;
    const float* bias = seg ? bias1 : bias0;
    const float* res = seg ? res1 : res0;
    void* Cm = seg ? C1 : C0;
    const int ldc = seg ? ldc1 : ldc0;
    const int lrow0 = (seg ? (mb - mb1) : mb) * 128;

    const __nv_bfloat16* Ag = A + (size_t)(mb * 128) * lda;
    const __nv_bfloat16* Bg = Bt + (size_t)(nb * 128) * K;

    const int nch = K >> 6;
    auto copy_stage = [&](int c, int s) {
        uint32_t sbase = sb + (uint32_t)s * 32768u;
        const __nv_bfloat16* ga = Ag + c * 64;
        const __nv_bfloat16* gb = Bg + c * 64;
#pragma unroll
        for (int p = 0; p < 8; p++) {
            int u = p * 128 + tid;
            int row = u >> 3, c16 = u & 7;
            CP16(sbase + SWZ128((uint32_t)row * 128 + c16 * 16),
                 ga + (size_t)row * lda + c16 * 8);
        }
#pragma unroll
        for (int p = 0; p < 8; p++) {
            int u = p * 128 + tid;
            int row = u >> 3, c16 = u & 7;
            CP16(sbase + 16384u + SWZ128((uint32_t)row * 128 + c16 * 16),
                 gb + (size_t)row * K + c16 * 8);
        }
    };

    float acc[4][8][4];
#pragma unroll
    for (int mt = 0; mt < 4; mt++)
#pragma unroll
        for (int nt = 0; nt < 8; nt++)
#pragma unroll
            for (int q = 0; q < 4; q++) acc[mt][nt][q] = 0.0f;

    const int a_row = wm * 64 + (lane & 15);
    const int b_row = wn * 64 + (lane & 15);
    const int hi = lane >> 4;

    copy_stage(0, 0);
    CPCOMMIT();
    if (nch > 1) copy_stage(1, 1);
    CPCOMMIT();

    for (int c = 0; c < nch; c++) {
        CPWAIT1();
        __syncthreads();
        if (c + 2 < nch) copy_stage(c + 2, (c + 2) % 3);
        CPCOMMIT();

        uint32_t abase = sb + (uint32_t)(c % 3) * 32768u;
        uint32_t bbase = abase + 16384u;
#pragma unroll
        for (int j = 0; j < 4; j++) {
            uint32_t af[4][4], bf[4][4];
            int ch = 2 * j + hi;
#pragma unroll
            for (int mt = 0; mt < 4; mt++) {
                uint32_t ad = abase + SWZ128((uint32_t)(a_row + mt * 16) * 128 + ch * 16);
                LDSM_X4(af[mt], ad);
            }
#pragma unroll
            for (int bt = 0; bt < 4; bt++) {
                uint32_t bd = bbase + SWZ128((uint32_t)(b_row + bt * 16) * 128 + ch * 16);
                LDSM_X4(bf[bt], bd);
            }
#pragma unroll
            for (int mt = 0; mt < 4; mt++)
#pragma unroll
                for (int nt = 0; nt < 8; nt++)
                    MMA16816(acc[mt][nt], af[mt],
                             bf[nt >> 1][nt & 1], bf[nt >> 1][(nt & 1) + 2]);
        }
    }

    int qrow = lane >> 2, qcol = (lane & 3) * 2;
#pragma unroll
    for (int mt = 0; mt < 4; mt++)
#pragma unroll
        for (int half = 0; half < 2; half++) {
            int row = lrow0 + wm * 64 + mt * 16 + qrow + half * 8;
#pragma unroll
            for (int nt = 0; nt < 8; nt++) {
                int col = nb * 128 + wn * 64 + nt * 8 + qcol;
                float v0 = acc[mt][nt][half * 2 + 0];
                float v1 = acc[mt][nt][half * 2 + 1];
                if (bias) {
                    float2 bv = *(const float2*)(bias + col);
                    v0 += bv.x; v1 += bv.y;
                }
                if (res) {
                    float2 rr = *(const float2*)(res + (size_t)row * ldr + col);
                    v0 += rr.x; v1 += rr.y;
                }
                if (act) { v0 = gelu_exact(v0); v1 = gelu_exact(v1); }
                if (outbf) {
                    *(uint32_t*)((__nv_bfloat16*)Cm + (size_t)row * ldc + col) =
                        bf2u(v0, v1);
                } else {
                    *(float2*)((float*)Cm + (size_t)row * ldc + col) =
                        make_float2(v0, v1);
                }
            }
        }
}

// ---------------------------------------------------------------------------
// Fused HMMA flash attention (unchanged from round 7)
// ---------------------------------------------------------------------------
__global__ __launch_bounds__(256) void smsa_fattn_kernel(
    const __nv_bfloat16* __restrict__ qkv, __nv_bfloat16* __restrict__ out) {
    extern __shared__ __align__(128) char smc[];
    uint32_t sbq = smem_u32(smc);
    const uint32_t Qs = sbq, Ks = sbq + 20480u, Vs = sbq + 40960u;
    int win = blockIdx.x >> 3, h = blockIdx.x & 7;
    int tid = threadIdx.x, lane = tid & 31, warp = tid >> 5;
    const __nv_bfloat16* base = qkv + (size_t)win * 256 * 768 + h * 32;

    {
        const uint4* qp = (const uint4*)(base + (size_t)tid * 768);
        const uint4* kp = (const uint4*)(base + (size_t)tid * 768 + 256);
        const uint4* vp = (const uint4*)(base + (size_t)tid * 768 + 512);
        uint32_t qd = Qs + tid * 80, kd = Ks + tid * 80, vd = Vs + tid * 80;
#pragma unroll
        for (int c = 0; c < 4; c++) {
            uint4 v;
            v = qp[c];
            asm volatile("st.shared.v4.b32 [%0], {%1,%2,%3,%4};"
                         :: "r"(qd + c * 16), "r"(v.x), "r"(v.y), "r"(v.z), "r"(v.w));
            v = kp[c];
            asm volatile("st.shared.v4.b32 [%0], {%1,%2,%3,%4};"
                         :: "r"(kd + c * 16), "r"(v.x), "r"(v.y), "r"(v.z), "r"(v.w));
            v = vp[c];
            asm volatile("st.shared.v4.b32 [%0], {%1,%2,%3,%4};"
                         :: "r"(vd + c * 16), "r"(v.x), "r"(v.y), "r"(v.z), "r"(v.w));
        }
    }
    __syncthreads();

    const int qb = warp * 32;
    uint32_t qf[2][2][4];
#pragma unroll
    for (int mt = 0; mt < 2; mt++)
#pragma unroll
        for (int kc = 0; kc < 2; kc++) {
            uint32_t ad = Qs + (uint32_t)(qb + mt * 16 + (lane & 15)) * 80
                          + (lane >> 4) * 16 + kc * 32;
            LDSM_X4(qf[mt][kc], ad);
        }

    float oacc[2][4][4];
#pragma unroll
    for (int mt = 0; mt < 2; mt++)
#pragma unroll
        for (int nt = 0; nt < 4; nt++)
#pragma unroll
            for (int q = 0; q < 4; q++) oacc[mt][nt][q] = 0.0f;
    float mrun[2][2] = {{-1e30f, -1e30f}, {-1e30f, -1e30f}};
    float lrun[2][2] = {{0.0f, 0.0f}, {0.0f, 0.0f}};
    const float C2 = 0.17677669529663687f * 1.4426950408889634f;

    for (int kb = 0; kb < 4; kb++) {
        float sacc[2][8][4];
#pragma unroll
        for (int mt = 0; mt < 2; mt++)
#pragma unroll
            for (int nt = 0; nt < 8; nt++)
#pragma unroll
                for (int q = 0; q < 4; q++) sacc[mt][nt][q] = 0.0f;

#pragma unroll
        for (int kc = 0; kc < 2; kc++) {
            uint32_t kf[4][4];
#pragma unroll
            for (int grp = 0; grp < 4; grp++) {
                uint32_t ad = Ks + (uint32_t)(kb * 64 + grp * 16 + (lane & 15)) * 80
                              + (lane >> 4) * 16 + kc * 32;
                LDSM_X4(kf[grp], ad);
            }
#pragma unroll
            for (int mt = 0; mt < 2; mt++)
#pragma unroll
                for (int nt = 0; nt < 8; nt++)
                    MMA16816(sacc[mt][nt], qf[mt][kc],
                             kf[nt >> 1][nt & 1], kf[nt >> 1][(nt & 1) + 2]);
        }

#pragma unroll
        for (int mt = 0; mt < 2; mt++)
#pragma unroll
            for (int hf = 0; hf < 2; hf++) {
                float mx = -1e30f;
#pragma unroll
                for (int nt = 0; nt < 8; nt++)
                    mx = fmaxf(mx, fmaxf(sacc[mt][nt][hf * 2], sacc[mt][nt][hf * 2 + 1]));
                mx = fmaxf(mx, __shfl_xor_sync(0xffffffffu, mx, 1));
                mx = fmaxf(mx, __shfl_xor_sync(0xffffffffu, mx, 2));
                float mold = mrun[mt][hf];
                float mnew = fmaxf(mold, mx);
                float corr = exp2f(C2 * (mold - mnew));
                mrun[mt][hf] = mnew;
                float sum = 0.0f;
#pragma unroll
                for (int nt = 0; nt < 8; nt++) {
                    float p0 = exp2f(C2 * (sacc[mt][nt][hf * 2] - mnew));
                    float p1 = exp2f(C2 * (sacc[mt][nt][hf * 2 + 1] - mnew));
                    sacc[mt][nt][hf * 2] = p0;
                    sacc[mt][nt][hf * 2 + 1] = p1;
                    sum += p0 + p1;
                }
                sum += __shfl_xor_sync(0xffffffffu, sum, 1);
                sum += __shfl_xor_sync(0xffffffffu, sum, 2);
                lrun[mt][hf] = lrun[mt][hf] * corr + sum;
#pragma unroll
                for (int nt = 0; nt < 4; nt++) {
                    oacc[mt][nt][hf * 2] *= corr;
                    oacc[mt][nt][hf * 2 + 1] *= corr;
                }
            }

#pragma unroll
        for (int kc4 = 0; kc4 < 4; kc4++) {
            uint32_t vf[2][4];
#pragma unroll
            for (int dg = 0; dg < 2; dg++) {
                uint32_t ad = Vs + (uint32_t)(kb * 64 + kc4 * 16 + (lane & 15)) * 80
                              + dg * 32 + (lane >> 4) * 16;
                LDSM_X4T(vf[dg], ad);
            }
#pragma unroll
            for (int mt = 0; mt < 2; mt++) {
                uint32_t a[4];
                a[0] = bf2u(sacc[mt][2 * kc4][0], sacc[mt][2 * kc4][1]);
                a[1] = bf2u(sacc[mt][2 * kc4][2], sacc[mt][2 * kc4][3]);
                a[2] = bf2u(sacc[mt][2 * kc4 + 1][0], sacc[mt][2 * kc4 + 1][1]);
                a[3] = bf2u(sacc[mt][2 * kc4 + 1][2], sacc[mt][2 * kc4 + 1][3]);
#pragma unroll
                for (int nt = 0; nt < 4; nt++)
                    MMA16816(oacc[mt][nt], a,
                             vf[nt >> 1][(nt & 1) * 2], vf[nt >> 1][(nt & 1) * 2 + 1]);
            }
        }
    }

#pragma unroll
    for (int mt = 0; mt < 2; mt++) {
        float inv0 = 1.0f / lrun[mt][0];
        float inv1 = 1.0f / lrun[mt][1];
        int row0 = win * 256 + qb + mt * 16 + (lane >> 2);
        int col = h * 32 + (lane & 3) * 2;
#pragma unroll
        for (int nt = 0; nt < 4; nt++) {
            *(uint32_t*)(out + (size_t)row0 * 256 + col + nt * 8) =
                bf2u(oacc[mt][nt][0] * inv0, oacc[mt][nt][1] * inv0);
            *(uint32_t*)(out + (size_t)(row0 + 8) * 256 + col + nt * 8) =
                bf2u(oacc[mt][nt][2] * inv1, oacc[mt][nt][3] * inv1);
        }
    }
}

// ---------------------------------------------------------------------------
__device__ __forceinline__ void decode_f(int f, int& fw, int& base_t,
                                         int& gwin, int& tt) {
    int b = f >> 10, h = (f >> 7) & 7, w = (f >> 4) & 7;
    int r1 = (f >> 2) & 3, r2 = f & 3;
    fw = (b * 8 + h) * 8 + w;
    base_t = r1 * 64 + r2 * 4;
    int gr = h * 4 + r1, gc = w * 4 + r2;
    gwin = b * 4 + (gr >> 4) * 2 + (gc >> 4);
    tt = (gr & 15) * 16 + (gc & 15);
}

__global__ void smsa_scatter_g_kernel(const float* __restrict__ g,
                                      float* __restrict__ out1) {
    int f = blockIdx.x, c = threadIdx.x;
    int fw, base_t, gwin, tt;
    decode_f(f, fw, base_t, gwin, tt);
    out1[((size_t)gwin * 256 + tt) * 256 + c] = g[(size_t)f * 256 + c];
}

__global__ __launch_bounds__(256) void smsa_xattn_kernel(
    const __nv_bfloat16* __restrict__ Q, const __nv_bfloat16* __restrict__ KV,
    __nv_bfloat16* __restrict__ AO) {
    int f = blockIdx.x;
    int h = threadIdx.x >> 5;
    int d = threadIdx.x & 31;
    int fw, base_t, gwin, tt;
    decode_f(f, fw, base_t, gwin, tt);
    float qd = __bfloat162float(Q[(size_t)f * 256 + h * 32 + d]);
    const float sc = 0.17677669529663687f;
    float s[16];
#pragma unroll
    for (int j = 0; j < 16; j++) {
        int t = base_t + (j >> 2) * 16 + (j & 3);
        float kd = __bfloat162float(KV[((size_t)(fw * 256 + t)) * 512 + h * 32 + d]);
        float pr = qd * kd;
#pragma unroll
        for (int o = 16; o > 0; o >>= 1)
            pr += __shfl_xor_sync(0xffffffffu, pr, o);
        s[j] = pr * sc;
    }
    float m = s[0];
#pragma unroll
    for (int j = 1; j < 16; j++) m = fmaxf(m, s[j]);
    float l = 0.0f, p[16];
#pragma unroll
    for (int j = 0; j < 16; j++) {
        p[j] = __expf(s[j] - m);
        l += p[j];
    }
    float inv = 1.0f / l;
    float acc = 0.0f;
#pragma unroll
    for (int j = 0; j < 16; j++) {
        int t = base_t + (j >> 2) * 16 + (j & 3);
        acc = fmaf(p[j], __bfloat162float(
                        KV[((size_t)(fw * 256 + t)) * 512 + 256 + h * 32 + d]),
                   acc);
    }
    AO[(size_t)f * 256 + h * 32 + d] = __float2bfloat16(acc * inv);
}

// ---------------------------------------------------------------------------
// Host side
// ---------------------------------------------------------------------------
static void run_hgemm_seg(const __nv_bfloat16* A, int lda,
                          const __nv_bfloat16* Bt0, const __nv_bfloat16* Bt1,
                          void* C0, void* C1, int ldc0, int ldc1,
                          const float* bias0, const float* bias1,
                          const float* res0, const float* res1, int ldr,
                          int M, int N, int K, int act, int outbf,
                          int mb1, int nbmax1) {
    dim3 grid(N / 128, M / 128);
    smsa_hgemm_kernel<<<grid, 128, GEMM_SMEM>>>(
        A, lda, Bt0, Bt1, C0, C1, ldc0, ldc1, bias0, bias1,
        res0, res1, ldr, K, act, outbf, mb1, nbmax1);
}

static void run_hgemm(const __nv_bfloat16* A, int lda, const __nv_bfloat16* Bt,
                      void* Cm, int ldc, const float* bias,
                      const float* res, int ldr, int M, int N, int K,
                      int act, int outbf) {
    run_hgemm_seg(A, lda, Bt, Bt, Cm, Cm, ldc, ldc, bias, bias, res, res, ldr,
                  M, N, K, act, outbf, 1 << 30, 1 << 30);
}

static void run_ln2(const float* x, __nv_bfloat16* y,
                    const float* g0, const float* b0,
                    const float* g1, const float* b1, int ntok, int bnd) {
    smsa_ln_kernel<<<ntok / 8, 256>>>(x, y, g0, b0, g1, b1, bnd);
}

extern "C" void kernel_launch(void* const* d_in, const int* in_sizes, int n_in,
                              void* d_out, int out_size) {
    const float* scale0 = (const float*)d_in[0];
    const float* scale1 = (const float*)d_in[1];
    const float* pe_w1 = (const float*)d_in[2];
    const float* pe_b1 = (const float*)d_in[3];
    const float* pe_w2 = (const float*)d_in[4];
    const float* ln1_g = (const float*)d_in[5];
    const float* ln1_b = (const float*)d_in[6];
    const float* wqkv = (const float*)d_in[7];
    const float* bqkv = (const float*)d_in[8];
    const float* wo = (const float*)d_in[9];
    const float* bo = (const float*)d_in[10];
    const float* ln2_g = (const float*)d_in[11];
    const float* ln2_b = (const float*)d_in[12];
    const float* mw1 = (const float*)d_in[13];
    const float* mb1 = (const float*)d_in[14];
    const float* mw2 = (const float*)d_in[15];
    const float* mb2 = (const float*)d_in[16];
    float* out = (float*)d_out;
    float* out0 = out;
    float* out1 = out + (size_t)65536 * 256;

    float *X, *PE, *G;
    __nv_bfloat16 *Hb, *QKVb, *Tb, *WT;
    cudaGetSymbolAddress((void**)&X, g_X);
    cudaGetSymbolAddress((void**)&PE, g_PE);
    cudaGetSymbolAddress((void**)&G, g_G);
    cudaGetSymbolAddress((void**)&Hb, g_Hb);
    cudaGetSymbolAddress((void**)&QKVb, g_QKVb);
    cudaGetSymbolAddress((void**)&Tb, g_Tb);
    cudaGetSymbolAddress((void**)&WT, g_WT);
    float* X1 = X + (size_t)65536 * 256;

    cudaFuncSetAttribute(smsa_fattn_kernel,
                         cudaFuncAttributeMaxDynamicSharedMemorySize, ATTN_SMEM);
    cudaFuncSetAttribute(smsa_hgemm_kernel,
                         cudaFuncAttributeMaxDynamicSharedMemorySize, GEMM_SMEM);

    const __nv_bfloat16 *wqkvT0 = WT + 0, *woT0 = WT + 196608;
    const __nv_bfloat16 *w1T0 = WT + 262144, *w2T0 = WT + 524288;
    const __nv_bfloat16 *wqkvT1 = WT + 786432, *woT1 = WT + 983040;
    const __nv_bfloat16 *w1T1 = WT + 1048576, *w2T1 = WT + 1310720;
    const float *ln1g0 = ln1_g, *ln1b0 = ln1_b;
    const float *ln2g0 = ln2_g, *ln2b0 = ln2_b;
    const float *ln1g1 = ln1_g + 256, *ln1b1 = ln1_b + 256;
    const float *ln2g1 = ln2_g + 256, *ln2b1 = ln2_b + 256;

    // 0) weight transposes, one launch
    {
        TrJobs J;
        const float* Ws[8] = {wqkv, wqkv + 196608, wo, wo + 65536,
                              mw1, mw1 + 262144, mw2, mw2 + 262144};
        __nv_bfloat16* Wts[8] = {WT + 0, WT + 786432, WT + 196608, WT + 983040,
                                 WT + 262144, WT + 1048576, WT + 524288, WT + 1310720};
        int Ks[8] = {256, 256, 256, 256, 256, 256, 1024, 1024};
        int Ns[8] = {768, 768, 256, 256, 1024, 1024, 256, 256};
        int b0 = 0;
        for (int i = 0; i < 8; i++) {
            J.W[i] = Ws[i]; J.Wt[i] = Wts[i]; J.K[i] = Ks[i]; J.N[i] = Ns[i];
            J.blk0[i] = b0;
            b0 += (Ks[i] / 32) * (Ns[i] / 32);
        }
        smsa_transpose_all_kernel<<<b0, dim3(32, 8)>>>(J);
    }

    // 1) position embeddings
    smsa_posemb_kernel<<<dim3(256, 2), 256>>>(pe_w1, pe_b1, pe_w2, PE);
    smsa_add_pe_ln_kernel<<<8192, 256>>>(scale0, PE, X, Hb, ln1g0, ln1b0);
    smsa_add_pe_kernel<<<1024, 256>>>(scale1, PE + 65536, X1);

    // 2) pool + LN1(scale1) -> X1, Hb rows 65536+
    smsa_pool_ln_kernel<<<4096, 256>>>(X, X1, Hb + (size_t)65536 * 256,
                                       ln1g1, ln1b1);

    // 3) MERGED sattn chain over 69632 rows
    run_hgemm_seg(Hb, 256, wqkvT0, wqkvT1,
                  QKVb, QKVb + (size_t)65536 * 768, 768, 768,
                  bqkv, bqkv + 768, nullptr, nullptr, 0,
                  NTOKA, 768, 256, 0, 1, MB1T, 6);
    smsa_fattn_kernel<<<(NTOKA / 256) * 8, 256, ATTN_SMEM>>>(QKVb, Hb);
    run_hgemm_seg(Hb, 256, woT0, woT1,
                  X, X1, 256, 256,
                  bo, bo + 256, X, X1, 256,
                  NTOKA, 256, 256, 0, 0, MB1T, 2);
    run_ln2(X, Hb, ln2g0, ln2b0, ln2g1, ln2b1, NTOKA, NTOK0);
    run_hgemm_seg(Hb, 256, w1T0, w1T1,
                  Tb, Tb + (size_t)65536 * 1024, 1024, 1024,
                  mb1, mb1 + 1024, nullptr, nullptr, 0,
                  NTOKA, 1024, 256, 1, 1, MB1T, 8);
    run_hgemm_seg(Tb, 1024, w2T0, w2T1,
                  out0, X1, 256, 256,
                  mb2, mb2 + 256, X, X1, 256,
                  NTOKA, 256, 1024, 0, 0, MB1T, 2);

    // cross kn LN: out0 -> Hb rows 0..65535
    run_ln2(out0, Hb, ln1g1, ln1b1, ln1g1, ln1b1, NTOK0, NTOK0);
    // gather + LN(G) -> G fp32, Hb rows 65536+ (bf16 S0)
    smsa_gather_ln_kernel<<<512, 256>>>(X1, G, Hb + (size_t)65536 * 256,
                                        ln1g1, ln1b1);

    __nv_bfloat16* Sqb = Tb;
    __nv_bfloat16* AOb = Tb + (size_t)4096 * 256;
    __nv_bfloat16* Sgb = Tb + (size_t)2 * 4096 * 256;
    __nv_bfloat16* Thb = Tb + (size_t)3 * 4096 * 256;

    // 4) segmented: seg0 = cross K|V (65536 x 512), seg1 = Sq (4096 x 256)
    run_hgemm_seg(Hb, 256, wqkvT1 + 256 * 256, wqkvT1,
                  QKVb, Sqb, 512, 256,
                  bqkv + 768 + 256, bqkv + 768, nullptr, nullptr, 0,
                  NTOKA, 512, 256, 0, 1, MB1T, 2);

    smsa_xattn_kernel<<<4096, 256>>>(Sqb, QKVb, AOb);
    run_hgemm(AOb, 256, woT1, G, 256, bo + 256, G, 256, NTOK1, 256, 256, 0, 0);
    run_ln2(G, Sgb, ln2g1, ln2b1, ln2g1, ln2b1, NTOK1, NTOK1);
    run_hgemm(Sgb, 256, w1T1, Thb, 1024, mb1 + 1024, nullptr, 0,
              NTOK1, 1024, 256, 1, 1);
    run_hgemm(Thb, 1024, w2T1, G, 256, mb2 + 256, G, 256, NTOK1, 256, 1024, 0, 0);

    // 5) scatter g back to o1 window layout
    smsa_scatter_g_kernel<<<4096, 256>>>(G, out1);
}